// round 3
// baseline (speedup 1.0000x reference)
#include <cuda_runtime.h>
#include <math.h>
#include <stdint.h>

#define BB 16
#define NP 8192
#define GG 128
#define KNb 32
#define CC 384
#define HH 6
#define LL 12
#define HIDD 1536
#define BG (BB*GG)          /* 2048 */
#define MROWS (BG*KNb)      /* 65536 */
#define EPSf 1e-5f

// ------------------------- scratch (static device memory) -------------------
__device__ float g_center [BG*3];
__device__ float g_centerO[BG*3];
__device__ float g_neigh  [MROWS*3];
__device__ float g_f1 [(size_t)MROWS*128];
__device__ float g_f2 [(size_t)MROWS*256];
__device__ float g_gmax[(size_t)BG*256];
__device__ float g_t  [(size_t)BG*512];
__device__ float g_s1 [(size_t)MROWS*512];
__device__ float g_s2 [(size_t)MROWS*384];
__device__ float g_psum[64*512];
__device__ float g_psq [64*512];
__device__ float g_scale[512];
__device__ float g_shift[512];
__device__ float g_h   [BG*CC];
__device__ float g_pos [BG*CC];
__device__ float g_xin [BG*CC];
__device__ float g_y   [BG*CC];
__device__ float g_qkv [BG*3*CC];
__device__ float g_attn[BG*CC];
__device__ float g_x1  [BG*CC];
__device__ float g_mh  [BG*HIDD];

// ------------------------------- FPS ----------------------------------------
__global__ void fps_kernel(const float* __restrict__ xyz, float* __restrict__ center)
{
    int b = blockIdx.x;
    int t = threadIdx.x;                      // 1024 threads
    const float* X = xyz + (size_t)b * NP * 3;
    float px[8], py[8], pz[8], dd[8];
#pragma unroll
    for (int j = 0; j < 8; j++) {
        int p = t + j * 1024;
        px[j] = X[p*3+0]; py[j] = X[p*3+1]; pz[j] = X[p*3+2];
        dd[j] = 1e10f;
    }
    __shared__ float rv[1024];
    __shared__ int   ri[1024];
    __shared__ int   s_far;
    int far = 0;
    for (int it = 0; it < GG; it++) {
        float cx = X[far*3+0], cy = X[far*3+1], cz = X[far*3+2];
        if (t == 0) {
            center[(b*GG+it)*3+0] = cx;
            center[(b*GG+it)*3+1] = cy;
            center[(b*GG+it)*3+2] = cz;
        }
        float bv = -1.f; int bi = 0;
#pragma unroll
        for (int j = 0; j < 8; j++) {
            float dx = px[j]-cx, dy = py[j]-cy, dz = pz[j]-cz;
            float d = dx*dx + dy*dy + dz*dz;
            if (d < dd[j]) dd[j] = d;
            if (dd[j] > bv) { bv = dd[j]; bi = t + j*1024; }
        }
        rv[t] = bv; ri[t] = bi;
        __syncthreads();
        for (int off = 512; off > 0; off >>= 1) {
            if (t < off) {
                float ov = rv[t+off]; int oi = ri[t+off];
                if (ov > rv[t] || (ov == rv[t] && oi < ri[t])) { rv[t] = ov; ri[t] = oi; }
            }
            __syncthreads();
        }
        if (t == 0) s_far = ri[0];
        __syncthreads();
        far = s_far;
    }
}

// --------------------------- greedy NN ordering ------------------------------
__global__ void order_kernel(const float* __restrict__ cen, float* __restrict__ cenO)
{
    int b = blockIdx.x;
    int t = threadIdx.x;                      // 128 threads
    __shared__ float cx[GG], cy[GG], cz[GG], nn[GG];
    __shared__ int visited[GG];
    __shared__ int s_last;
    __shared__ float rv[GG];
    __shared__ int ri[GG];
    cx[t] = cen[(b*GG+t)*3+0];
    cy[t] = cen[(b*GG+t)*3+1];
    cz[t] = cen[(b*GG+t)*3+2];
    nn[t] = cx[t]*cx[t] + cy[t]*cy[t] + cz[t]*cz[t];
    visited[t] = 0;
    if (t == 0) {
        visited[0] = 1; s_last = 0;
        cenO[(b*GG)*3+0] = cx[0]; cenO[(b*GG)*3+1] = cy[0]; cenO[(b*GG)*3+2] = cz[0];
    }
    __syncthreads();
    for (int step = 1; step < GG; step++) {
        int last = s_last;
        float d;
        if (visited[t]) d = 3.4e38f;
        else {
            float dot = cx[last]*cx[t] + cy[last]*cy[t] + cz[last]*cz[t];
            d = fmaxf(nn[last] + nn[t] - 2.f*dot, 0.f);
        }
        rv[t] = d; ri[t] = t;
        __syncthreads();
        for (int off = 64; off > 0; off >>= 1) {
            if (t < off) {
                float ov = rv[t+off]; int oi = ri[t+off];
                if (ov < rv[t] || (ov == rv[t] && oi < ri[t])) { rv[t] = ov; ri[t] = oi; }
            }
            __syncthreads();
        }
        if (t == 0) {
            int nx = ri[0];
            visited[nx] = 1; s_last = nx;
            cenO[(b*GG+step)*3+0] = cx[nx];
            cenO[(b*GG+step)*3+1] = cy[nx];
            cenO[(b*GG+step)*3+2] = cz[nx];
        }
        __syncthreads();
    }
}

// ------------------------------- kNN + gather --------------------------------
__global__ void knn_kernel(const float* __restrict__ xyz, const float* __restrict__ cenO,
                           float* __restrict__ neigh)
{
    int bg = blockIdx.x;
    int b  = bg >> 7;
    int t  = threadIdx.x;                     // 256 threads
    const float* X = xyz + (size_t)b * NP * 3;
    float cx = cenO[bg*3+0], cy = cenO[bg*3+1], cz = cenO[bg*3+2];
    __shared__ float sd[NP];
    __shared__ float rv[256];
    __shared__ int ri[256];
#pragma unroll
    for (int j = 0; j < NP/256; j++) {
        int p = t + j*256;
        float dx = X[p*3+0]-cx, dy = X[p*3+1]-cy, dz = X[p*3+2]-cz;
        sd[p] = dx*dx + dy*dy + dz*dz;
    }
    __syncthreads();
    for (int k = 0; k < KNb; k++) {
        float bv = 3.4e38f; int bi = 0;
#pragma unroll
        for (int j = 0; j < NP/256; j++) {
            int p = t + j*256;
            float d = sd[p];
            if (d < bv) { bv = d; bi = p; }
        }
        rv[t] = bv; ri[t] = bi;
        __syncthreads();
        for (int off = 128; off > 0; off >>= 1) {
            if (t < off) {
                float ov = rv[t+off]; int oi = ri[t+off];
                if (ov < rv[t] || (ov == rv[t] && oi < ri[t])) { rv[t] = ov; ri[t] = oi; }
            }
            __syncthreads();
        }
        if (t == 0) {
            int m = ri[0];
            neigh[((size_t)bg*KNb + k)*3+0] = X[m*3+0]-cx;
            neigh[((size_t)bg*KNb + k)*3+1] = X[m*3+1]-cy;
            neigh[((size_t)bg*KNb + k)*3+2] = X[m*3+2]-cz;
            sd[m] = 3.4e38f;
        }
        __syncthreads();
    }
}

// ------------------------------- GEMM ----------------------------------------
// C[m,n] = act( BN?(A)[m,:] . W[n,:] + bias[n] + res )   W row-major (N,K), ld ldw
// RES: 0 none, 1 full res[m*N+n], 2 group res[(m/32)*N+n]
// ACT: 0 none, 1 relu, 2 exact gelu
// BNA: apply relu(a*scale[k]+shift[k]) to A elements
template<int ACT, int RES, int BNA>
__global__ void __launch_bounds__(256) gemm_k(
    const float* __restrict__ A, int lda,
    const float* __restrict__ W, int ldw,
    const float* __restrict__ bias,
    const float* __restrict__ res,
    const float* __restrict__ bnscale, const float* __restrict__ bnshift,
    float* __restrict__ C, int M, int N, int K)
{
    __shared__ float As[16][64];
    __shared__ float Ws[16][64];
    int tid = threadIdx.x;
    int tx = tid & 15, ty = tid >> 4;
    int m0 = blockIdx.y * 64, n0 = blockIdx.x * 64;
    float acc[4][4] = {};
    for (int kk = 0; kk < K; kk += 16) {
#pragma unroll
        for (int i = 0; i < 4; i++) {
            int idx = tid + i*256;
            int k = idx & 15, m = idx >> 4;
            float a = 0.f, w = 0.f;
            if (kk + k < K) {
                a = A[(size_t)(m0+m)*lda + kk + k];
                if (BNA) a = fmaxf(fmaf(a, bnscale[kk+k], bnshift[kk+k]), 0.f);
                w = W[(size_t)(n0+m)*ldw + kk + k];
            }
            As[k][m] = a;
            Ws[k][m] = w;
        }
        __syncthreads();
#pragma unroll
        for (int k = 0; k < 16; k++) {
            float4 av = *(const float4*)&As[k][ty*4];
            float4 wv = *(const float4*)&Ws[k][tx*4];
            float ar[4] = {av.x, av.y, av.z, av.w};
            float wr[4] = {wv.x, wv.y, wv.z, wv.w};
#pragma unroll
            for (int i = 0; i < 4; i++)
#pragma unroll
                for (int j = 0; j < 4; j++)
                    acc[i][j] = fmaf(ar[i], wr[j], acc[i][j]);
        }
        __syncthreads();
    }
#pragma unroll
    for (int i = 0; i < 4; i++) {
        int m = m0 + ty*4 + i;
#pragma unroll
        for (int j = 0; j < 4; j++) {
            int n = n0 + tx*4 + j;
            float v = acc[i][j];
            if (bias) v += bias[n];
            if (RES == 1) v += res[(size_t)m*N + n];
            if (RES == 2) v += res[(size_t)(m >> 5)*N + n];
            if (ACT == 1) v = fmaxf(v, 0.f);
            if (ACT == 2) v = 0.5f*v*(1.f + erff(v*0.70710678118654752f));
            C[(size_t)m*N + n] = v;
        }
    }
}

// --------------------------- BN column stats ---------------------------------
__global__ void colstats_kernel(const float* __restrict__ X, int M, int C,
                                float* __restrict__ psum, float* __restrict__ psq)
{
    int c = blockIdx.x * 32 + threadIdx.x;
    int ry = threadIdx.y;                     // 8
    float s = 0.f, s2 = 0.f;
    for (int r = blockIdx.y*8 + ry; r < M; r += gridDim.y*8) {
        float v = X[(size_t)r*C + c];
        s += v; s2 += v*v;
    }
    __shared__ float sh[8][32], sh2[8][32];
    sh[ry][threadIdx.x] = s; sh2[ry][threadIdx.x] = s2;
    __syncthreads();
    if (ry == 0) {
        for (int j = 1; j < 8; j++) { s += sh[j][threadIdx.x]; s2 += sh2[j][threadIdx.x]; }
        psum[blockIdx.y*C + c] = s;
        psq [blockIdx.y*C + c] = s2;
    }
}

__global__ void bnfin_kernel(const float* __restrict__ psum, const float* __restrict__ psq,
                             int C, float invM,
                             const float* __restrict__ g, const float* __restrict__ b,
                             float* __restrict__ scale, float* __restrict__ shift)
{
    int c = blockIdx.x * blockDim.x + threadIdx.x;
    if (c >= C) return;
    float s = 0.f, s2 = 0.f;
    for (int j = 0; j < 64; j++) { s += psum[j*C + c]; s2 += psq[j*C + c]; }
    float mean = s * invM;
    float var  = s2 * invM - mean*mean;
    float sc = g[c] * rsqrtf(var + EPSf);
    scale[c] = sc;
    shift[c] = b[c] - mean*sc;
}

// ------------------------------ max pools ------------------------------------
__global__ void gmax_kernel(const float* __restrict__ f2, float* __restrict__ gm)
{
    int g = blockIdx.x; int c = threadIdx.x;  // 256
    float m = -3.4e38f;
    for (int k = 0; k < KNb; k++) m = fmaxf(m, f2[((size_t)g*KNb + k)*256 + c]);
    gm[(size_t)g*256 + c] = m;
}

__global__ void tokmax_kernel(const float* __restrict__ s2, const float* __restrict__ sos,
                              float* __restrict__ h)
{
    int bg = blockIdx.x; int c = threadIdx.x; // 384
    int g = bg & (GG-1);
    float m = -3.4e38f;
    for (int k = 0; k < KNb; k++) m = fmaxf(m, s2[((size_t)bg*KNb + k)*CC + c]);
    if (g < GG-1) h[(size_t)(bg+1)*CC + c] = m;   // shift-right (sos at g=0)
    if (g == 0)   h[(size_t)bg*CC + c] = sos[c];
}

// --------------------------- positional embedding ----------------------------
__global__ void pos_kernel(const float* __restrict__ cenO, float* __restrict__ pos)
{
    int bg = blockIdx.x; int t = threadIdx.x; // 384
    int ch = t >> 7;
    int rem = t & 127;
    int i = rem >> 1, s = rem & 1;
    float coord = cenO[bg*3 + ch];
    float inv = expf(-(2.f * (float)i / 128.f) * logf(10000.f));
    float ang = coord * inv;
    pos[(size_t)bg*CC + t] = s ? cosf(ang) : sinf(ang);
}

// ------------------------------ LayerNorm ------------------------------------
__global__ void ln_kernel(const float* __restrict__ x, const float* __restrict__ pos,
                          float* __restrict__ xin, float* __restrict__ y,
                          const float* __restrict__ gw, const float* __restrict__ bw)
{
    int r = blockIdx.x; int t = threadIdx.x;  // 128 threads, 3 cols each
    __shared__ float red[128];
    __shared__ float s_mean, s_rstd;
    float v[3];
    float s = 0.f;
#pragma unroll
    for (int i = 0; i < 3; i++) {
        int c = t + i*128;
        float vv = x[(size_t)r*CC + c];
        if (pos) vv += pos[(size_t)r*CC + c];
        if (xin) xin[(size_t)r*CC + c] = vv;
        v[i] = vv; s += vv;
    }
    red[t] = s; __syncthreads();
    for (int off = 64; off > 0; off >>= 1) { if (t < off) red[t] += red[t+off]; __syncthreads(); }
    if (t == 0) s_mean = red[0] / (float)CC;
    __syncthreads();
    float mean = s_mean;
    float d = 0.f;
#pragma unroll
    for (int i = 0; i < 3; i++) { float e = v[i]-mean; d += e*e; }
    red[t] = d; __syncthreads();
    for (int off = 64; off > 0; off >>= 1) { if (t < off) red[t] += red[t+off]; __syncthreads(); }
    if (t == 0) s_rstd = rsqrtf(red[0] / (float)CC + EPSf);
    __syncthreads();
    float rstd = s_rstd;
#pragma unroll
    for (int i = 0; i < 3; i++) {
        int c = t + i*128;
        y[(size_t)r*CC + c] = (v[i]-mean)*rstd*gw[c] + bw[c];
    }
}

// ------------------------------ attention ------------------------------------
// One block = (batch b, head h). 128 threads = one query row each.
// Q in registers, K in 32KB static shared, V streamed from global (warp-uniform
// row loads, L1-resident). No dynamic smem, no cudaFuncSetAttribute.
__global__ void attn_kernel(const float* __restrict__ qkv, float* __restrict__ out)
{
    __shared__ float sK[128*64];    // 32 KB
    int h = blockIdx.x, b = blockIdx.y;
    int t = threadIdx.x;            // 128 = one query each
    const float* base = qkv + (size_t)b*GG*(3*CC) + h*64;
    const float* src = base + (size_t)t*(3*CC);
    float q[64];
#pragma unroll
    for (int d = 0; d < 64; d += 4) {
        float4 qv = *(const float4*)&src[d];
        q[d+0]=qv.x; q[d+1]=qv.y; q[d+2]=qv.z; q[d+3]=qv.w;
        float4 kv = *(const float4*)&src[CC + d];
        sK[t*64+d+0]=kv.x; sK[t*64+d+1]=kv.y; sK[t*64+d+2]=kv.z; sK[t*64+d+3]=kv.w;
    }
    __syncthreads();
    const float scale = 0.125f;
    float mx = -3.4e38f;
    for (int j = 0; j <= t; j++) {
        float s = 0.f;
#pragma unroll
        for (int d = 0; d < 64; d++) s = fmaf(q[d], sK[j*64+d], s);
        s *= scale;
        if (s > mx) mx = s;
    }
    float acc[64];
#pragma unroll
    for (int d = 0; d < 64; d++) acc[d] = 0.f;
    float sum = 0.f;
    for (int j = 0; j <= t; j++) {
        float s = 0.f;
#pragma unroll
        for (int d = 0; d < 64; d++) s = fmaf(q[d], sK[j*64+d], s);
        float e = expf(s*scale - mx);
        sum += e;
        const float* vrow = base + (size_t)j*(3*CC) + 2*CC;
#pragma unroll
        for (int d = 0; d < 64; d += 4) {
            float4 vv = *(const float4*)&vrow[d];
            acc[d+0] = fmaf(e, vv.x, acc[d+0]);
            acc[d+1] = fmaf(e, vv.y, acc[d+1]);
            acc[d+2] = fmaf(e, vv.z, acc[d+2]);
            acc[d+3] = fmaf(e, vv.w, acc[d+3]);
        }
    }
    float inv = 1.f / sum;
    float* dst = out + ((size_t)(b*GG + t))*CC + h*64;
#pragma unroll
    for (int d = 0; d < 64; d++) dst[d] = acc[d]*inv;
}

// --------------------------------- launch ------------------------------------
static float* sym(const void* s) { void* p = nullptr; cudaGetSymbolAddress(&p, s); return (float*)p; }

extern "C" void kernel_launch(void* const* d_in, const int* in_sizes, int n_in,
                              void* d_out, int out_size)
{
    const float* xyz    = (const float*)d_in[0];
    const float* ec1_w  = (const float*)d_in[1];
    const float* ec1_b  = (const float*)d_in[2];
    const float* bn1_g  = (const float*)d_in[3];
    const float* bn1_b  = (const float*)d_in[4];
    const float* ec2_w  = (const float*)d_in[5];
    const float* ec2_b  = (const float*)d_in[6];
    const float* sc1_w  = (const float*)d_in[7];
    const float* sc1_b  = (const float*)d_in[8];
    const float* bn2_g  = (const float*)d_in[9];
    const float* bn2_b  = (const float*)d_in[10];
    const float* sc2_w  = (const float*)d_in[11];
    const float* sc2_b  = (const float*)d_in[12];
    const float* sos    = (const float*)d_in[13];
    const float* ln1_g  = (const float*)d_in[14];
    const float* ln1_b  = (const float*)d_in[15];
    const float* qkv_w  = (const float*)d_in[16];
    const float* qkv_b  = (const float*)d_in[17];
    const float* out_w  = (const float*)d_in[18];
    const float* out_b  = (const float*)d_in[19];
    const float* ln2_g  = (const float*)d_in[20];
    const float* ln2_b  = (const float*)d_in[21];
    const float* mlp1_w = (const float*)d_in[22];
    const float* mlp1_b = (const float*)d_in[23];
    const float* mlp2_w = (const float*)d_in[24];
    const float* mlp2_b = (const float*)d_in[25];
    const float* lnf_g  = (const float*)d_in[26];
    const float* lnf_b  = (const float*)d_in[27];

    float* p_center  = sym(g_center);
    float* p_centerO = sym(g_centerO);
    float* p_neigh   = sym(g_neigh);
    float* p_f1   = sym(g_f1);
    float* p_f2   = sym(g_f2);
    float* p_gmax = sym(g_gmax);
    float* p_t    = sym(g_t);
    float* p_s1   = sym(g_s1);
    float* p_s2   = sym(g_s2);
    float* p_psum = sym(g_psum);
    float* p_psq  = sym(g_psq);
    float* p_scale= sym(g_scale);
    float* p_shift= sym(g_shift);
    float* p_h    = sym(g_h);
    float* p_pos  = sym(g_pos);
    float* p_xin  = sym(g_xin);
    float* p_y    = sym(g_y);
    float* p_qkv  = sym(g_qkv);
    float* p_attn = sym(g_attn);
    float* p_x1   = sym(g_x1);
    float* p_mh   = sym(g_mh);

    // ---- grouping ----
    fps_kernel  <<<BB, 1024>>>(xyz, p_center);
    order_kernel<<<BB, GG  >>>(p_center, p_centerO);
    knn_kernel  <<<BG, 256 >>>(xyz, p_centerO, p_neigh);

    // ---- encoder ----
    // ec1: (65536,3) @ (128,3)^T
    gemm_k<0,0,0><<<dim3(128/64, MROWS/64), 256>>>(p_neigh, 3, ec1_w, 3, ec1_b,
                                                   nullptr, nullptr, nullptr,
                                                   p_f1, MROWS, 128, 3);
    colstats_kernel<<<dim3(128/32, 64), dim3(32,8)>>>(p_f1, MROWS, 128, p_psum, p_psq);
    bnfin_kernel<<<1, 128>>>(p_psum, p_psq, 128, 1.f/(float)MROWS, bn1_g, bn1_b, p_scale, p_shift);
    // ec2 with fused BN1+relu on A: (65536,128)->(65536,256)
    gemm_k<0,0,1><<<dim3(256/64, MROWS/64), 256>>>(p_f1, 128, ec2_w, 128, ec2_b,
                                                   nullptr, p_scale, p_shift,
                                                   p_f2, MROWS, 256, 128);
    gmax_kernel<<<BG, 256>>>(p_f2, p_gmax);
    // t = gmax @ sc1_w[:, :256]^T + sc1_b     (per-group part of the concat)
    gemm_k<0,0,0><<<dim3(512/64, BG/64), 256>>>(p_gmax, 256, sc1_w, 512, sc1_b,
                                                nullptr, nullptr, nullptr,
                                                p_t, BG, 512, 256);
    // s1 = f2 @ sc1_w[:, 256:]^T + broadcast(t)
    gemm_k<0,2,0><<<dim3(512/64, MROWS/64), 256>>>(p_f2, 256, sc1_w + 256, 512, nullptr,
                                                   p_t, nullptr, nullptr,
                                                   p_s1, MROWS, 512, 256);
    colstats_kernel<<<dim3(512/32, 64), dim3(32,8)>>>(p_s1, MROWS, 512, p_psum, p_psq);
    bnfin_kernel<<<4, 128>>>(p_psum, p_psq, 512, 1.f/(float)MROWS, bn2_g, bn2_b, p_scale, p_shift);
    // sc2 with fused BN2+relu on A: (65536,512)->(65536,384)
    gemm_k<0,0,1><<<dim3(384/64, MROWS/64), 256>>>(p_s1, 512, sc2_w, 512, sc2_b,
                                                   nullptr, p_scale, p_shift,
                                                   p_s2, MROWS, 384, 512);
    tokmax_kernel<<<BG, CC>>>(p_s2, sos, p_h);
    pos_kernel<<<BG, CC>>>(p_centerO, p_pos);

    // ---- GPT ----
    for (int l = 0; l < LL; l++) {
        const float* qw = qkv_w  + (size_t)l*3*CC*CC;
        const float* qb = qkv_b  + (size_t)l*3*CC;
        const float* ow = out_w  + (size_t)l*CC*CC;
        const float* ob = out_b  + (size_t)l*CC;
        const float* m1w= mlp1_w + (size_t)l*HIDD*CC;
        const float* m1b= mlp1_b + (size_t)l*HIDD;
        const float* m2w= mlp2_w + (size_t)l*CC*HIDD;
        const float* m2b= mlp2_b + (size_t)l*CC;

        // xin = h + pos ; y = LN1(xin)
        ln_kernel<<<BG, 128>>>(p_h, p_pos, p_xin, p_y, ln1_g + l*CC, ln1_b + l*CC);
        // qkv
        gemm_k<0,0,0><<<dim3(3*CC/64, BG/64), 256>>>(p_y, CC, qw, CC, qb,
                                                     nullptr, nullptr, nullptr,
                                                     p_qkv, BG, 3*CC, CC);
        attn_kernel<<<dim3(HH, BB), 128>>>(p_qkv, p_attn);
        // x1 = xin + attn @ ow^T + ob
        gemm_k<0,1,0><<<dim3(CC/64, BG/64), 256>>>(p_attn, CC, ow, CC, ob,
                                                   p_xin, nullptr, nullptr,
                                                   p_x1, BG, CC, CC);
        // y = LN2(x1)
        ln_kernel<<<BG, 128>>>(p_x1, nullptr, nullptr, p_y, ln2_g + l*CC, ln2_b + l*CC);
        // mh = gelu(y @ m1w^T + m1b)
        gemm_k<2,0,0><<<dim3(HIDD/64, BG/64), 256>>>(p_y, CC, m1w, CC, m1b,
                                                     nullptr, nullptr, nullptr,
                                                     p_mh, BG, HIDD, CC);
        // h = x1 + mh @ m2w^T + m2b
        gemm_k<0,1,0><<<dim3(CC/64, BG/64), 256>>>(p_mh, HIDD, m2w, HIDD, m2b,
                                                   p_x1, nullptr, nullptr,
                                                   p_h, BG, CC, HIDD);
    }

    // final LN -> output
    ln_kernel<<<BG, 128>>>(p_h, nullptr, nullptr, (float*)d_out, lnf_g, lnf_b);
}

// round 6
// speedup vs baseline: 1.6394x; 1.6394x over previous
#include <cuda_runtime.h>
#include <math.h>
#include <stdint.h>

#define BB 16
#define NP 8192
#define GG 128
#define KNb 32
#define CC 384
#define HH 6
#define LL 12
#define HIDD 1536
#define BG (BB*GG)          /* 2048 */
#define MROWS (BG*KNb)      /* 65536 */
#define EPSf 1e-5f

// ------------------------- scratch (static device memory) -------------------
__device__ float g_center [BG*3];
__device__ float g_centerO[BG*3];
__device__ float g_neigh  [MROWS*3];
__device__ float g_f1 [(size_t)MROWS*128];
__device__ float g_f2 [(size_t)MROWS*256];
__device__ float g_gmax[(size_t)BG*256];
__device__ float g_t  [(size_t)BG*512];
__device__ float g_s1 [(size_t)MROWS*512];
__device__ float g_s2 [(size_t)MROWS*384];
__device__ float g_psum[64*512];
__device__ float g_psq [64*512];
__device__ float g_scale[512];
__device__ float g_shift[512];
__device__ float g_h   [BG*CC];
__device__ float g_pos [BG*CC];
__device__ float g_xin [BG*CC];
__device__ float g_y   [BG*CC];
__device__ float g_qkv [BG*3*CC];
__device__ float g_attn[BG*CC];
__device__ float g_x1  [BG*CC];
__device__ float g_mh  [BG*HIDD];

// ------------------------------- FPS ----------------------------------------
__global__ void fps_kernel(const float* __restrict__ xyz, float* __restrict__ center)
{
    int b = blockIdx.x;
    int t = threadIdx.x;                      // 1024 threads
    const float* X = xyz + (size_t)b * NP * 3;
    float px[8], py[8], pz[8], dd[8];
#pragma unroll
    for (int j = 0; j < 8; j++) {
        int p = t + j * 1024;
        px[j] = X[p*3+0]; py[j] = X[p*3+1]; pz[j] = X[p*3+2];
        dd[j] = 1e10f;
    }
    __shared__ float rv[1024];
    __shared__ int   ri[1024];
    __shared__ int   s_far;
    int far = 0;
    for (int it = 0; it < GG; it++) {
        float cx = X[far*3+0], cy = X[far*3+1], cz = X[far*3+2];
        if (t == 0) {
            center[(b*GG+it)*3+0] = cx;
            center[(b*GG+it)*3+1] = cy;
            center[(b*GG+it)*3+2] = cz;
        }
        float bv = -1.f; int bi = 0;
#pragma unroll
        for (int j = 0; j < 8; j++) {
            float dx = px[j]-cx, dy = py[j]-cy, dz = pz[j]-cz;
            float d = dx*dx + dy*dy + dz*dz;
            if (d < dd[j]) dd[j] = d;
            if (dd[j] > bv) { bv = dd[j]; bi = t + j*1024; }
        }
        rv[t] = bv; ri[t] = bi;
        __syncthreads();
        for (int off = 512; off > 0; off >>= 1) {
            if (t < off) {
                float ov = rv[t+off]; int oi = ri[t+off];
                if (ov > rv[t] || (ov == rv[t] && oi < ri[t])) { rv[t] = ov; ri[t] = oi; }
            }
            __syncthreads();
        }
        if (t == 0) s_far = ri[0];
        __syncthreads();
        far = s_far;
    }
}

// --------------------------- greedy NN ordering ------------------------------
__global__ void order_kernel(const float* __restrict__ cen, float* __restrict__ cenO)
{
    int b = blockIdx.x;
    int t = threadIdx.x;                      // 128 threads
    __shared__ float cx[GG], cy[GG], cz[GG], nn[GG];
    __shared__ int visited[GG];
    __shared__ int s_last;
    __shared__ float rv[GG];
    __shared__ int ri[GG];
    cx[t] = cen[(b*GG+t)*3+0];
    cy[t] = cen[(b*GG+t)*3+1];
    cz[t] = cen[(b*GG+t)*3+2];
    nn[t] = cx[t]*cx[t] + cy[t]*cy[t] + cz[t]*cz[t];
    visited[t] = 0;
    if (t == 0) {
        visited[0] = 1; s_last = 0;
        cenO[(b*GG)*3+0] = cx[0]; cenO[(b*GG)*3+1] = cy[0]; cenO[(b*GG)*3+2] = cz[0];
    }
    __syncthreads();
    for (int step = 1; step < GG; step++) {
        int last = s_last;
        float d;
        if (visited[t]) d = 3.4e38f;
        else {
            float dot = cx[last]*cx[t] + cy[last]*cy[t] + cz[last]*cz[t];
            d = fmaxf(nn[last] + nn[t] - 2.f*dot, 0.f);
        }
        rv[t] = d; ri[t] = t;
        __syncthreads();
        for (int off = 64; off > 0; off >>= 1) {
            if (t < off) {
                float ov = rv[t+off]; int oi = ri[t+off];
                if (ov < rv[t] || (ov == rv[t] && oi < ri[t])) { rv[t] = ov; ri[t] = oi; }
            }
            __syncthreads();
        }
        if (t == 0) {
            int nx = ri[0];
            visited[nx] = 1; s_last = nx;
            cenO[(b*GG+step)*3+0] = cx[nx];
            cenO[(b*GG+step)*3+1] = cy[nx];
            cenO[(b*GG+step)*3+2] = cz[nx];
        }
        __syncthreads();
    }
}

// ------------------------------- kNN + gather --------------------------------
__global__ void knn_kernel(const float* __restrict__ xyz, const float* __restrict__ cenO,
                           float* __restrict__ neigh)
{
    int bg = blockIdx.x;
    int b  = bg >> 7;
    int t  = threadIdx.x;                     // 256 threads
    const float* X = xyz + (size_t)b * NP * 3;
    float cx = cenO[bg*3+0], cy = cenO[bg*3+1], cz = cenO[bg*3+2];
    __shared__ float sd[NP];
    __shared__ float rv[256];
    __shared__ int ri[256];
#pragma unroll
    for (int j = 0; j < NP/256; j++) {
        int p = t + j*256;
        float dx = X[p*3+0]-cx, dy = X[p*3+1]-cy, dz = X[p*3+2]-cz;
        sd[p] = dx*dx + dy*dy + dz*dz;
    }
    __syncthreads();
    for (int k = 0; k < KNb; k++) {
        float bv = 3.4e38f; int bi = 0;
#pragma unroll
        for (int j = 0; j < NP/256; j++) {
            int p = t + j*256;
            float d = sd[p];
            if (d < bv) { bv = d; bi = p; }
        }
        rv[t] = bv; ri[t] = bi;
        __syncthreads();
        for (int off = 128; off > 0; off >>= 1) {
            if (t < off) {
                float ov = rv[t+off]; int oi = ri[t+off];
                if (ov < rv[t] || (ov == rv[t] && oi < ri[t])) { rv[t] = ov; ri[t] = oi; }
            }
            __syncthreads();
        }
        if (t == 0) {
            int m = ri[0];
            neigh[((size_t)bg*KNb + k)*3+0] = X[m*3+0]-cx;
            neigh[((size_t)bg*KNb + k)*3+1] = X[m*3+1]-cy;
            neigh[((size_t)bg*KNb + k)*3+2] = X[m*3+2]-cz;
            sd[m] = 3.4e38f;
        }
        __syncthreads();
    }
}

// --------------------- small-K GEMM (only ec1, K=3) ---------------------------
template<int ACT, int RES, int BNA>
__global__ void __launch_bounds__(256) gemm_k(
    const float* __restrict__ A, int lda,
    const float* __restrict__ W, int ldw,
    const float* __restrict__ bias,
    const float* __restrict__ res,
    const float* __restrict__ bnscale, const float* __restrict__ bnshift,
    float* __restrict__ C, int M, int N, int K)
{
    __shared__ float As[16][64];
    __shared__ float Ws[16][64];
    int tid = threadIdx.x;
    int tx = tid & 15, ty = tid >> 4;
    int m0 = blockIdx.y * 64, n0 = blockIdx.x * 64;
    float acc[4][4] = {};
    for (int kk = 0; kk < K; kk += 16) {
#pragma unroll
        for (int i = 0; i < 4; i++) {
            int idx = tid + i*256;
            int k = idx & 15, m = idx >> 4;
            float a = 0.f, w = 0.f;
            if (kk + k < K) {
                a = A[(size_t)(m0+m)*lda + kk + k];
                if (BNA) a = fmaxf(fmaf(a, bnscale[kk+k], bnshift[kk+k]), 0.f);
                w = W[(size_t)(n0+m)*ldw + kk + k];
            }
            As[k][m] = a;
            Ws[k][m] = w;
        }
        __syncthreads();
#pragma unroll
        for (int k = 0; k < 16; k++) {
            float4 av = *(const float4*)&As[k][ty*4];
            float4 wv = *(const float4*)&Ws[k][tx*4];
            float ar[4] = {av.x, av.y, av.z, av.w};
            float wr[4] = {wv.x, wv.y, wv.z, wv.w};
#pragma unroll
            for (int i = 0; i < 4; i++)
#pragma unroll
                for (int j = 0; j < 4; j++)
                    acc[i][j] = fmaf(ar[i], wr[j], acc[i][j]);
        }
        __syncthreads();
    }
#pragma unroll
    for (int i = 0; i < 4; i++) {
        int m = m0 + ty*4 + i;
#pragma unroll
        for (int j = 0; j < 4; j++) {
            int n = n0 + tx*4 + j;
            float v = acc[i][j];
            if (bias) v += bias[n];
            if (RES == 1) v += res[(size_t)m*N + n];
            if (RES == 2) v += res[(size_t)(m >> 5)*N + n];
            if (ACT == 1) v = fmaxf(v, 0.f);
            if (ACT == 2) v = 0.5f*v*(1.f + erff(v*0.70710678118654752f));
            C[(size_t)m*N + n] = v;
        }
    }
}

// ---------------- main tiled GEMM: double-buffered, 256 threads --------------
// BM x BN block tile, TM x TN per thread (TM=8; TN=8 or 4), KT=16.
// Requires M%BM==0, N%BN==0, K%16==0 (true for all call sites).
// C = act( BN?(A) @ W^T + bias + res )
template<int BM, int BN, int TN, int ACT, int RES, int BNA>
__global__ void __launch_bounds__(256) gemm2(
    const float* __restrict__ A, int lda,
    const float* __restrict__ W, int ldw,
    const float* __restrict__ bias,
    const float* __restrict__ res,
    const float* __restrict__ bnsc, const float* __restrict__ bnsh,
    float* __restrict__ C, int M, int N, int K)
{
    constexpr int KT  = 16;
    constexpr int AF4 = BM*KT/(4*256);     // float4 per thread for A tile
    constexpr int WF4 = BN*KT/(4*256);     // float4 per thread for W tile
    constexpr int BH  = (TN == 8) ? BN/2 : 0;
    __shared__ float As[2][KT][BM+4];
    __shared__ float Ws[2][KT][BN+4];

    int tid = threadIdx.x;
    int tx = tid & 15, ty = tid >> 4;
    int m0 = blockIdx.y * BM, n0 = blockIdx.x * BN;

    float4 ra[AF4], rw[WF4];
    float acc[8][TN];
#pragma unroll
    for (int i = 0; i < 8; i++)
#pragma unroll
        for (int j = 0; j < TN; j++) acc[i][j] = 0.f;

    // ---- load tile 0 into regs ----
#pragma unroll
    for (int j = 0; j < AF4; j++) {
        int f = tid + j*256; int m = f >> 2, c = f & 3;
        float4 v = *(const float4*)&A[(size_t)(m0+m)*lda + c*4];
        if (BNA) {
            float4 s = *(const float4*)&bnsc[c*4];
            float4 h = *(const float4*)&bnsh[c*4];
            v.x = fmaxf(fmaf(v.x,s.x,h.x),0.f);
            v.y = fmaxf(fmaf(v.y,s.y,h.y),0.f);
            v.z = fmaxf(fmaf(v.z,s.z,h.z),0.f);
            v.w = fmaxf(fmaf(v.w,s.w,h.w),0.f);
        }
        ra[j] = v;
    }
#pragma unroll
    for (int j = 0; j < WF4; j++) {
        int f = tid + j*256; int m = f >> 2, c = f & 3;
        rw[j] = *(const float4*)&W[(size_t)(n0+m)*ldw + c*4];
    }
    // ---- store tile 0 ----
#pragma unroll
    for (int j = 0; j < AF4; j++) {
        int f = tid + j*256; int m = f >> 2, c = f & 3;
        As[0][c*4+0][m] = ra[j].x; As[0][c*4+1][m] = ra[j].y;
        As[0][c*4+2][m] = ra[j].z; As[0][c*4+3][m] = ra[j].w;
    }
#pragma unroll
    for (int j = 0; j < WF4; j++) {
        int f = tid + j*256; int m = f >> 2, c = f & 3;
        Ws[0][c*4+0][m] = rw[j].x; Ws[0][c*4+1][m] = rw[j].y;
        Ws[0][c*4+2][m] = rw[j].z; Ws[0][c*4+3][m] = rw[j].w;
    }
    __syncthreads();

    int nt = K / KT;
    int buf = 0;
    for (int t = 0; t < nt; t++) {
        // prefetch next tile
        if (t + 1 < nt) {
            int kk = (t+1)*KT;
#pragma unroll
            for (int j = 0; j < AF4; j++) {
                int f = tid + j*256; int m = f >> 2, c = f & 3;
                float4 v = *(const float4*)&A[(size_t)(m0+m)*lda + kk + c*4];
                if (BNA) {
                    float4 s = *(const float4*)&bnsc[kk + c*4];
                    float4 h = *(const float4*)&bnsh[kk + c*4];
                    v.x = fmaxf(fmaf(v.x,s.x,h.x),0.f);
                    v.y = fmaxf(fmaf(v.y,s.y,h.y),0.f);
                    v.z = fmaxf(fmaf(v.z,s.z,h.z),0.f);
                    v.w = fmaxf(fmaf(v.w,s.w,h.w),0.f);
                }
                ra[j] = v;
            }
#pragma unroll
            for (int j = 0; j < WF4; j++) {
                int f = tid + j*256; int m = f >> 2, c = f & 3;
                rw[j] = *(const float4*)&W[(size_t)(n0+m)*ldw + kk + c*4];
            }
        }
        // compute current tile
#pragma unroll
        for (int k = 0; k < KT; k++) {
            float a[8], b[TN];
            *(float4*)&a[0] = *(const float4*)&As[buf][k][ty*4];
            *(float4*)&a[4] = *(const float4*)&As[buf][k][ty*4 + BM/2];
            *(float4*)&b[0] = *(const float4*)&Ws[buf][k][tx*4];
            if (TN == 8)
                *(float4*)&b[4] = *(const float4*)&Ws[buf][k][tx*4 + BH];
#pragma unroll
            for (int i = 0; i < 8; i++)
#pragma unroll
                for (int j = 0; j < TN; j++)
                    acc[i][j] = fmaf(a[i], b[j], acc[i][j]);
        }
        // store next tile into other buffer
        if (t + 1 < nt) {
            int nb = buf ^ 1;
#pragma unroll
            for (int j = 0; j < AF4; j++) {
                int f = tid + j*256; int m = f >> 2, c = f & 3;
                As[nb][c*4+0][m] = ra[j].x; As[nb][c*4+1][m] = ra[j].y;
                As[nb][c*4+2][m] = ra[j].z; As[nb][c*4+3][m] = ra[j].w;
            }
#pragma unroll
            for (int j = 0; j < WF4; j++) {
                int f = tid + j*256; int m = f >> 2, c = f & 3;
                Ws[nb][c*4+0][m] = rw[j].x; Ws[nb][c*4+1][m] = rw[j].y;
                Ws[nb][c*4+2][m] = rw[j].z; Ws[nb][c*4+3][m] = rw[j].w;
            }
            __syncthreads();
            buf = nb;
        }
    }

    // ---- epilogue ----
#pragma unroll
    for (int i = 0; i < 8; i++) {
        int m = m0 + ((i < 4) ? (ty*4 + i) : (BM/2 + ty*4 + (i-4)));
#pragma unroll
        for (int half = 0; half < ((TN==8)?2:1); half++) {
            int nb0 = n0 + tx*4 + half*BH;
            float4 v;
            float* vp = &v.x;
#pragma unroll
            for (int j = 0; j < 4; j++) {
                float x = acc[i][half*4 + j];
                int n = nb0 + j;
                if (bias) x += bias[n];
                if (RES == 1) x += res[(size_t)m*N + n];
                if (RES == 2) x += res[(size_t)(m >> 5)*N + n];
                if (ACT == 1) x = fmaxf(x, 0.f);
                if (ACT == 2) x = 0.5f*x*(1.f + erff(x*0.70710678118654752f));
                vp[j] = x;
            }
            *(float4*)&C[(size_t)m*N + nb0] = v;
        }
    }
}

// --------------------------- BN column stats ---------------------------------
__global__ void colstats_kernel(const float* __restrict__ X, int M, int C,
                                float* __restrict__ psum, float* __restrict__ psq)
{
    int c = blockIdx.x * 32 + threadIdx.x;
    int ry = threadIdx.y;                     // 8
    float s = 0.f, s2 = 0.f;
    for (int r = blockIdx.y*8 + ry; r < M; r += gridDim.y*8) {
        float v = X[(size_t)r*C + c];
        s += v; s2 += v*v;
    }
    __shared__ float sh[8][32], sh2[8][32];
    sh[ry][threadIdx.x] = s; sh2[ry][threadIdx.x] = s2;
    __syncthreads();
    if (ry == 0) {
        for (int j = 1; j < 8; j++) { s += sh[j][threadIdx.x]; s2 += sh2[j][threadIdx.x]; }
        psum[blockIdx.y*C + c] = s;
        psq [blockIdx.y*C + c] = s2;
    }
}

__global__ void bnfin_kernel(const float* __restrict__ psum, const float* __restrict__ psq,
                             int C, float invM,
                             const float* __restrict__ g, const float* __restrict__ b,
                             float* __restrict__ scale, float* __restrict__ shift)
{
    int c = blockIdx.x * blockDim.x + threadIdx.x;
    if (c >= C) return;
    float s = 0.f, s2 = 0.f;
    for (int j = 0; j < 64; j++) { s += psum[j*C + c]; s2 += psq[j*C + c]; }
    float mean = s * invM;
    float var  = s2 * invM - mean*mean;
    float sc = g[c] * rsqrtf(var + EPSf);
    scale[c] = sc;
    shift[c] = b[c] - mean*sc;
}

// ------------------------------ max pools ------------------------------------
__global__ void gmax_kernel(const float* __restrict__ f2, float* __restrict__ gm)
{
    int g = blockIdx.x; int c = threadIdx.x;  // 256
    float m = -3.4e38f;
    for (int k = 0; k < KNb; k++) m = fmaxf(m, f2[((size_t)g*KNb + k)*256 + c]);
    gm[(size_t)g*256 + c] = m;
}

__global__ void tokmax_kernel(const float* __restrict__ s2, const float* __restrict__ sos,
                              float* __restrict__ h)
{
    int bg = blockIdx.x; int c = threadIdx.x; // 384
    int g = bg & (GG-1);
    float m = -3.4e38f;
    for (int k = 0; k < KNb; k++) m = fmaxf(m, s2[((size_t)bg*KNb + k)*CC + c]);
    if (g < GG-1) h[(size_t)(bg+1)*CC + c] = m;   // shift-right (sos at g=0)
    if (g == 0)   h[(size_t)bg*CC + c] = sos[c];
}

// --------------------------- positional embedding ----------------------------
__global__ void pos_kernel(const float* __restrict__ cenO, float* __restrict__ pos)
{
    int bg = blockIdx.x; int t = threadIdx.x; // 384
    int ch = t >> 7;
    int rem = t & 127;
    int i = rem >> 1, s = rem & 1;
    float coord = cenO[bg*3 + ch];
    float inv = expf(-(2.f * (float)i / 128.f) * logf(10000.f));
    float ang = coord * inv;
    pos[(size_t)bg*CC + t] = s ? cosf(ang) : sinf(ang);
}

// ------------------------------ LayerNorm ------------------------------------
__global__ void ln_kernel(const float* __restrict__ x, const float* __restrict__ pos,
                          float* __restrict__ xin, float* __restrict__ y,
                          const float* __restrict__ gw, const float* __restrict__ bw)
{
    int r = blockIdx.x; int t = threadIdx.x;  // 128 threads, 3 cols each
    __shared__ float red[128];
    __shared__ float s_mean, s_rstd;
    float v[3];
    float s = 0.f;
#pragma unroll
    for (int i = 0; i < 3; i++) {
        int c = t + i*128;
        float vv = x[(size_t)r*CC + c];
        if (pos) vv += pos[(size_t)r*CC + c];
        if (xin) xin[(size_t)r*CC + c] = vv;
        v[i] = vv; s += vv;
    }
    red[t] = s; __syncthreads();
    for (int off = 64; off > 0; off >>= 1) { if (t < off) red[t] += red[t+off]; __syncthreads(); }
    if (t == 0) s_mean = red[0] / (float)CC;
    __syncthreads();
    float mean = s_mean;
    float d = 0.f;
#pragma unroll
    for (int i = 0; i < 3; i++) { float e = v[i]-mean; d += e*e; }
    red[t] = d; __syncthreads();
    for (int off = 64; off > 0; off >>= 1) { if (t < off) red[t] += red[t+off]; __syncthreads(); }
    if (t == 0) s_rstd = rsqrtf(red[0] / (float)CC + EPSf);
    __syncthreads();
    float rstd = s_rstd;
#pragma unroll
    for (int i = 0; i < 3; i++) {
        int c = t + i*128;
        y[(size_t)r*CC + c] = (v[i]-mean)*rstd*gw[c] + bw[c];
    }
}

// ------------------------------ attention ------------------------------------
__global__ void attn_kernel(const float* __restrict__ qkv, float* __restrict__ out)
{
    __shared__ float sK[128*64];    // 32 KB
    int h = blockIdx.x, b = blockIdx.y;
    int t = threadIdx.x;            // 128 = one query each
    const float* base = qkv + (size_t)b*GG*(3*CC) + h*64;
    const float* src = base + (size_t)t*(3*CC);
    float q[64];
#pragma unroll
    for (int d = 0; d < 64; d += 4) {
        float4 qv = *(const float4*)&src[d];
        q[d+0]=qv.x; q[d+1]=qv.y; q[d+2]=qv.z; q[d+3]=qv.w;
        float4 kv = *(const float4*)&src[CC + d];
        sK[t*64+d+0]=kv.x; sK[t*64+d+1]=kv.y; sK[t*64+d+2]=kv.z; sK[t*64+d+3]=kv.w;
    }
    __syncthreads();
    const float scale = 0.125f;
    float mx = -3.4e38f;
    for (int j = 0; j <= t; j++) {
        float s = 0.f;
#pragma unroll
        for (int d = 0; d < 64; d++) s = fmaf(q[d], sK[j*64+d], s);
        s *= scale;
        if (s > mx) mx = s;
    }
    float acc[64];
#pragma unroll
    for (int d = 0; d < 64; d++) acc[d] = 0.f;
    float sum = 0.f;
    for (int j = 0; j <= t; j++) {
        float s = 0.f;
#pragma unroll
        for (int d = 0; d < 64; d++) s = fmaf(q[d], sK[j*64+d], s);
        float e = expf(s*scale - mx);
        sum += e;
        const float* vrow = base + (size_t)j*(3*CC) + 2*CC;
#pragma unroll
        for (int d = 0; d < 64; d += 4) {
            float4 vv = *(const float4*)&vrow[d];
            acc[d+0] = fmaf(e, vv.x, acc[d+0]);
            acc[d+1] = fmaf(e, vv.y, acc[d+1]);
            acc[d+2] = fmaf(e, vv.z, acc[d+2]);
            acc[d+3] = fmaf(e, vv.w, acc[d+3]);
        }
    }
    float inv = 1.f / sum;
    float* dst = out + ((size_t)(b*GG + t))*CC + h*64;
#pragma unroll
    for (int d = 0; d < 64; d++) dst[d] = acc[d]*inv;
}

// --------------------------------- launch ------------------------------------
static float* sym(const void* s) { void* p = nullptr; cudaGetSymbolAddress(&p, s); return (float*)p; }

extern "C" void kernel_launch(void* const* d_in, const int* in_sizes, int n_in,
                              void* d_out, int out_size)
{
    const float* xyz    = (const float*)d_in[0];
    const float* ec1_w  = (const float*)d_in[1];
    const float* ec1_b  = (const float*)d_in[2];
    const float* bn1_g  = (const float*)d_in[3];
    const float* bn1_b  = (const float*)d_in[4];
    const float* ec2_w  = (const float*)d_in[5];
    const float* ec2_b  = (const float*)d_in[6];
    const float* sc1_w  = (const float*)d_in[7];
    const float* sc1_b  = (const float*)d_in[8];
    const float* bn2_g  = (const float*)d_in[9];
    const float* bn2_b  = (const float*)d_in[10];
    const float* sc2_w  = (const float*)d_in[11];
    const float* sc2_b  = (const float*)d_in[12];
    const float* sos    = (const float*)d_in[13];
    const float* ln1_g  = (const float*)d_in[14];
    const float* ln1_b  = (const float*)d_in[15];
    const float* qkv_w  = (const float*)d_in[16];
    const float* qkv_b  = (const float*)d_in[17];
    const float* out_w  = (const float*)d_in[18];
    const float* out_b  = (const float*)d_in[19];
    const float* ln2_g  = (const float*)d_in[20];
    const float* ln2_b  = (const float*)d_in[21];
    const float* mlp1_w = (const float*)d_in[22];
    const float* mlp1_b = (const float*)d_in[23];
    const float* mlp2_w = (const float*)d_in[24];
    const float* mlp2_b = (const float*)d_in[25];
    const float* lnf_g  = (const float*)d_in[26];
    const float* lnf_b  = (const float*)d_in[27];

    float* p_center  = sym(g_center);
    float* p_centerO = sym(g_centerO);
    float* p_neigh   = sym(g_neigh);
    float* p_f1   = sym(g_f1);
    float* p_f2   = sym(g_f2);
    float* p_gmax = sym(g_gmax);
    float* p_t    = sym(g_t);
    float* p_s1   = sym(g_s1);
    float* p_s2   = sym(g_s2);
    float* p_psum = sym(g_psum);
    float* p_psq  = sym(g_psq);
    float* p_scale= sym(g_scale);
    float* p_shift= sym(g_shift);
    float* p_h    = sym(g_h);
    float* p_pos  = sym(g_pos);
    float* p_xin  = sym(g_xin);
    float* p_y    = sym(g_y);
    float* p_qkv  = sym(g_qkv);
    float* p_attn = sym(g_attn);
    float* p_x1   = sym(g_x1);
    float* p_mh   = sym(g_mh);

    // ---- grouping ----
    fps_kernel  <<<BB, 1024>>>(xyz, p_center);
    order_kernel<<<BB, GG  >>>(p_center, p_centerO);
    knn_kernel  <<<BG, 256 >>>(xyz, p_centerO, p_neigh);

    // ---- encoder ----
    // ec1: (65536,3)@(128,3)^T  (K=3, small-K path)
    gemm_k<0,0,0><<<dim3(128/64, MROWS/64), 256>>>(p_neigh, 3, ec1_w, 3, ec1_b,
                                                   nullptr, nullptr, nullptr,
                                                   p_f1, MROWS, 128, 3);
    colstats_kernel<<<dim3(128/32, 64), dim3(32,8)>>>(p_f1, MROWS, 128, p_psum, p_psq);
    bnfin_kernel<<<1, 128>>>(p_psum, p_psq, 128, 1.f/(float)MROWS, bn1_g, bn1_b, p_scale, p_shift);
    // ec2 (BN1+relu fused on A): (65536,128)->(65536,256)
    gemm2<128,128,8, 0,0,1><<<dim3(256/128, MROWS/128), 256>>>(p_f1, 128, ec2_w, 128, ec2_b,
                                                               nullptr, p_scale, p_shift,
                                                               p_f2, MROWS, 256, 128);
    gmax_kernel<<<BG, 256>>>(p_f2, p_gmax);
    // t = gmax @ sc1_w[:, :256]^T + sc1_b
    gemm2<128,64,4, 0,0,0><<<dim3(512/64, BG/128), 256>>>(p_gmax, 256, sc1_w, 512, sc1_b,
                                                          nullptr, nullptr, nullptr,
                                                          p_t, BG, 512, 256);
    // s1 = f2 @ sc1_w[:, 256:]^T + broadcast(t)
    gemm2<128,128,8, 0,2,0><<<dim3(512/128, MROWS/128), 256>>>(p_f2, 256, sc1_w + 256, 512, nullptr,
                                                               p_t, nullptr, nullptr,
                                                               p_s1, MROWS, 512, 256);
    colstats_kernel<<<dim3(512/32, 64), dim3(32,8)>>>(p_s1, MROWS, 512, p_psum, p_psq);
    bnfin_kernel<<<4, 128>>>(p_psum, p_psq, 512, 1.f/(float)MROWS, bn2_g, bn2_b, p_scale, p_shift);
    // sc2 (BN2+relu fused on A): (65536,512)->(65536,384)
    gemm2<128,128,8, 0,0,1><<<dim3(384/128, MROWS/128), 256>>>(p_s1, 512, sc2_w, 512, sc2_b,
                                                               nullptr, p_scale, p_shift,
                                                               p_s2, MROWS, 384, 512);
    tokmax_kernel<<<BG, CC>>>(p_s2, sos, p_h);
    pos_kernel<<<BG, CC>>>(p_centerO, p_pos);

    // ---- GPT ----
    for (int l = 0; l < LL; l++) {
        const float* qw = qkv_w  + (size_t)l*3*CC*CC;
        const float* qb = qkv_b  + (size_t)l*3*CC;
        const float* ow = out_w  + (size_t)l*CC*CC;
        const float* ob = out_b  + (size_t)l*CC;
        const float* m1w= mlp1_w + (size_t)l*HIDD*CC;
        const float* m1b= mlp1_b + (size_t)l*HIDD;
        const float* m2w= mlp2_w + (size_t)l*CC*HIDD;
        const float* m2b= mlp2_b + (size_t)l*CC;

        // xin = h + pos ; y = LN1(xin)
        ln_kernel<<<BG, 128>>>(p_h, p_pos, p_xin, p_y, ln1_g + l*CC, ln1_b + l*CC);
        // qkv: (2048,384)->(2048,1152)
        gemm2<128,128,8, 0,0,0><<<dim3(3*CC/128, BG/128), 256>>>(p_y, CC, qw, CC, qb,
                                                                 nullptr, nullptr, nullptr,
                                                                 p_qkv, BG, 3*CC, CC);
        attn_kernel<<<dim3(HH, BB), 128>>>(p_qkv, p_attn);
        // x1 = xin + attn @ ow^T + ob  (N=384 -> 64-wide tiles)
        gemm2<128,64,4, 0,1,0><<<dim3(CC/64, BG/128), 256>>>(p_attn, CC, ow, CC, ob,
                                                             p_xin, nullptr, nullptr,
                                                             p_x1, BG, CC, CC);
        // y = LN2(x1)
        ln_kernel<<<BG, 128>>>(p_x1, nullptr, nullptr, p_y, ln2_g + l*CC, ln2_b + l*CC);
        // mh = gelu(y @ m1w^T + m1b)
        gemm2<128,128,8, 2,0,0><<<dim3(HIDD/128, BG/128), 256>>>(p_y, CC, m1w, CC, m1b,
                                                                 nullptr, nullptr, nullptr,
                                                                 p_mh, BG, HIDD, CC);
        // h = x1 + mh @ m2w^T + m2b  (N=384 -> 64-wide tiles)
        gemm2<128,64,4, 0,1,0><<<dim3(CC/64, BG/128), 256>>>(p_mh, HIDD, m2w, HIDD, m2b,
                                                             p_x1, nullptr, nullptr,
                                                             p_h, BG, CC, HIDD);
    }

    // final LN -> output
    ln_kernel<<<BG, 128>>>(p_h, nullptr, nullptr, (float*)d_out, lnf_g, lnf_b);
}

// round 7
// speedup vs baseline: 2.1464x; 1.3093x over previous
#include <cuda_runtime.h>
#include <math.h>
#include <stdint.h>

#define BB 16
#define NP 8192
#define GG 128
#define KNb 32
#define CC 384
#define HH 6
#define LL 12
#define HIDD 1536
#define BG (BB*GG)          /* 2048 */
#define MROWS (BG*KNb)      /* 65536 */
#define EPSf 1e-5f

// ------------------------- scratch (static device memory) -------------------
__device__ float g_center [BG*3];
__device__ float g_centerO[BG*3];
__device__ float g_neigh  [MROWS*3];
__device__ float g_f1 [(size_t)MROWS*128];
__device__ float g_f2 [(size_t)MROWS*256];
__device__ float g_gmax[(size_t)BG*256];
__device__ float g_t  [(size_t)BG*512];
__device__ float g_s1 [(size_t)MROWS*512];
__device__ float g_s2 [(size_t)MROWS*384];
__device__ float g_psum[64*512];
__device__ float g_psq [64*512];
__device__ float g_scale[512];
__device__ float g_shift[512];
__device__ float g_h   [BG*CC];
__device__ float g_pos [BG*CC];
__device__ float g_xin [BG*CC];
__device__ float g_y   [BG*CC];
__device__ float g_qkv [BG*3*CC];
__device__ float g_attn[BG*CC];
__device__ float g_x1  [BG*CC];
__device__ float g_mh  [BG*HIDD];

// ------------------------------- FPS ----------------------------------------
__global__ void fps_kernel(const float* __restrict__ xyz, float* __restrict__ center)
{
    int b = blockIdx.x;
    int t = threadIdx.x;                      // 1024 threads
    const float* X = xyz + (size_t)b * NP * 3;
    float px[8], py[8], pz[8], dd[8];
#pragma unroll
    for (int j = 0; j < 8; j++) {
        int p = t + j * 1024;
        px[j] = X[p*3+0]; py[j] = X[p*3+1]; pz[j] = X[p*3+2];
        dd[j] = 1e10f;
    }
    __shared__ float rv[1024];
    __shared__ int   ri[1024];
    __shared__ int   s_far;
    int far = 0;
    for (int it = 0; it < GG; it++) {
        float cx = X[far*3+0], cy = X[far*3+1], cz = X[far*3+2];
        if (t == 0) {
            center[(b*GG+it)*3+0] = cx;
            center[(b*GG+it)*3+1] = cy;
            center[(b*GG+it)*3+2] = cz;
        }
        float bv = -1.f; int bi = 0;
#pragma unroll
        for (int j = 0; j < 8; j++) {
            float dx = px[j]-cx, dy = py[j]-cy, dz = pz[j]-cz;
            float d = dx*dx + dy*dy + dz*dz;
            if (d < dd[j]) dd[j] = d;
            if (dd[j] > bv) { bv = dd[j]; bi = t + j*1024; }
        }
        rv[t] = bv; ri[t] = bi;
        __syncthreads();
        for (int off = 512; off > 0; off >>= 1) {
            if (t < off) {
                float ov = rv[t+off]; int oi = ri[t+off];
                if (ov > rv[t] || (ov == rv[t] && oi < ri[t])) { rv[t] = ov; ri[t] = oi; }
            }
            __syncthreads();
        }
        if (t == 0) s_far = ri[0];
        __syncthreads();
        far = s_far;
    }
}

// --------------------------- greedy NN ordering ------------------------------
__global__ void order_kernel(const float* __restrict__ cen, float* __restrict__ cenO)
{
    int b = blockIdx.x;
    int t = threadIdx.x;                      // 128 threads
    __shared__ float cx[GG], cy[GG], cz[GG], nn[GG];
    __shared__ int visited[GG];
    __shared__ int s_last;
    __shared__ float rv[GG];
    __shared__ int ri[GG];
    cx[t] = cen[(b*GG+t)*3+0];
    cy[t] = cen[(b*GG+t)*3+1];
    cz[t] = cen[(b*GG+t)*3+2];
    nn[t] = cx[t]*cx[t] + cy[t]*cy[t] + cz[t]*cz[t];
    visited[t] = 0;
    if (t == 0) {
        visited[0] = 1; s_last = 0;
        cenO[(b*GG)*3+0] = cx[0]; cenO[(b*GG)*3+1] = cy[0]; cenO[(b*GG)*3+2] = cz[0];
    }
    __syncthreads();
    for (int step = 1; step < GG; step++) {
        int last = s_last;
        float d;
        if (visited[t]) d = 3.4e38f;
        else {
            float dot = cx[last]*cx[t] + cy[last]*cy[t] + cz[last]*cz[t];
            d = fmaxf(nn[last] + nn[t] - 2.f*dot, 0.f);
        }
        rv[t] = d; ri[t] = t;
        __syncthreads();
        for (int off = 64; off > 0; off >>= 1) {
            if (t < off) {
                float ov = rv[t+off]; int oi = ri[t+off];
                if (ov < rv[t] || (ov == rv[t] && oi < ri[t])) { rv[t] = ov; ri[t] = oi; }
            }
            __syncthreads();
        }
        if (t == 0) {
            int nx = ri[0];
            visited[nx] = 1; s_last = nx;
            cenO[(b*GG+step)*3+0] = cx[nx];
            cenO[(b*GG+step)*3+1] = cy[nx];
            cenO[(b*GG+step)*3+2] = cz[nx];
        }
        __syncthreads();
    }
}

// ------------------------------- kNN + gather --------------------------------
__global__ void knn_kernel(const float* __restrict__ xyz, const float* __restrict__ cenO,
                           float* __restrict__ neigh)
{
    int bg = blockIdx.x;
    int b  = bg >> 7;
    int t  = threadIdx.x;                     // 256 threads
    const float* X = xyz + (size_t)b * NP * 3;
    float cx = cenO[bg*3+0], cy = cenO[bg*3+1], cz = cenO[bg*3+2];
    __shared__ float sd[NP];
    __shared__ float rv[256];
    __shared__ int ri[256];
#pragma unroll
    for (int j = 0; j < NP/256; j++) {
        int p = t + j*256;
        float dx = X[p*3+0]-cx, dy = X[p*3+1]-cy, dz = X[p*3+2]-cz;
        sd[p] = dx*dx + dy*dy + dz*dz;
    }
    __syncthreads();
    for (int k = 0; k < KNb; k++) {
        float bv = 3.4e38f; int bi = 0;
#pragma unroll
        for (int j = 0; j < NP/256; j++) {
            int p = t + j*256;
            float d = sd[p];
            if (d < bv) { bv = d; bi = p; }
        }
        rv[t] = bv; ri[t] = bi;
        __syncthreads();
        for (int off = 128; off > 0; off >>= 1) {
            if (t < off) {
                float ov = rv[t+off]; int oi = ri[t+off];
                if (ov < rv[t] || (ov == rv[t] && oi < ri[t])) { rv[t] = ov; ri[t] = oi; }
            }
            __syncthreads();
        }
        if (t == 0) {
            int m = ri[0];
            neigh[((size_t)bg*KNb + k)*3+0] = X[m*3+0]-cx;
            neigh[((size_t)bg*KNb + k)*3+1] = X[m*3+1]-cy;
            neigh[((size_t)bg*KNb + k)*3+2] = X[m*3+2]-cz;
            sd[m] = 3.4e38f;
        }
        __syncthreads();
    }
}

// --------------------- small-K GEMM (only ec1, K=3) ---------------------------
template<int ACT, int RES, int BNA>
__global__ void __launch_bounds__(256) gemm_k(
    const float* __restrict__ A, int lda,
    const float* __restrict__ W, int ldw,
    const float* __restrict__ bias,
    const float* __restrict__ res,
    const float* __restrict__ bnscale, const float* __restrict__ bnshift,
    float* __restrict__ C, int M, int N, int K)
{
    __shared__ float As[16][64];
    __shared__ float Ws[16][64];
    int tid = threadIdx.x;
    int tx = tid & 15, ty = tid >> 4;
    int m0 = blockIdx.y * 64, n0 = blockIdx.x * 64;
    float acc[4][4] = {};
    for (int kk = 0; kk < K; kk += 16) {
#pragma unroll
        for (int i = 0; i < 4; i++) {
            int idx = tid + i*256;
            int k = idx & 15, m = idx >> 4;
            float a = 0.f, w = 0.f;
            if (kk + k < K) {
                a = A[(size_t)(m0+m)*lda + kk + k];
                if (BNA) a = fmaxf(fmaf(a, bnscale[kk+k], bnshift[kk+k]), 0.f);
                w = W[(size_t)(n0+m)*ldw + kk + k];
            }
            As[k][m] = a;
            Ws[k][m] = w;
        }
        __syncthreads();
#pragma unroll
        for (int k = 0; k < 16; k++) {
            float4 av = *(const float4*)&As[k][ty*4];
            float4 wv = *(const float4*)&Ws[k][tx*4];
            float ar[4] = {av.x, av.y, av.z, av.w};
            float wr[4] = {wv.x, wv.y, wv.z, wv.w};
#pragma unroll
            for (int i = 0; i < 4; i++)
#pragma unroll
                for (int j = 0; j < 4; j++)
                    acc[i][j] = fmaf(ar[i], wr[j], acc[i][j]);
        }
        __syncthreads();
    }
#pragma unroll
    for (int i = 0; i < 4; i++) {
        int m = m0 + ty*4 + i;
#pragma unroll
        for (int j = 0; j < 4; j++) {
            int n = n0 + tx*4 + j;
            float v = acc[i][j];
            if (bias) v += bias[n];
            if (RES == 1) v += res[(size_t)m*N + n];
            if (RES == 2) v += res[(size_t)(m >> 5)*N + n];
            if (ACT == 1) v = fmaxf(v, 0.f);
            if (ACT == 2) v = 0.5f*v*(1.f + erff(v*0.70710678118654752f));
            C[(size_t)m*N + n] = v;
        }
    }
}

// ------------------- tf32 tensor-core GEMM (mma.sync) ------------------------
// 128x128 block tile, KT=16, 256 threads = 8 warps in 2x4; warp tile 64x32
// = 4x4 m16n8k8 tf32 MMAs. A,W staged to smem already rounded to tf32.
// C = act( BN?(A) @ W^T + bias + res ).  M%128==0, N%128==0, K%16==0.
__device__ __forceinline__ float to_tf32(float x)
{
    uint32_t u;
    asm("cvt.rna.tf32.f32 %0, %1;" : "=r"(u) : "f"(x));
    return __uint_as_float(u);
}

template<int ACT, int RES, int BNA>
__global__ void __launch_bounds__(256) gemm_tc(
    const float* __restrict__ A, int lda,
    const float* __restrict__ W, int ldw,
    const float* __restrict__ bias,
    const float* __restrict__ res,
    const float* __restrict__ bnsc, const float* __restrict__ bnsh,
    float* __restrict__ C, int M, int N, int K)
{
    constexpr int BM = 128, BN = 128, KT = 16, PAD = 8;
    __shared__ float As[2][KT][BM+PAD];
    __shared__ float Ws[2][KT][BN+PAD];

    int tid  = threadIdx.x;
    int m0 = blockIdx.y * BM, n0 = blockIdx.x * BN;
    int lane = tid & 31, warp = tid >> 5;
    int wm = warp & 1, wn = warp >> 1;        // 2 x 4 warp grid
    int m0w = wm * 64, n0w = wn * 32;
    int g  = lane >> 2, tg = lane & 3;

    float4 ra[2], rw[2];
    float acc[4][4][4];
#pragma unroll
    for (int a = 0; a < 4; a++)
#pragma unroll
        for (int b = 0; b < 4; b++)
#pragma unroll
            for (int c = 0; c < 4; c++) acc[a][b][c] = 0.f;

    // ---- stage tile 0 ----
#pragma unroll
    for (int j = 0; j < 2; j++) {
        int f = tid + j*256; int m = f >> 2, c = f & 3;
        float4 v = *(const float4*)&A[(size_t)(m0+m)*lda + c*4];
        if (BNA) {
            float4 s = *(const float4*)&bnsc[c*4];
            float4 h = *(const float4*)&bnsh[c*4];
            v.x = fmaxf(fmaf(v.x,s.x,h.x),0.f);
            v.y = fmaxf(fmaf(v.y,s.y,h.y),0.f);
            v.z = fmaxf(fmaf(v.z,s.z,h.z),0.f);
            v.w = fmaxf(fmaf(v.w,s.w,h.w),0.f);
        }
        v.x = to_tf32(v.x); v.y = to_tf32(v.y); v.z = to_tf32(v.z); v.w = to_tf32(v.w);
        ra[j] = v;
        float4 w4 = *(const float4*)&W[(size_t)(n0+m)*ldw + c*4];
        w4.x = to_tf32(w4.x); w4.y = to_tf32(w4.y); w4.z = to_tf32(w4.z); w4.w = to_tf32(w4.w);
        rw[j] = w4;
    }
#pragma unroll
    for (int j = 0; j < 2; j++) {
        int f = tid + j*256; int m = f >> 2, c = f & 3;
        As[0][c*4+0][m] = ra[j].x; As[0][c*4+1][m] = ra[j].y;
        As[0][c*4+2][m] = ra[j].z; As[0][c*4+3][m] = ra[j].w;
        Ws[0][c*4+0][m] = rw[j].x; Ws[0][c*4+1][m] = rw[j].y;
        Ws[0][c*4+2][m] = rw[j].z; Ws[0][c*4+3][m] = rw[j].w;
    }
    __syncthreads();

    int ntiles = K / KT;
    int buf = 0;
    for (int t = 0; t < ntiles; t++) {
        if (t + 1 < ntiles) {
            int kk = (t+1)*KT;
#pragma unroll
            for (int j = 0; j < 2; j++) {
                int f = tid + j*256; int m = f >> 2, c = f & 3;
                float4 v = *(const float4*)&A[(size_t)(m0+m)*lda + kk + c*4];
                if (BNA) {
                    float4 s = *(const float4*)&bnsc[kk + c*4];
                    float4 h = *(const float4*)&bnsh[kk + c*4];
                    v.x = fmaxf(fmaf(v.x,s.x,h.x),0.f);
                    v.y = fmaxf(fmaf(v.y,s.y,h.y),0.f);
                    v.z = fmaxf(fmaf(v.z,s.z,h.z),0.f);
                    v.w = fmaxf(fmaf(v.w,s.w,h.w),0.f);
                }
                v.x = to_tf32(v.x); v.y = to_tf32(v.y); v.z = to_tf32(v.z); v.w = to_tf32(v.w);
                ra[j] = v;
                float4 w4 = *(const float4*)&W[(size_t)(n0+m)*ldw + kk + c*4];
                w4.x = to_tf32(w4.x); w4.y = to_tf32(w4.y); w4.z = to_tf32(w4.z); w4.w = to_tf32(w4.w);
                rw[j] = w4;
            }
        }
        // ---- compute current tile: 2 k8 substeps ----
#pragma unroll
        for (int ks = 0; ks < 2; ks++) {
            uint32_t af[4][4], bf[4][2];
#pragma unroll
            for (int mt = 0; mt < 4; mt++) {
                int r = m0w + mt*16 + g;
                af[mt][0] = __float_as_uint(As[buf][ks*8+tg  ][r  ]);
                af[mt][1] = __float_as_uint(As[buf][ks*8+tg  ][r+8]);
                af[mt][2] = __float_as_uint(As[buf][ks*8+tg+4][r  ]);
                af[mt][3] = __float_as_uint(As[buf][ks*8+tg+4][r+8]);
            }
#pragma unroll
            for (int nt = 0; nt < 4; nt++) {
                int c = n0w + nt*8 + g;
                bf[nt][0] = __float_as_uint(Ws[buf][ks*8+tg  ][c]);
                bf[nt][1] = __float_as_uint(Ws[buf][ks*8+tg+4][c]);
            }
#pragma unroll
            for (int mt = 0; mt < 4; mt++)
#pragma unroll
                for (int nt = 0; nt < 4; nt++) {
                    asm volatile(
                        "mma.sync.aligned.m16n8k8.row.col.f32.tf32.tf32.f32 "
                        "{%0,%1,%2,%3}, {%4,%5,%6,%7}, {%8,%9}, {%0,%1,%2,%3};\n"
                        : "+f"(acc[mt][nt][0]), "+f"(acc[mt][nt][1]),
                          "+f"(acc[mt][nt][2]), "+f"(acc[mt][nt][3])
                        : "r"(af[mt][0]), "r"(af[mt][1]), "r"(af[mt][2]), "r"(af[mt][3]),
                          "r"(bf[nt][0]), "r"(bf[nt][1]));
                }
        }
        if (t + 1 < ntiles) {
            int nb = buf ^ 1;
#pragma unroll
            for (int j = 0; j < 2; j++) {
                int f = tid + j*256; int m = f >> 2, c = f & 3;
                As[nb][c*4+0][m] = ra[j].x; As[nb][c*4+1][m] = ra[j].y;
                As[nb][c*4+2][m] = ra[j].z; As[nb][c*4+3][m] = ra[j].w;
                Ws[nb][c*4+0][m] = rw[j].x; Ws[nb][c*4+1][m] = rw[j].y;
                Ws[nb][c*4+2][m] = rw[j].z; Ws[nb][c*4+3][m] = rw[j].w;
            }
            __syncthreads();
            buf = nb;
        }
    }

    // ---- epilogue ----
#pragma unroll
    for (int mt = 0; mt < 4; mt++) {
#pragma unroll
        for (int nt = 0; nt < 4; nt++) {
            int c0 = n0 + n0w + nt*8 + 2*tg;
#pragma unroll
            for (int h = 0; h < 2; h++) {
                int r = m0 + m0w + mt*16 + g + h*8;
                float x0 = acc[mt][nt][h*2+0];
                float x1 = acc[mt][nt][h*2+1];
                if (bias) { x0 += bias[c0]; x1 += bias[c0+1]; }
                if (RES == 1) { x0 += res[(size_t)r*N + c0]; x1 += res[(size_t)r*N + c0+1]; }
                if (RES == 2) { x0 += res[(size_t)(r >> 5)*N + c0]; x1 += res[(size_t)(r >> 5)*N + c0+1]; }
                if (ACT == 1) { x0 = fmaxf(x0, 0.f); x1 = fmaxf(x1, 0.f); }
                if (ACT == 2) {
                    x0 = 0.5f*x0*(1.f + erff(x0*0.70710678118654752f));
                    x1 = 0.5f*x1*(1.f + erff(x1*0.70710678118654752f));
                }
                float2 v2 = make_float2(x0, x1);
                *(float2*)&C[(size_t)r*N + c0] = v2;
            }
        }
    }
}

// --------------------------- BN column stats ---------------------------------
__global__ void colstats_kernel(const float* __restrict__ X, int M, int C,
                                float* __restrict__ psum, float* __restrict__ psq)
{
    int c = blockIdx.x * 32 + threadIdx.x;
    int ry = threadIdx.y;                     // 8
    float s = 0.f, s2 = 0.f;
    for (int r = blockIdx.y*8 + ry; r < M; r += gridDim.y*8) {
        float v = X[(size_t)r*C + c];
        s += v; s2 += v*v;
    }
    __shared__ float sh[8][32], sh2[8][32];
    sh[ry][threadIdx.x] = s; sh2[ry][threadIdx.x] = s2;
    __syncthreads();
    if (ry == 0) {
        for (int j = 1; j < 8; j++) { s += sh[j][threadIdx.x]; s2 += sh2[j][threadIdx.x]; }
        psum[blockIdx.y*C + c] = s;
        psq [blockIdx.y*C + c] = s2;
    }
}

__global__ void bnfin_kernel(const float* __restrict__ psum, const float* __restrict__ psq,
                             int C, float invM,
                             const float* __restrict__ g, const float* __restrict__ b,
                             float* __restrict__ scale, float* __restrict__ shift)
{
    int c = blockIdx.x * blockDim.x + threadIdx.x;
    if (c >= C) return;
    float s = 0.f, s2 = 0.f;
    for (int j = 0; j < 64; j++) { s += psum[j*C + c]; s2 += psq[j*C + c]; }
    float mean = s * invM;
    float var  = s2 * invM - mean*mean;
    float sc = g[c] * rsqrtf(var + EPSf);
    scale[c] = sc;
    shift[c] = b[c] - mean*sc;
}

// ------------------------------ max pools ------------------------------------
__global__ void gmax_kernel(const float* __restrict__ f2, float* __restrict__ gm)
{
    int g = blockIdx.x; int c = threadIdx.x;  // 256
    float m = -3.4e38f;
    for (int k = 0; k < KNb; k++) m = fmaxf(m, f2[((size_t)g*KNb + k)*256 + c]);
    gm[(size_t)g*256 + c] = m;
}

__global__ void tokmax_kernel(const float* __restrict__ s2, const float* __restrict__ sos,
                              float* __restrict__ h)
{
    int bg = blockIdx.x; int c = threadIdx.x; // 384
    int g = bg & (GG-1);
    float m = -3.4e38f;
    for (int k = 0; k < KNb; k++) m = fmaxf(m, s2[((size_t)bg*KNb + k)*CC + c]);
    if (g < GG-1) h[(size_t)(bg+1)*CC + c] = m;   // shift-right (sos at g=0)
    if (g == 0)   h[(size_t)bg*CC + c] = sos[c];
}

// --------------------------- positional embedding ----------------------------
__global__ void pos_kernel(const float* __restrict__ cenO, float* __restrict__ pos)
{
    int bg = blockIdx.x; int t = threadIdx.x; // 384
    int ch = t >> 7;
    int rem = t & 127;
    int i = rem >> 1, s = rem & 1;
    float coord = cenO[bg*3 + ch];
    float inv = expf(-(2.f * (float)i / 128.f) * logf(10000.f));
    float ang = coord * inv;
    pos[(size_t)bg*CC + t] = s ? cosf(ang) : sinf(ang);
}

// ------------------------------ LayerNorm ------------------------------------
__global__ void ln_kernel(const float* __restrict__ x, const float* __restrict__ pos,
                          float* __restrict__ xin, float* __restrict__ y,
                          const float* __restrict__ gw, const float* __restrict__ bw)
{
    int r = blockIdx.x; int t = threadIdx.x;  // 128 threads, 3 cols each
    __shared__ float red[128];
    __shared__ float s_mean, s_rstd;
    float v[3];
    float s = 0.f;
#pragma unroll
    for (int i = 0; i < 3; i++) {
        int c = t + i*128;
        float vv = x[(size_t)r*CC + c];
        if (pos) vv += pos[(size_t)r*CC + c];
        if (xin) xin[(size_t)r*CC + c] = vv;
        v[i] = vv; s += vv;
    }
    red[t] = s; __syncthreads();
    for (int off = 64; off > 0; off >>= 1) { if (t < off) red[t] += red[t+off]; __syncthreads(); }
    if (t == 0) s_mean = red[0] / (float)CC;
    __syncthreads();
    float mean = s_mean;
    float d = 0.f;
#pragma unroll
    for (int i = 0; i < 3; i++) { float e = v[i]-mean; d += e*e; }
    red[t] = d; __syncthreads();
    for (int off = 64; off > 0; off >>= 1) { if (t < off) red[t] += red[t+off]; __syncthreads(); }
    if (t == 0) s_rstd = rsqrtf(red[0] / (float)CC + EPSf);
    __syncthreads();
    float rstd = s_rstd;
#pragma unroll
    for (int i = 0; i < 3; i++) {
        int c = t + i*128;
        y[(size_t)r*CC + c] = (v[i]-mean)*rstd*gw[c] + bw[c];
    }
}

// ------------------------------ attention ------------------------------------
__global__ void attn_kernel(const float* __restrict__ qkv, float* __restrict__ out)
{
    __shared__ float sK[128*64];    // 32 KB
    int h = blockIdx.x, b = blockIdx.y;
    int t = threadIdx.x;            // 128 = one query each
    const float* base = qkv + (size_t)b*GG*(3*CC) + h*64;
    const float* src = base + (size_t)t*(3*CC);
    float q[64];
#pragma unroll
    for (int d = 0; d < 64; d += 4) {
        float4 qv = *(const float4*)&src[d];
        q[d+0]=qv.x; q[d+1]=qv.y; q[d+2]=qv.z; q[d+3]=qv.w;
        float4 kv = *(const float4*)&src[CC + d];
        sK[t*64+d+0]=kv.x; sK[t*64+d+1]=kv.y; sK[t*64+d+2]=kv.z; sK[t*64+d+3]=kv.w;
    }
    __syncthreads();
    const float scale = 0.125f;
    float mx = -3.4e38f;
    for (int j = 0; j <= t; j++) {
        float s = 0.f;
#pragma unroll
        for (int d = 0; d < 64; d++) s = fmaf(q[d], sK[j*64+d], s);
        s *= scale;
        if (s > mx) mx = s;
    }
    float acc[64];
#pragma unroll
    for (int d = 0; d < 64; d++) acc[d] = 0.f;
    float sum = 0.f;
    for (int j = 0; j <= t; j++) {
        float s = 0.f;
#pragma unroll
        for (int d = 0; d < 64; d++) s = fmaf(q[d], sK[j*64+d], s);
        float e = expf(s*scale - mx);
        sum += e;
        const float* vrow = base + (size_t)j*(3*CC) + 2*CC;
#pragma unroll
        for (int d = 0; d < 64; d += 4) {
            float4 vv = *(const float4*)&vrow[d];
            acc[d+0] = fmaf(e, vv.x, acc[d+0]);
            acc[d+1] = fmaf(e, vv.y, acc[d+1]);
            acc[d+2] = fmaf(e, vv.z, acc[d+2]);
            acc[d+3] = fmaf(e, vv.w, acc[d+3]);
        }
    }
    float inv = 1.f / sum;
    float* dst = out + ((size_t)(b*GG + t))*CC + h*64;
#pragma unroll
    for (int d = 0; d < 64; d++) dst[d] = acc[d]*inv;
}

// --------------------------------- launch ------------------------------------
static float* sym(const void* s) { void* p = nullptr; cudaGetSymbolAddress(&p, s); return (float*)p; }

extern "C" void kernel_launch(void* const* d_in, const int* in_sizes, int n_in,
                              void* d_out, int out_size)
{
    const float* xyz    = (const float*)d_in[0];
    const float* ec1_w  = (const float*)d_in[1];
    const float* ec1_b  = (const float*)d_in[2];
    const float* bn1_g  = (const float*)d_in[3];
    const float* bn1_b  = (const float*)d_in[4];
    const float* ec2_w  = (const float*)d_in[5];
    const float* ec2_b  = (const float*)d_in[6];
    const float* sc1_w  = (const float*)d_in[7];
    const float* sc1_b  = (const float*)d_in[8];
    const float* bn2_g  = (const float*)d_in[9];
    const float* bn2_b  = (const float*)d_in[10];
    const float* sc2_w  = (const float*)d_in[11];
    const float* sc2_b  = (const float*)d_in[12];
    const float* sos    = (const float*)d_in[13];
    const float* ln1_g  = (const float*)d_in[14];
    const float* ln1_b  = (const float*)d_in[15];
    const float* qkv_w  = (const float*)d_in[16];
    const float* qkv_b  = (const float*)d_in[17];
    const float* out_w  = (const float*)d_in[18];
    const float* out_b  = (const float*)d_in[19];
    const float* ln2_g  = (const float*)d_in[20];
    const float* ln2_b  = (const float*)d_in[21];
    const float* mlp1_w = (const float*)d_in[22];
    const float* mlp1_b = (const float*)d_in[23];
    const float* mlp2_w = (const float*)d_in[24];
    const float* mlp2_b = (const float*)d_in[25];
    const float* lnf_g  = (const float*)d_in[26];
    const float* lnf_b  = (const float*)d_in[27];

    float* p_center  = sym(g_center);
    float* p_centerO = sym(g_centerO);
    float* p_neigh   = sym(g_neigh);
    float* p_f1   = sym(g_f1);
    float* p_f2   = sym(g_f2);
    float* p_gmax = sym(g_gmax);
    float* p_t    = sym(g_t);
    float* p_s1   = sym(g_s1);
    float* p_s2   = sym(g_s2);
    float* p_psum = sym(g_psum);
    float* p_psq  = sym(g_psq);
    float* p_scale= sym(g_scale);
    float* p_shift= sym(g_shift);
    float* p_h    = sym(g_h);
    float* p_pos  = sym(g_pos);
    float* p_xin  = sym(g_xin);
    float* p_y    = sym(g_y);
    float* p_qkv  = sym(g_qkv);
    float* p_attn = sym(g_attn);
    float* p_x1   = sym(g_x1);
    float* p_mh   = sym(g_mh);

    // ---- grouping ----
    fps_kernel  <<<BB, 1024>>>(xyz, p_center);
    order_kernel<<<BB, GG  >>>(p_center, p_centerO);
    knn_kernel  <<<BG, 256 >>>(xyz, p_centerO, p_neigh);

    // ---- encoder ----
    // ec1: (65536,3)@(128,3)^T  (K=3, small-K fp32 path)
    gemm_k<0,0,0><<<dim3(128/64, MROWS/64), 256>>>(p_neigh, 3, ec1_w, 3, ec1_b,
                                                   nullptr, nullptr, nullptr,
                                                   p_f1, MROWS, 128, 3);
    colstats_kernel<<<dim3(128/32, 64), dim3(32,8)>>>(p_f1, MROWS, 128, p_psum, p_psq);
    bnfin_kernel<<<1, 128>>>(p_psum, p_psq, 128, 1.f/(float)MROWS, bn1_g, bn1_b, p_scale, p_shift);
    // ec2 (BN1+relu fused on A): (65536,128)->(65536,256)
    gemm_tc<0,0,1><<<dim3(256/128, MROWS/128), 256>>>(p_f1, 128, ec2_w, 128, ec2_b,
                                                      nullptr, p_scale, p_shift,
                                                      p_f2, MROWS, 256, 128);
    gmax_kernel<<<BG, 256>>>(p_f2, p_gmax);
    // t = gmax @ sc1_w[:, :256]^T + sc1_b
    gemm_tc<0,0,0><<<dim3(512/128, BG/128), 256>>>(p_gmax, 256, sc1_w, 512, sc1_b,
                                                   nullptr, nullptr, nullptr,
                                                   p_t, BG, 512, 256);
    // s1 = f2 @ sc1_w[:, 256:]^T + broadcast(t)
    gemm_tc<0,2,0><<<dim3(512/128, MROWS/128), 256>>>(p_f2, 256, sc1_w + 256, 512, nullptr,
                                                      p_t, nullptr, nullptr,
                                                      p_s1, MROWS, 512, 256);
    colstats_kernel<<<dim3(512/32, 64), dim3(32,8)>>>(p_s1, MROWS, 512, p_psum, p_psq);
    bnfin_kernel<<<4, 128>>>(p_psum, p_psq, 512, 1.f/(float)MROWS, bn2_g, bn2_b, p_scale, p_shift);
    // sc2 (BN2+relu fused on A): (65536,512)->(65536,384)
    gemm_tc<0,0,1><<<dim3(384/128, MROWS/128), 256>>>(p_s1, 512, sc2_w, 512, sc2_b,
                                                      nullptr, p_scale, p_shift,
                                                      p_s2, MROWS, 384, 512);
    tokmax_kernel<<<BG, CC>>>(p_s2, sos, p_h);
    pos_kernel<<<BG, CC>>>(p_centerO, p_pos);

    // ---- GPT ----
    for (int l = 0; l < LL; l++) {
        const float* qw = qkv_w  + (size_t)l*3*CC*CC;
        const float* qb = qkv_b  + (size_t)l*3*CC;
        const float* ow = out_w  + (size_t)l*CC*CC;
        const float* ob = out_b  + (size_t)l*CC;
        const float* m1w= mlp1_w + (size_t)l*HIDD*CC;
        const float* m1b= mlp1_b + (size_t)l*HIDD;
        const float* m2w= mlp2_w + (size_t)l*CC*HIDD;
        const float* m2b= mlp2_b + (size_t)l*CC;

        // xin = h + pos ; y = LN1(xin)
        ln_kernel<<<BG, 128>>>(p_h, p_pos, p_xin, p_y, ln1_g + l*CC, ln1_b + l*CC);
        // qkv: (2048,384)->(2048,1152)
        gemm_tc<0,0,0><<<dim3(3*CC/128, BG/128), 256>>>(p_y, CC, qw, CC, qb,
                                                        nullptr, nullptr, nullptr,
                                                        p_qkv, BG, 3*CC, CC);
        attn_kernel<<<dim3(HH, BB), 128>>>(p_qkv, p_attn);
        // x1 = xin + attn @ ow^T + ob
        gemm_tc<0,1,0><<<dim3(CC/128, BG/128), 256>>>(p_attn, CC, ow, CC, ob,
                                                      p_xin, nullptr, nullptr,
                                                      p_x1, BG, CC, CC);
        // y = LN2(x1)
        ln_kernel<<<BG, 128>>>(p_x1, nullptr, nullptr, p_y, ln2_g + l*CC, ln2_b + l*CC);
        // mh = gelu(y @ m1w^T + m1b)
        gemm_tc<2,0,0><<<dim3(HIDD/128, BG/128), 256>>>(p_y, CC, m1w, CC, m1b,
                                                        nullptr, nullptr, nullptr,
                                                        p_mh, BG, HIDD, CC);
        // h = x1 + mh @ m2w^T + m2b
        gemm_tc<0,1,0><<<dim3(CC/128, BG/128), 256>>>(p_mh, HIDD, m2w, HIDD, m2b,
                                                      p_x1, nullptr, nullptr,
                                                      p_h, BG, CC, HIDD);
    }

    // final LN -> output
    ln_kernel<<<BG, 128>>>(p_h, nullptr, nullptr, (float*)d_out, lnf_g, lnf_b);
}

// round 9
// speedup vs baseline: 2.7925x; 1.3010x over previous
#include <cuda_runtime.h>
#include <cuda_bf16.h>
#include <math.h>
#include <stdint.h>

#define BB 16
#define NP 8192
#define GG 128
#define KNb 32
#define CC 384
#define HH 6
#define LL 12
#define HIDD 1536
#define BG (BB*GG)          /* 2048 */
#define MROWS (BG*KNb)      /* 65536 */
#define EPSf 1e-5f

// ------------------------- scratch (static device memory) -------------------
__device__ float g_center [BG*3];
__device__ float g_centerO[BG*3];
__device__ float g_neigh  [MROWS*3];
__device__ float g_f1 [(size_t)MROWS*128];
__device__ float g_f2 [(size_t)MROWS*256];
__device__ float g_gmax[(size_t)BG*256];
__device__ float g_t  [(size_t)BG*512];
__device__ float g_s1 [(size_t)MROWS*512];
__device__ float g_s2 [(size_t)MROWS*384];
__device__ float g_psum[64*512];
__device__ float g_psq [64*512];
__device__ float g_scale[512];
__device__ float g_shift[512];
__device__ float g_h   [BG*CC];
__device__ float g_pos [BG*CC];
__device__ float g_xin [BG*CC];
__device__ float g_y   [BG*CC];
__device__ float g_qkv [BG*3*CC];
__device__ float g_attn[BG*CC];
__device__ float g_x1  [BG*CC];
__device__ float g_mh  [BG*HIDD];

// ------------------------------- FPS ----------------------------------------
__global__ void fps_kernel(const float* __restrict__ xyz, float* __restrict__ center)
{
    int b = blockIdx.x;
    int t = threadIdx.x;                      // 1024 threads = 32 warps
    int lane = t & 31, warp = t >> 5;
    const float* X = xyz + (size_t)b * NP * 3;
    float px[8], py[8], pz[8], dd[8];
#pragma unroll
    for (int j = 0; j < 8; j++) {
        int p = t + j * 1024;
        px[j] = X[p*3+0]; py[j] = X[p*3+1]; pz[j] = X[p*3+2];
        dd[j] = 1e10f;
    }
    __shared__ float rv[32];
    __shared__ int   ri[32];
    __shared__ int   s_far;
    int far = 0;
    for (int it = 0; it < GG; it++) {
        float cx = X[far*3+0], cy = X[far*3+1], cz = X[far*3+2];
        if (t == 0) {
            center[(b*GG+it)*3+0] = cx;
            center[(b*GG+it)*3+1] = cy;
            center[(b*GG+it)*3+2] = cz;
        }
        float bv = -1.f; int bi = 0;
#pragma unroll
        for (int j = 0; j < 8; j++) {
            float dx = px[j]-cx, dy = py[j]-cy, dz = pz[j]-cz;
            float d = dx*dx + dy*dy + dz*dz;
            if (d < dd[j]) dd[j] = d;
            if (dd[j] > bv) { bv = dd[j]; bi = t + j*1024; }
        }
#pragma unroll
        for (int off = 16; off > 0; off >>= 1) {
            float ov = __shfl_down_sync(0xffffffffu, bv, off);
            int   oi = __shfl_down_sync(0xffffffffu, bi, off);
            if (ov > bv || (ov == bv && oi < bi)) { bv = ov; bi = oi; }
        }
        if (lane == 0) { rv[warp] = bv; ri[warp] = bi; }
        __syncthreads();
        if (warp == 0) {
            bv = rv[lane]; bi = ri[lane];
#pragma unroll
            for (int off = 16; off > 0; off >>= 1) {
                float ov = __shfl_down_sync(0xffffffffu, bv, off);
                int   oi = __shfl_down_sync(0xffffffffu, bi, off);
                if (ov > bv || (ov == bv && oi < bi)) { bv = ov; bi = oi; }
            }
            if (lane == 0) s_far = bi;
        }
        __syncthreads();
        far = s_far;
    }
}

// --------------------------- greedy NN ordering ------------------------------
__global__ void order_kernel(const float* __restrict__ cen, float* __restrict__ cenO)
{
    int b = blockIdx.x;
    int t = threadIdx.x;                      // 128 threads = 4 warps
    int lane = t & 31, warp = t >> 5;
    __shared__ float cx[GG], cy[GG], cz[GG], nn[GG];
    __shared__ int visited[GG];
    __shared__ int s_last;
    __shared__ float rv[4];
    __shared__ int ri[4];
    cx[t] = cen[(b*GG+t)*3+0];
    cy[t] = cen[(b*GG+t)*3+1];
    cz[t] = cen[(b*GG+t)*3+2];
    nn[t] = cx[t]*cx[t] + cy[t]*cy[t] + cz[t]*cz[t];
    visited[t] = 0;
    if (t == 0) {
        visited[0] = 1; s_last = 0;
        cenO[(b*GG)*3+0] = cx[0]; cenO[(b*GG)*3+1] = cy[0]; cenO[(b*GG)*3+2] = cz[0];
    }
    __syncthreads();
    for (int step = 1; step < GG; step++) {
        int last = s_last;
        float d;
        if (visited[t]) d = 3.4e38f;
        else {
            float dot = cx[last]*cx[t] + cy[last]*cy[t] + cz[last]*cz[t];
            d = fmaxf(nn[last] + nn[t] - 2.f*dot, 0.f);
        }
        float bv = d; int bi = t;
#pragma unroll
        for (int off = 16; off > 0; off >>= 1) {
            float ov = __shfl_down_sync(0xffffffffu, bv, off);
            int   oi = __shfl_down_sync(0xffffffffu, bi, off);
            if (ov < bv || (ov == bv && oi < bi)) { bv = ov; bi = oi; }
        }
        if (lane == 0) { rv[warp] = bv; ri[warp] = bi; }
        __syncthreads();
        if (t == 0) {
            float mv = rv[0]; int mi = ri[0];
#pragma unroll
            for (int j = 1; j < 4; j++)
                if (rv[j] < mv || (rv[j] == mv && ri[j] < mi)) { mv = rv[j]; mi = ri[j]; }
            visited[mi] = 1; s_last = mi;
            cenO[(b*GG+step)*3+0] = cx[mi];
            cenO[(b*GG+step)*3+1] = cy[mi];
            cenO[(b*GG+step)*3+2] = cz[mi];
        }
        __syncthreads();
    }
}

// ------------------------------- kNN + gather --------------------------------
__global__ void knn_kernel(const float* __restrict__ xyz, const float* __restrict__ cenO,
                           float* __restrict__ neigh)
{
    int bg = blockIdx.x;
    int b  = bg >> 7;
    int t  = threadIdx.x;                     // 256 threads = 8 warps
    int lane = t & 31, warp = t >> 5;
    const float* X = xyz + (size_t)b * NP * 3;
    float cx = cenO[bg*3+0], cy = cenO[bg*3+1], cz = cenO[bg*3+2];
    __shared__ float sd[NP];
    __shared__ float rv[8];
    __shared__ int ri[8];
#pragma unroll
    for (int j = 0; j < NP/256; j++) {
        int p = t + j*256;
        float dx = X[p*3+0]-cx, dy = X[p*3+1]-cy, dz = X[p*3+2]-cz;
        sd[p] = dx*dx + dy*dy + dz*dz;
    }
    __syncthreads();
    for (int k = 0; k < KNb; k++) {
        float bv = 3.4e38f; int bi = 0;
#pragma unroll
        for (int j = 0; j < NP/256; j++) {
            int p = t + j*256;
            float d = sd[p];
            if (d < bv) { bv = d; bi = p; }
        }
#pragma unroll
        for (int off = 16; off > 0; off >>= 1) {
            float ov = __shfl_down_sync(0xffffffffu, bv, off);
            int   oi = __shfl_down_sync(0xffffffffu, bi, off);
            if (ov < bv || (ov == bv && oi < bi)) { bv = ov; bi = oi; }
        }
        if (lane == 0) { rv[warp] = bv; ri[warp] = bi; }
        __syncthreads();
        if (t == 0) {
            float mv = rv[0]; int mi = ri[0];
#pragma unroll
            for (int j = 1; j < 8; j++)
                if (rv[j] < mv || (rv[j] == mv && ri[j] < mi)) { mv = rv[j]; mi = ri[j]; }
            neigh[((size_t)bg*KNb + k)*3+0] = X[mi*3+0]-cx;
            neigh[((size_t)bg*KNb + k)*3+1] = X[mi*3+1]-cy;
            neigh[((size_t)bg*KNb + k)*3+2] = X[mi*3+2]-cz;
            sd[mi] = 3.4e38f;
        }
        __syncthreads();
    }
}

// --------------------- small-K GEMM (only ec1, K=3) ---------------------------
template<int ACT, int RES, int BNA>
__global__ void __launch_bounds__(256) gemm_k(
    const float* __restrict__ A, int lda,
    const float* __restrict__ W, int ldw,
    const float* __restrict__ bias,
    const float* __restrict__ res,
    const float* __restrict__ bnscale, const float* __restrict__ bnshift,
    float* __restrict__ C, int M, int N, int K)
{
    __shared__ float As[16][64];
    __shared__ float Ws[16][64];
    int tid = threadIdx.x;
    int tx = tid & 15, ty = tid >> 4;
    int m0 = blockIdx.y * 64, n0 = blockIdx.x * 64;
    float acc[4][4] = {};
    for (int kk = 0; kk < K; kk += 16) {
#pragma unroll
        for (int i = 0; i < 4; i++) {
            int idx = tid + i*256;
            int k = idx & 15, m = idx >> 4;
            float a = 0.f, w = 0.f;
            if (kk + k < K) {
                a = A[(size_t)(m0+m)*lda + kk + k];
                if (BNA) a = fmaxf(fmaf(a, bnscale[kk+k], bnshift[kk+k]), 0.f);
                w = W[(size_t)(n0+m)*ldw + kk + k];
            }
            As[k][m] = a;
            Ws[k][m] = w;
        }
        __syncthreads();
#pragma unroll
        for (int k = 0; k < 16; k++) {
            float4 av = *(const float4*)&As[k][ty*4];
            float4 wv = *(const float4*)&Ws[k][tx*4];
            float ar[4] = {av.x, av.y, av.z, av.w};
            float wr[4] = {wv.x, wv.y, wv.z, wv.w};
#pragma unroll
            for (int i = 0; i < 4; i++)
#pragma unroll
                for (int j = 0; j < 4; j++)
                    acc[i][j] = fmaf(ar[i], wr[j], acc[i][j]);
        }
        __syncthreads();
    }
#pragma unroll
    for (int i = 0; i < 4; i++) {
        int m = m0 + ty*4 + i;
#pragma unroll
        for (int j = 0; j < 4; j++) {
            int n = n0 + tx*4 + j;
            float v = acc[i][j];
            if (bias) v += bias[n];
            if (RES == 1) v += res[(size_t)m*N + n];
            if (RES == 2) v += res[(size_t)(m >> 5)*N + n];
            if (ACT == 1) v = fmaxf(v, 0.f);
            if (ACT == 2) v = 0.5f*v*(1.f + erff(v*0.70710678118654752f));
            C[(size_t)m*N + n] = v;
        }
    }
}

// ------------------- bf16 tensor-core GEMM (mma.sync m16n8k16) ---------------
// 128x128 block tile, KT=16, 256 threads = 8 warps (2x4); warp tile 64x32
// = 4x4 m16n8k16 MMAs per k16-tile. Tiles staged to smem as bf16,
// row-major [m][k] / [n][k] padded to 24 elems (48B, 12-bank stride ->
// conflict-free fragment loads). C = act( BN?(A) @ W^T + bias + res ).
// M%128==0, N%128==0, K%16==0.
template<int ACT, int RES, int BNA>
__global__ void __launch_bounds__(256) gemm_bf(
    const float* __restrict__ A, int lda,
    const float* __restrict__ W, int ldw,
    const float* __restrict__ bias,
    const float* __restrict__ res,
    const float* __restrict__ bnsc, const float* __restrict__ bnsh,
    float* __restrict__ C, int M, int N, int K)
{
    constexpr int BM = 128, BN = 128, KT = 16, RS = 24;   // RS = padded row stride
    __shared__ __align__(16) __nv_bfloat16 As[2][BM][RS];
    __shared__ __align__(16) __nv_bfloat16 Ws[2][BN][RS];

    int tid  = threadIdx.x;
    int m0 = blockIdx.y * BM, n0 = blockIdx.x * BN;
    int lane = tid & 31, warp = tid >> 5;
    int wm = warp & 1, wn = warp >> 1;        // 2 x 4 warp grid
    int m0w = wm * 64, n0w = wn * 32;
    int g  = lane >> 2, tg = lane & 3;

    uint2 ra[2], rw[2];
    float acc[4][4][4];
#pragma unroll
    for (int a = 0; a < 4; a++)
#pragma unroll
        for (int b = 0; b < 4; b++)
#pragma unroll
            for (int c = 0; c < 4; c++) acc[a][b][c] = 0.f;

#pragma unroll
    for (int j = 0; j < 2; j++) {
        int f = tid + j*256; int m = f >> 2, c = f & 3;
        float4 v = *(const float4*)&A[(size_t)(m0+m)*lda + c*4];
        if (BNA) {
            float4 s = *(const float4*)&bnsc[c*4];
            float4 h = *(const float4*)&bnsh[c*4];
            v.x = fmaxf(fmaf(v.x,s.x,h.x),0.f);
            v.y = fmaxf(fmaf(v.y,s.y,h.y),0.f);
            v.z = fmaxf(fmaf(v.z,s.z,h.z),0.f);
            v.w = fmaxf(fmaf(v.w,s.w,h.w),0.f);
        }
        union { __nv_bfloat162 h2[2]; uint2 u; } cv;
        cv.h2[0] = __floats2bfloat162_rn(v.x, v.y);
        cv.h2[1] = __floats2bfloat162_rn(v.z, v.w);
        ra[j] = cv.u;
        float4 w4 = *(const float4*)&W[(size_t)(n0+m)*ldw + c*4];
        union { __nv_bfloat162 h2[2]; uint2 u; } cw;
        cw.h2[0] = __floats2bfloat162_rn(w4.x, w4.y);
        cw.h2[1] = __floats2bfloat162_rn(w4.z, w4.w);
        rw[j] = cw.u;
    }
#pragma unroll
    for (int j = 0; j < 2; j++) {
        int f = tid + j*256; int m = f >> 2, c = f & 3;
        *(uint2*)&As[0][m][c*4] = ra[j];
        *(uint2*)&Ws[0][m][c*4] = rw[j];
    }
    __syncthreads();

    int ntiles = K / KT;
    int buf = 0;
    for (int t = 0; t < ntiles; t++) {
        if (t + 1 < ntiles) {
            int kk = (t+1)*KT;
#pragma unroll
            for (int j = 0; j < 2; j++) {
                int f = tid + j*256; int m = f >> 2, c = f & 3;
                float4 v = *(const float4*)&A[(size_t)(m0+m)*lda + kk + c*4];
                if (BNA) {
                    float4 s = *(const float4*)&bnsc[kk + c*4];
                    float4 h = *(const float4*)&bnsh[kk + c*4];
                    v.x = fmaxf(fmaf(v.x,s.x,h.x),0.f);
                    v.y = fmaxf(fmaf(v.y,s.y,h.y),0.f);
                    v.z = fmaxf(fmaf(v.z,s.z,h.z),0.f);
                    v.w = fmaxf(fmaf(v.w,s.w,h.w),0.f);
                }
                union { __nv_bfloat162 h2[2]; uint2 u; } cv;
                cv.h2[0] = __floats2bfloat162_rn(v.x, v.y);
                cv.h2[1] = __floats2bfloat162_rn(v.z, v.w);
                ra[j] = cv.u;
                float4 w4 = *(const float4*)&W[(size_t)(n0+m)*ldw + kk + c*4];
                union { __nv_bfloat162 h2[2]; uint2 u; } cw;
                cw.h2[0] = __floats2bfloat162_rn(w4.x, w4.y);
                cw.h2[1] = __floats2bfloat162_rn(w4.z, w4.w);
                rw[j] = cw.u;
            }
        }
        // ---- compute current k16 tile ----
        {
            uint32_t af[4][4], bfr[4][2];
#pragma unroll
            for (int mt = 0; mt < 4; mt++) {
                int r = m0w + mt*16 + g;
                af[mt][0] = *(const uint32_t*)&As[buf][r  ][2*tg];
                af[mt][1] = *(const uint32_t*)&As[buf][r+8][2*tg];
                af[mt][2] = *(const uint32_t*)&As[buf][r  ][2*tg+8];
                af[mt][3] = *(const uint32_t*)&As[buf][r+8][2*tg+8];
            }
#pragma unroll
            for (int nt = 0; nt < 4; nt++) {
                int c = n0w + nt*8 + g;
                bfr[nt][0] = *(const uint32_t*)&Ws[buf][c][2*tg];
                bfr[nt][1] = *(const uint32_t*)&Ws[buf][c][2*tg+8];
            }
#pragma unroll
            for (int mt = 0; mt < 4; mt++)
#pragma unroll
                for (int nt = 0; nt < 4; nt++) {
                    asm volatile(
                        "mma.sync.aligned.m16n8k16.row.col.f32.bf16.bf16.f32 "
                        "{%0,%1,%2,%3}, {%4,%5,%6,%7}, {%8,%9}, {%0,%1,%2,%3};\n"
                        : "+f"(acc[mt][nt][0]), "+f"(acc[mt][nt][1]),
                          "+f"(acc[mt][nt][2]), "+f"(acc[mt][nt][3])
                        : "r"(af[mt][0]), "r"(af[mt][1]), "r"(af[mt][2]), "r"(af[mt][3]),
                          "r"(bfr[nt][0]), "r"(bfr[nt][1]));
                }
        }
        if (t + 1 < ntiles) {
            int nb = buf ^ 1;
            __syncthreads();
#pragma unroll
            for (int j = 0; j < 2; j++) {
                int f = tid + j*256; int m = f >> 2, c = f & 3;
                *(uint2*)&As[nb][m][c*4] = ra[j];
                *(uint2*)&Ws[nb][m][c*4] = rw[j];
            }
            __syncthreads();
            buf = nb;
        }
    }

    // ---- epilogue (same C layout as m16n8k8) ----
#pragma unroll
    for (int mt = 0; mt < 4; mt++) {
#pragma unroll
        for (int nt = 0; nt < 4; nt++) {
            int c0 = n0 + n0w + nt*8 + 2*tg;
#pragma unroll
            for (int h = 0; h < 2; h++) {
                int r = m0 + m0w + mt*16 + g + h*8;
                float x0 = acc[mt][nt][h*2+0];
                float x1 = acc[mt][nt][h*2+1];
                if (bias) { x0 += bias[c0]; x1 += bias[c0+1]; }
                if (RES == 1) { x0 += res[(size_t)r*N + c0]; x1 += res[(size_t)r*N + c0+1]; }
                if (RES == 2) { x0 += res[(size_t)(r >> 5)*N + c0]; x1 += res[(size_t)(r >> 5)*N + c0+1]; }
                if (ACT == 1) { x0 = fmaxf(x0, 0.f); x1 = fmaxf(x1, 0.f); }
                if (ACT == 2) {
                    x0 = 0.5f*x0*(1.f + erff(x0*0.70710678118654752f));
                    x1 = 0.5f*x1*(1.f + erff(x1*0.70710678118654752f));
                }
                float2 v2 = make_float2(x0, x1);
                *(float2*)&C[(size_t)r*N + c0] = v2;
            }
        }
    }
}

// --------------------------- BN column stats ---------------------------------
__global__ void colstats_kernel(const float* __restrict__ X, int M, int C,
                                float* __restrict__ psum, float* __restrict__ psq)
{
    int c = blockIdx.x * 32 + threadIdx.x;
    int ry = threadIdx.y;                     // 8
    float s = 0.f, s2 = 0.f;
    for (int r = blockIdx.y*8 + ry; r < M; r += gridDim.y*8) {
        float v = X[(size_t)r*C + c];
        s += v; s2 += v*v;
    }
    __shared__ float sh[8][32], sh2[8][32];
    sh[ry][threadIdx.x] = s; sh2[ry][threadIdx.x] = s2;
    __syncthreads();
    if (ry == 0) {
        for (int j = 1; j < 8; j++) { s += sh[j][threadIdx.x]; s2 += sh2[j][threadIdx.x]; }
        psum[blockIdx.y*C + c] = s;
        psq [blockIdx.y*C + c] = s2;
    }
}

__global__ void bnfin_kernel(const float* __restrict__ psum, const float* __restrict__ psq,
                             int C, float invM,
                             const float* __restrict__ g, const float* __restrict__ b,
                             float* __restrict__ scale, float* __restrict__ shift)
{
    int c = blockIdx.x * blockDim.x + threadIdx.x;
    if (c >= C) return;
    float s = 0.f, s2 = 0.f;
    for (int j = 0; j < 64; j++) { s += psum[j*C + c]; s2 += psq[j*C + c]; }
    float mean = s * invM;
    float var  = s2 * invM - mean*mean;
    float sc = g[c] * rsqrtf(var + EPSf);
    scale[c] = sc;
    shift[c] = b[c] - mean*sc;
}

// ------------------------------ max pools ------------------------------------
__global__ void gmax_kernel(const float* __restrict__ f2, float* __restrict__ gm)
{
    int g = blockIdx.x; int c = threadIdx.x;  // 256
    float m = -3.4e38f;
    for (int k = 0; k < KNb; k++) m = fmaxf(m, f2[((size_t)g*KNb + k)*256 + c]);
    gm[(size_t)g*256 + c] = m;
}

__global__ void tokmax_kernel(const float* __restrict__ s2, const float* __restrict__ sos,
                              float* __restrict__ h)
{
    int bg = blockIdx.x; int c = threadIdx.x; // 384
    int g = bg & (GG-1);
    float m = -3.4e38f;
    for (int k = 0; k < KNb; k++) m = fmaxf(m, s2[((size_t)bg*KNb + k)*CC + c]);
    if (g < GG-1) h[(size_t)(bg+1)*CC + c] = m;   // shift-right (sos at g=0)
    if (g == 0)   h[(size_t)bg*CC + c] = sos[c];
}

// --------------------------- positional embedding ----------------------------
__global__ void pos_kernel(const float* __restrict__ cenO, float* __restrict__ pos)
{
    int bg = blockIdx.x; int t = threadIdx.x; // 384
    int ch = t >> 7;
    int rem = t & 127;
    int i = rem >> 1, s = rem & 1;
    float coord = cenO[bg*3 + ch];
    float inv = expf(-(2.f * (float)i / 128.f) * logf(10000.f));
    float ang = coord * inv;
    pos[(size_t)bg*CC + t] = s ? cosf(ang) : sinf(ang);
}

// ------------------------------ LayerNorm (warp per row) ---------------------
__global__ void ln_kernel(const float* __restrict__ x, const float* __restrict__ pos,
                          float* __restrict__ xin, float* __restrict__ y,
                          const float* __restrict__ gw, const float* __restrict__ bw)
{
    int lane = threadIdx.x & 31, warp = threadIdx.x >> 5;
    int r = blockIdx.x * 4 + warp;            // 128 threads = 4 rows
    const int NV = CC / 32;                   // 12
    float v[NV];
    float s = 0.f;
#pragma unroll
    for (int i = 0; i < NV; i++) {
        int c = lane + i*32;
        float vv = x[(size_t)r*CC + c];
        if (pos) vv += pos[(size_t)r*CC + c];
        if (xin) xin[(size_t)r*CC + c] = vv;
        v[i] = vv; s += vv;
    }
#pragma unroll
    for (int off = 16; off > 0; off >>= 1) s += __shfl_xor_sync(0xffffffffu, s, off);
    float mean = s / (float)CC;
    float d = 0.f;
#pragma unroll
    for (int i = 0; i < NV; i++) { float e = v[i]-mean; d += e*e; }
#pragma unroll
    for (int off = 16; off > 0; off >>= 1) d += __shfl_xor_sync(0xffffffffu, d, off);
    float rstd = rsqrtf(d / (float)CC + EPSf);
#pragma unroll
    for (int i = 0; i < NV; i++) {
        int c = lane + i*32;
        y[(size_t)r*CC + c] = (v[i]-mean)*rstd*gw[c] + bw[c];
    }
}

// ------------------------------ attention ------------------------------------
__global__ void attn_kernel(const float* __restrict__ qkv, float* __restrict__ out)
{
    __shared__ float sK[128*64];    // 32 KB
    int h = blockIdx.x, b = blockIdx.y;
    int t = threadIdx.x;            // 128 = one query each
    const float* base = qkv + (size_t)b*GG*(3*CC) + h*64;
    const float* src = base + (size_t)t*(3*CC);
    float q[64];
#pragma unroll
    for (int d = 0; d < 64; d += 4) {
        float4 qv = *(const float4*)&src[d];
        q[d+0]=qv.x; q[d+1]=qv.y; q[d+2]=qv.z; q[d+3]=qv.w;
        float4 kv = *(const float4*)&src[CC + d];
        sK[t*64+d+0]=kv.x; sK[t*64+d+1]=kv.y; sK[t*64+d+2]=kv.z; sK[t*64+d+3]=kv.w;
    }
    __syncthreads();
    const float scale = 0.125f;
    float mx = -3.4e38f;
    for (int j = 0; j <= t; j++) {
        float s = 0.f;
#pragma unroll
        for (int d = 0; d < 64; d++) s = fmaf(q[d], sK[j*64+d], s);
        s *= scale;
        if (s > mx) mx = s;
    }
    float acc[64];
#pragma unroll
    for (int d = 0; d < 64; d++) acc[d] = 0.f;
    float sum = 0.f;
    for (int j = 0; j <= t; j++) {
        float s = 0.f;
#pragma unroll
        for (int d = 0; d < 64; d++) s = fmaf(q[d], sK[j*64+d], s);
        float e = expf(s*scale - mx);
        sum += e;
        const float* vrow = base + (size_t)j*(3*CC) + 2*CC;
#pragma unroll
        for (int d = 0; d < 64; d += 4) {
            float4 vv = *(const float4*)&vrow[d];
            acc[d+0] = fmaf(e, vv.x, acc[d+0]);
            acc[d+1] = fmaf(e, vv.y, acc[d+1]);
            acc[d+2] = fmaf(e, vv.z, acc[d+2]);
            acc[d+3] = fmaf(e, vv.w, acc[d+3]);
        }
    }
    float inv = 1.f / sum;
    float* dst = out + ((size_t)(b*GG + t))*CC + h*64;
#pragma unroll
    for (int d = 0; d < 64; d++) dst[d] = acc[d]*inv;
}

// --------------------------------- launch ------------------------------------
static float* sym(const void* s) { void* p = nullptr; cudaGetSymbolAddress(&p, s); return (float*)p; }

extern "C" void kernel_launch(void* const* d_in, const int* in_sizes, int n_in,
                              void* d_out, int out_size)
{
    const float* xyz    = (const float*)d_in[0];
    const float* ec1_w  = (const float*)d_in[1];
    const float* ec1_b  = (const float*)d_in[2];
    const float* bn1_g  = (const float*)d_in[3];
    const float* bn1_b  = (const float*)d_in[4];
    const float* ec2_w  = (const float*)d_in[5];
    const float* ec2_b  = (const float*)d_in[6];
    const float* sc1_w  = (const float*)d_in[7];
    const float* sc1_b  = (const float*)d_in[8];
    const float* bn2_g  = (const float*)d_in[9];
    const float* bn2_b  = (const float*)d_in[10];
    const float* sc2_w  = (const float*)d_in[11];
    const float* sc2_b  = (const float*)d_in[12];
    const float* sos    = (const float*)d_in[13];
    const float* ln1_g  = (const float*)d_in[14];
    const float* ln1_b  = (const float*)d_in[15];
    const float* qkv_w  = (const float*)d_in[16];
    const float* qkv_b  = (const float*)d_in[17];
    const float* out_w  = (const float*)d_in[18];
    const float* out_b  = (const float*)d_in[19];
    const float* ln2_g  = (const float*)d_in[20];
    const float* ln2_b  = (const float*)d_in[21];
    const float* mlp1_w = (const float*)d_in[22];
    const float* mlp1_b = (const float*)d_in[23];
    const float* mlp2_w = (const float*)d_in[24];
    const float* mlp2_b = (const float*)d_in[25];
    const float* lnf_g  = (const float*)d_in[26];
    const float* lnf_b  = (const float*)d_in[27];

    float* p_center  = sym(g_center);
    float* p_centerO = sym(g_centerO);
    float* p_neigh   = sym(g_neigh);
    float* p_f1   = sym(g_f1);
    float* p_f2   = sym(g_f2);
    float* p_gmax = sym(g_gmax);
    float* p_t    = sym(g_t);
    float* p_s1   = sym(g_s1);
    float* p_s2   = sym(g_s2);
    float* p_psum = sym(g_psum);
    float* p_psq  = sym(g_psq);
    float* p_scale= sym(g_scale);
    float* p_shift= sym(g_shift);
    float* p_h    = sym(g_h);
    float* p_pos  = sym(g_pos);
    float* p_xin  = sym(g_xin);
    float* p_y    = sym(g_y);
    float* p_qkv  = sym(g_qkv);
    float* p_attn = sym(g_attn);
    float* p_x1   = sym(g_x1);
    float* p_mh   = sym(g_mh);

    // ---- grouping ----
    fps_kernel  <<<BB, 1024>>>(xyz, p_center);
    order_kernel<<<BB, GG  >>>(p_center, p_centerO);
    knn_kernel  <<<BG, 256 >>>(xyz, p_centerO, p_neigh);

    // ---- encoder ----
    // ec1: (65536,3)@(128,3)^T  (K=3, small-K fp32 path)
    gemm_k<0,0,0><<<dim3(128/64, MROWS/64), 256>>>(p_neigh, 3, ec1_w, 3, ec1_b,
                                                   nullptr, nullptr, nullptr,
                                                   p_f1, MROWS, 128, 3);
    colstats_kernel<<<dim3(128/32, 64), dim3(32,8)>>>(p_f1, MROWS, 128, p_psum, p_psq);
    bnfin_kernel<<<1, 128>>>(p_psum, p_psq, 128, 1.f/(float)MROWS, bn1_g, bn1_b, p_scale, p_shift);
    // ec2 (BN1+relu fused on A): (65536,128)->(65536,256)
    gemm_bf<0,0,1><<<dim3(256/128, MROWS/128), 256>>>(p_f1, 128, ec2_w, 128, ec2_b,
                                                      nullptr, p_scale, p_shift,
                                                      p_f2, MROWS, 256, 128);
    gmax_kernel<<<BG, 256>>>(p_f2, p_gmax);
    // t = gmax @ sc1_w[:, :256]^T + sc1_b
    gemm_bf<0,0,0><<<dim3(512/128, BG/128), 256>>>(p_gmax, 256, sc1_w, 512, sc1_b,
                                                   nullptr, nullptr, nullptr,
                                                   p_t, BG, 512, 256);
    // s1 = f2 @ sc1_w[:, 256:]^T + broadcast(t)
    gemm_bf<0,2,0><<<dim3(512/128, MROWS/128), 256>>>(p_f2, 256, sc1_w + 256, 512, nullptr,
                                                      p_t, nullptr, nullptr,
                                                      p_s1, MROWS, 512, 256);
    colstats_kernel<<<dim3(512/32, 64), dim3(32,8)>>>(p_s1, MROWS, 512, p_psum, p_psq);
    bnfin_kernel<<<4, 128>>>(p_psum, p_psq, 512, 1.f/(float)MROWS, bn2_g, bn2_b, p_scale, p_shift);
    // sc2 (BN2+relu fused on A): (65536,512)->(65536,384)
    gemm_bf<0,0,1><<<dim3(384/128, MROWS/128), 256>>>(p_s1, 512, sc2_w, 512, sc2_b,
                                                      nullptr, p_scale, p_shift,
                                                      p_s2, MROWS, 384, 512);
    tokmax_kernel<<<BG, CC>>>(p_s2, sos, p_h);
    pos_kernel<<<BG, CC>>>(p_centerO, p_pos);

    // ---- GPT ----
    for (int l = 0; l < LL; l++) {
        const float* qw = qkv_w  + (size_t)l*3*CC*CC;
        const float* qb = qkv_b  + (size_t)l*3*CC;
        const float* ow = out_w  + (size_t)l*CC*CC;
        const float* ob = out_b  + (size_t)l*CC;
        const float* m1w= mlp1_w + (size_t)l*HIDD*CC;
        const float* m1b= mlp1_b + (size_t)l*HIDD;
        const float* m2w= mlp2_w + (size_t)l*CC*HIDD;
        const float* m2b= mlp2_b + (size_t)l*CC;

        // xin = h + pos ; y = LN1(xin)
        ln_kernel<<<BG/4, 128>>>(p_h, p_pos, p_xin, p_y, ln1_g + l*CC, ln1_b + l*CC);
        // qkv: (2048,384)->(2048,1152)
        gemm_bf<0,0,0><<<dim3(3*CC/128, BG/128), 256>>>(p_y, CC, qw, CC, qb,
                                                        nullptr, nullptr, nullptr,
                                                        p_qkv, BG, 3*CC, CC);
        attn_kernel<<<dim3(HH, BB), 128>>>(p_qkv, p_attn);
        // x1 = xin + attn @ ow^T + ob
        gemm_bf<0,1,0><<<dim3(CC/128, BG/128), 256>>>(p_attn, CC, ow, CC, ob,
                                                      p_xin, nullptr, nullptr,
                                                      p_x1, BG, CC, CC);
        // y = LN2(x1)
        ln_kernel<<<BG/4, 128>>>(p_x1, nullptr, nullptr, p_y, ln2_g + l*CC, ln2_b + l*CC);
        // mh = gelu(y @ m1w^T + m1b)
        gemm_bf<2,0,0><<<dim3(HIDD/128, BG/128), 256>>>(p_y, CC, m1w, CC, m1b,
                                                        nullptr, nullptr, nullptr,
                                                        p_mh, BG, HIDD, CC);
        // h = x1 + mh @ m2w^T + m2b
        gemm_bf<0,1,0><<<dim3(CC/128, BG/128), 256>>>(p_mh, HIDD, m2w, HIDD, m2b,
                                                      p_x1, nullptr, nullptr,
                                                      p_h, BG, CC, HIDD);
    }

    // final LN -> output
    ln_kernel<<<BG/4, 128>>>(p_h, nullptr, nullptr, (float*)d_out, lnf_g, lnf_b);
}

// round 10
// speedup vs baseline: 3.6987x; 1.3245x over previous
#include <cuda_runtime.h>
#include <cuda_bf16.h>
#include <math.h>
#include <stdint.h>

#define BB 16
#define NP 8192
#define GG 128
#define KNb 32
#define CC 384
#define HH 6
#define LL 12
#define HIDD 1536
#define BG (BB*GG)          /* 2048 */
#define MROWS (BG*KNb)      /* 65536 */
#define EPSf 1e-5f

// ------------------------- scratch (static device memory) -------------------
__device__ float g_center [BG*3];
__device__ float g_centerO[BG*3];
__device__ float g_neigh  [MROWS*3];
__device__ float g_f1 [(size_t)MROWS*128];
__device__ float g_f2 [(size_t)MROWS*256];
__device__ float g_gmax[(size_t)BG*256];
__device__ float g_t  [(size_t)BG*512];
__device__ float g_s1 [(size_t)MROWS*512];
__device__ float g_s2 [(size_t)MROWS*384];
__device__ float g_psum[64*512];
__device__ float g_psq [64*512];
__device__ float g_scale[512];
__device__ float g_shift[512];
__device__ float g_h   [BG*CC];
__device__ float g_pos [BG*CC];
__device__ float g_xin [BG*CC];
__device__ float g_x1  [BG*CC];
__device__ float g_qkv [BG*3*CC];
// bf16 activations (GEMM inputs only)
__device__ __nv_bfloat16 g_ybf  [BG*CC];
__device__ __nv_bfloat16 g_attnbf[BG*CC];
__device__ __nv_bfloat16 g_mhbf [BG*HIDD];
// bf16 pre-converted weights
__device__ __nv_bfloat16 g_wqkv[(size_t)LL*3*CC*CC];
__device__ __nv_bfloat16 g_wout[(size_t)LL*CC*CC];
__device__ __nv_bfloat16 g_wm1 [(size_t)LL*HIDD*CC];
__device__ __nv_bfloat16 g_wm2 [(size_t)LL*CC*HIDD];
__device__ __nv_bfloat16 g_wec2[256*128];
__device__ __nv_bfloat16 g_wsc1[512*512];
__device__ __nv_bfloat16 g_wsc2[384*512];

// ------------------------ fp32 -> bf16 conversion ----------------------------
__global__ void cvt_kernel(const float* __restrict__ src, __nv_bfloat16* __restrict__ dst, int n4)
{
    int i = blockIdx.x * blockDim.x + threadIdx.x;
    if (i >= n4) return;
    float4 v = *(const float4*)&src[i*4];
    union { __nv_bfloat162 h2[2]; uint2 u; } c;
    c.h2[0] = __floats2bfloat162_rn(v.x, v.y);
    c.h2[1] = __floats2bfloat162_rn(v.z, v.w);
    *(uint2*)&dst[i*4] = c.u;
}

// ------------------------------- FPS ----------------------------------------
__global__ void fps_kernel(const float* __restrict__ xyz, float* __restrict__ center)
{
    int b = blockIdx.x;
    int t = threadIdx.x;                      // 1024 threads = 32 warps
    int lane = t & 31, warp = t >> 5;
    const float* X = xyz + (size_t)b * NP * 3;
    float px[8], py[8], pz[8], dd[8];
#pragma unroll
    for (int j = 0; j < 8; j++) {
        int p = t + j * 1024;
        px[j] = X[p*3+0]; py[j] = X[p*3+1]; pz[j] = X[p*3+2];
        dd[j] = 1e10f;
    }
    __shared__ float rv[32];
    __shared__ int   ri[32];
    __shared__ int   s_far;
    int far = 0;
    for (int it = 0; it < GG; it++) {
        float cx = X[far*3+0], cy = X[far*3+1], cz = X[far*3+2];
        if (t == 0) {
            center[(b*GG+it)*3+0] = cx;
            center[(b*GG+it)*3+1] = cy;
            center[(b*GG+it)*3+2] = cz;
        }
        float bv = -1.f; int bi = 0;
#pragma unroll
        for (int j = 0; j < 8; j++) {
            float dx = px[j]-cx, dy = py[j]-cy, dz = pz[j]-cz;
            float d = dx*dx + dy*dy + dz*dz;
            if (d < dd[j]) dd[j] = d;
            if (dd[j] > bv) { bv = dd[j]; bi = t + j*1024; }
        }
#pragma unroll
        for (int off = 16; off > 0; off >>= 1) {
            float ov = __shfl_down_sync(0xffffffffu, bv, off);
            int   oi = __shfl_down_sync(0xffffffffu, bi, off);
            if (ov > bv || (ov == bv && oi < bi)) { bv = ov; bi = oi; }
        }
        if (lane == 0) { rv[warp] = bv; ri[warp] = bi; }
        __syncthreads();
        if (warp == 0) {
            bv = rv[lane]; bi = ri[lane];
#pragma unroll
            for (int off = 16; off > 0; off >>= 1) {
                float ov = __shfl_down_sync(0xffffffffu, bv, off);
                int   oi = __shfl_down_sync(0xffffffffu, bi, off);
                if (ov > bv || (ov == bv && oi < bi)) { bv = ov; bi = oi; }
            }
            if (lane == 0) s_far = bi;
        }
        __syncthreads();
        far = s_far;
    }
}

// --------------------------- greedy NN ordering ------------------------------
__global__ void order_kernel(const float* __restrict__ cen, float* __restrict__ cenO)
{
    int b = blockIdx.x;
    int t = threadIdx.x;                      // 128 threads = 4 warps
    int lane = t & 31, warp = t >> 5;
    __shared__ float cx[GG], cy[GG], cz[GG], nn[GG];
    __shared__ int visited[GG];
    __shared__ int s_last;
    __shared__ float rv[4];
    __shared__ int ri[4];
    cx[t] = cen[(b*GG+t)*3+0];
    cy[t] = cen[(b*GG+t)*3+1];
    cz[t] = cen[(b*GG+t)*3+2];
    nn[t] = cx[t]*cx[t] + cy[t]*cy[t] + cz[t]*cz[t];
    visited[t] = 0;
    if (t == 0) {
        visited[0] = 1; s_last = 0;
        cenO[(b*GG)*3+0] = cx[0]; cenO[(b*GG)*3+1] = cy[0]; cenO[(b*GG)*3+2] = cz[0];
    }
    __syncthreads();
    for (int step = 1; step < GG; step++) {
        int last = s_last;
        float d;
        if (visited[t]) d = 3.4e38f;
        else {
            float dot = cx[last]*cx[t] + cy[last]*cy[t] + cz[last]*cz[t];
            d = fmaxf(nn[last] + nn[t] - 2.f*dot, 0.f);
        }
        float bv = d; int bi = t;
#pragma unroll
        for (int off = 16; off > 0; off >>= 1) {
            float ov = __shfl_down_sync(0xffffffffu, bv, off);
            int   oi = __shfl_down_sync(0xffffffffu, bi, off);
            if (ov < bv || (ov == bv && oi < bi)) { bv = ov; bi = oi; }
        }
        if (lane == 0) { rv[warp] = bv; ri[warp] = bi; }
        __syncthreads();
        if (t == 0) {
            float mv = rv[0]; int mi = ri[0];
#pragma unroll
            for (int j = 1; j < 4; j++)
                if (rv[j] < mv || (rv[j] == mv && ri[j] < mi)) { mv = rv[j]; mi = ri[j]; }
            visited[mi] = 1; s_last = mi;
            cenO[(b*GG+step)*3+0] = cx[mi];
            cenO[(b*GG+step)*3+1] = cy[mi];
            cenO[(b*GG+step)*3+2] = cz[mi];
        }
        __syncthreads();
    }
}

// ------------------------------- kNN + gather --------------------------------
__global__ void knn_kernel(const float* __restrict__ xyz, const float* __restrict__ cenO,
                           float* __restrict__ neigh)
{
    int bg = blockIdx.x;
    int b  = bg >> 7;
    int t  = threadIdx.x;                     // 256 threads = 8 warps
    int lane = t & 31, warp = t >> 5;
    const float* X = xyz + (size_t)b * NP * 3;
    float cx = cenO[bg*3+0], cy = cenO[bg*3+1], cz = cenO[bg*3+2];
    __shared__ float sd[NP];
    __shared__ float rv[8];
    __shared__ int ri[8];
#pragma unroll
    for (int j = 0; j < NP/256; j++) {
        int p = t + j*256;
        float dx = X[p*3+0]-cx, dy = X[p*3+1]-cy, dz = X[p*3+2]-cz;
        sd[p] = dx*dx + dy*dy + dz*dz;
    }
    __syncthreads();
    for (int k = 0; k < KNb; k++) {
        float bv = 3.4e38f; int bi = 0;
#pragma unroll
        for (int j = 0; j < NP/256; j++) {
            int p = t + j*256;
            float d = sd[p];
            if (d < bv) { bv = d; bi = p; }
        }
#pragma unroll
        for (int off = 16; off > 0; off >>= 1) {
            float ov = __shfl_down_sync(0xffffffffu, bv, off);
            int   oi = __shfl_down_sync(0xffffffffu, bi, off);
            if (ov < bv || (ov == bv && oi < bi)) { bv = ov; bi = oi; }
        }
        if (lane == 0) { rv[warp] = bv; ri[warp] = bi; }
        __syncthreads();
        if (t == 0) {
            float mv = rv[0]; int mi = ri[0];
#pragma unroll
            for (int j = 1; j < 8; j++)
                if (rv[j] < mv || (rv[j] == mv && ri[j] < mi)) { mv = rv[j]; mi = ri[j]; }
            neigh[((size_t)bg*KNb + k)*3+0] = X[mi*3+0]-cx;
            neigh[((size_t)bg*KNb + k)*3+1] = X[mi*3+1]-cy;
            neigh[((size_t)bg*KNb + k)*3+2] = X[mi*3+2]-cz;
            sd[mi] = 3.4e38f;
        }
        __syncthreads();
    }
}

// --------------------- small-K GEMM (only ec1, K=3) ---------------------------
template<int ACT, int RES, int BNA>
__global__ void __launch_bounds__(256) gemm_k(
    const float* __restrict__ A, int lda,
    const float* __restrict__ W, int ldw,
    const float* __restrict__ bias,
    const float* __restrict__ res,
    const float* __restrict__ bnscale, const float* __restrict__ bnshift,
    float* __restrict__ C, int M, int N, int K)
{
    __shared__ float As[16][64];
    __shared__ float Ws[16][64];
    int tid = threadIdx.x;
    int tx = tid & 15, ty = tid >> 4;
    int m0 = blockIdx.y * 64, n0 = blockIdx.x * 64;
    float acc[4][4] = {};
    for (int kk = 0; kk < K; kk += 16) {
#pragma unroll
        for (int i = 0; i < 4; i++) {
            int idx = tid + i*256;
            int k = idx & 15, m = idx >> 4;
            float a = 0.f, w = 0.f;
            if (kk + k < K) {
                a = A[(size_t)(m0+m)*lda + kk + k];
                if (BNA) a = fmaxf(fmaf(a, bnscale[kk+k], bnshift[kk+k]), 0.f);
                w = W[(size_t)(n0+m)*ldw + kk + k];
            }
            As[k][m] = a;
            Ws[k][m] = w;
        }
        __syncthreads();
#pragma unroll
        for (int k = 0; k < 16; k++) {
            float4 av = *(const float4*)&As[k][ty*4];
            float4 wv = *(const float4*)&Ws[k][tx*4];
            float ar[4] = {av.x, av.y, av.z, av.w};
            float wr[4] = {wv.x, wv.y, wv.z, wv.w};
#pragma unroll
            for (int i = 0; i < 4; i++)
#pragma unroll
                for (int j = 0; j < 4; j++)
                    acc[i][j] = fmaf(ar[i], wr[j], acc[i][j]);
        }
        __syncthreads();
    }
#pragma unroll
    for (int i = 0; i < 4; i++) {
        int m = m0 + ty*4 + i;
#pragma unroll
        for (int j = 0; j < 4; j++) {
            int n = n0 + tx*4 + j;
            float v = acc[i][j];
            if (bias) v += bias[n];
            C[(size_t)m*N + n] = v;
        }
    }
}

// ------------------- bf16 tensor-core GEMM (mma.sync m16n8k16) ---------------
// BM x 128 block tile, KT=32, 256 threads = 8 warps.
//   BM=128: warps 2x4, warp tile 64x32 (4x4 MMA tiles)
//   BM=64 : warps 1x8, warp tile 64x16 (4x2 MMA tiles)
// W is bf16 (preconverted), ldw in elements. A is fp32 (ABF=0, optional
// BN-scale fused) or bf16 (ABF=1). Output fp32 (OUTBF=0) or bf16 (OUTBF=1).
// smem rows padded to RS=40 bf16 (20-bank stride, conflict-free fragments).
// M%BM==0, N%128==0, K%32==0.
template<int BM, int ACT, int RES, int BNA, int ABF, int OUTBF>
__global__ void __launch_bounds__(256) gemm_bf(
    const void* __restrict__ Av, int lda,
    const __nv_bfloat16* __restrict__ W, int ldw,
    const float* __restrict__ bias,
    const float* __restrict__ res,
    const float* __restrict__ bnsc, const float* __restrict__ bnsh,
    void* __restrict__ Cv, int M, int N, int K)
{
    constexpr int KT = 32, RS = 40;
    constexpr int NT  = (BM == 128) ? 4 : 2;     // n-tiles per warp
    constexpr int NA8 = BM*KT/8/256;             // 16B chunks/thread (bf16 A)
    constexpr int NA4 = BM*KT/4/256;             // 4-float chunks/thread (fp32 A)
    __shared__ __align__(16) __nv_bfloat16 As[2][BM][RS];
    __shared__ __align__(16) __nv_bfloat16 Ws[2][128][RS];

    const float* Af = (const float*)Av;
    const __nv_bfloat16* Ab = (const __nv_bfloat16*)Av;
    float* Cf = (float*)Cv;
    __nv_bfloat16* Cb = (__nv_bfloat16*)Cv;

    int tid  = threadIdx.x;
    int m0 = blockIdx.y * BM, n0 = blockIdx.x * 128;
    int lane = tid & 31, warp = tid >> 5;
    int m0w = (BM == 128) ? (warp & 1)*64 : 0;
    int n0w = (BM == 128) ? (warp >> 1)*32 : warp*16;
    int g  = lane >> 2, tg = lane & 3;

    uint4 rw4[2];
    uint4 raB[NA8 > 0 ? NA8 : 1];
    uint2 raF[NA4];
    float acc[4][NT][4];
#pragma unroll
    for (int a = 0; a < 4; a++)
#pragma unroll
        for (int b = 0; b < NT; b++)
#pragma unroll
            for (int c = 0; c < 4; c++) acc[a][b][c] = 0.f;

    // ================= prefetch tile kk into registers =================
    auto prefetch = [&](int kk) {
        if (ABF) {
#pragma unroll
            for (int j = 0; j < NA8; j++) {
                int f = tid + j*256; int m = f >> 2, c = f & 3;
                raB[j] = *(const uint4*)&Ab[(size_t)(m0+m)*lda + kk + c*8];
            }
        } else {
#pragma unroll
            for (int j = 0; j < NA4; j++) {
                int f = tid + j*256; int m = f >> 3, c = f & 7;
                float4 v = *(const float4*)&Af[(size_t)(m0+m)*lda + kk + c*4];
                if (BNA) {
                    float4 s = *(const float4*)&bnsc[kk + c*4];
                    float4 h = *(const float4*)&bnsh[kk + c*4];
                    v.x = fmaxf(fmaf(v.x,s.x,h.x),0.f);
                    v.y = fmaxf(fmaf(v.y,s.y,h.y),0.f);
                    v.z = fmaxf(fmaf(v.z,s.z,h.z),0.f);
                    v.w = fmaxf(fmaf(v.w,s.w,h.w),0.f);
                }
                union { __nv_bfloat162 h2[2]; uint2 u; } cvu;
                cvu.h2[0] = __floats2bfloat162_rn(v.x, v.y);
                cvu.h2[1] = __floats2bfloat162_rn(v.z, v.w);
                raF[j] = cvu.u;
            }
        }
#pragma unroll
        for (int j = 0; j < 2; j++) {
            int f = tid + j*256; int m = f >> 2, c = f & 3;
            rw4[j] = *(const uint4*)&W[(size_t)(n0+m)*ldw + kk + c*8];
        }
    };
    auto store = [&](int nb) {
        if (ABF) {
#pragma unroll
            for (int j = 0; j < NA8; j++) {
                int f = tid + j*256; int m = f >> 2, c = f & 3;
                *(uint4*)&As[nb][m][c*8] = raB[j];
            }
        } else {
#pragma unroll
            for (int j = 0; j < NA4; j++) {
                int f = tid + j*256; int m = f >> 3, c = f & 7;
                *(uint2*)&As[nb][m][c*4] = raF[j];
            }
        }
#pragma unroll
        for (int j = 0; j < 2; j++) {
            int f = tid + j*256; int m = f >> 2, c = f & 3;
            *(uint4*)&Ws[nb][m][c*8] = rw4[j];
        }
    };

    prefetch(0);
    store(0);
    __syncthreads();

    int ntiles = K / KT;
    int buf = 0;
    for (int t = 0; t < ntiles; t++) {
        if (t + 1 < ntiles) prefetch((t+1)*KT);
        // ---- compute current KT=32 tile: 2 k16 substeps ----
#pragma unroll
        for (int ks = 0; ks < 2; ks++) {
            uint32_t af[4][4], bfr[NT][2];
            int kb = ks*16;
#pragma unroll
            for (int mt = 0; mt < 4; mt++) {
                int r = m0w + mt*16 + g;
                af[mt][0] = *(const uint32_t*)&As[buf][r  ][kb + 2*tg];
                af[mt][1] = *(const uint32_t*)&As[buf][r+8][kb + 2*tg];
                af[mt][2] = *(const uint32_t*)&As[buf][r  ][kb + 2*tg+8];
                af[mt][3] = *(const uint32_t*)&As[buf][r+8][kb + 2*tg+8];
            }
#pragma unroll
            for (int nt = 0; nt < NT; nt++) {
                int c = n0w + nt*8 + g;
                bfr[nt][0] = *(const uint32_t*)&Ws[buf][c][kb + 2*tg];
                bfr[nt][1] = *(const uint32_t*)&Ws[buf][c][kb + 2*tg+8];
            }
#pragma unroll
            for (int mt = 0; mt < 4; mt++)
#pragma unroll
                for (int nt = 0; nt < NT; nt++) {
                    asm volatile(
                        "mma.sync.aligned.m16n8k16.row.col.f32.bf16.bf16.f32 "
                        "{%0,%1,%2,%3}, {%4,%5,%6,%7}, {%8,%9}, {%0,%1,%2,%3};\n"
                        : "+f"(acc[mt][nt][0]), "+f"(acc[mt][nt][1]),
                          "+f"(acc[mt][nt][2]), "+f"(acc[mt][nt][3])
                        : "r"(af[mt][0]), "r"(af[mt][1]), "r"(af[mt][2]), "r"(af[mt][3]),
                          "r"(bfr[nt][0]), "r"(bfr[nt][1]));
                }
        }
        if (t + 1 < ntiles) {
            int nb = buf ^ 1;
            store(nb);
            __syncthreads();
            buf = nb;
        }
    }

    // ---- epilogue ----
#pragma unroll
    for (int mt = 0; mt < 4; mt++) {
#pragma unroll
        for (int nt = 0; nt < NT; nt++) {
            int c0 = n0 + n0w + nt*8 + 2*tg;
#pragma unroll
            for (int h = 0; h < 2; h++) {
                int r = m0 + m0w + mt*16 + g + h*8;
                float x0 = acc[mt][nt][h*2+0];
                float x1 = acc[mt][nt][h*2+1];
                if (bias) { x0 += bias[c0]; x1 += bias[c0+1]; }
                if (RES == 1) { x0 += res[(size_t)r*N + c0]; x1 += res[(size_t)r*N + c0+1]; }
                if (RES == 2) { x0 += res[(size_t)(r >> 5)*N + c0]; x1 += res[(size_t)(r >> 5)*N + c0+1]; }
                if (ACT == 1) { x0 = fmaxf(x0, 0.f); x1 = fmaxf(x1, 0.f); }
                if (ACT == 2) {
                    x0 = 0.5f*x0*(1.f + erff(x0*0.70710678118654752f));
                    x1 = 0.5f*x1*(1.f + erff(x1*0.70710678118654752f));
                }
                if (OUTBF) {
                    __nv_bfloat162 v2 = __floats2bfloat162_rn(x0, x1);
                    *(__nv_bfloat162*)&Cb[(size_t)r*N + c0] = v2;
                } else {
                    *(float2*)&Cf[(size_t)r*N + c0] = make_float2(x0, x1);
                }
            }
        }
    }
}

// --------------------------- BN column stats ---------------------------------
__global__ void colstats_kernel(const float* __restrict__ X, int M, int C,
                                float* __restrict__ psum, float* __restrict__ psq)
{
    int c = blockIdx.x * 32 + threadIdx.x;
    int ry = threadIdx.y;                     // 8
    float s = 0.f, s2 = 0.f;
    for (int r = blockIdx.y*8 + ry; r < M; r += gridDim.y*8) {
        float v = X[(size_t)r*C + c];
        s += v; s2 += v*v;
    }
    __shared__ float sh[8][32], sh2[8][32];
    sh[ry][threadIdx.x] = s; sh2[ry][threadIdx.x] = s2;
    __syncthreads();
    if (ry == 0) {
        for (int j = 1; j < 8; j++) { s += sh[j][threadIdx.x]; s2 += sh2[j][threadIdx.x]; }
        psum[blockIdx.y*C + c] = s;
        psq [blockIdx.y*C + c] = s2;
    }
}

__global__ void bnfin_kernel(const float* __restrict__ psum, const float* __restrict__ psq,
                             int C, float invM,
                             const float* __restrict__ g, const float* __restrict__ b,
                             float* __restrict__ scale, float* __restrict__ shift)
{
    int c = blockIdx.x * blockDim.x + threadIdx.x;
    if (c >= C) return;
    float s = 0.f, s2 = 0.f;
    for (int j = 0; j < 64; j++) { s += psum[j*C + c]; s2 += psq[j*C + c]; }
    float mean = s * invM;
    float var  = s2 * invM - mean*mean;
    float sc = g[c] * rsqrtf(var + EPSf);
    scale[c] = sc;
    shift[c] = b[c] - mean*sc;
}

// ------------------------------ max pools ------------------------------------
__global__ void gmax_kernel(const float* __restrict__ f2, float* __restrict__ gm)
{
    int g = blockIdx.x; int c = threadIdx.x;  // 256
    float m = -3.4e38f;
    for (int k = 0; k < KNb; k++) m = fmaxf(m, f2[((size_t)g*KNb + k)*256 + c]);
    gm[(size_t)g*256 + c] = m;
}

__global__ void tokmax_kernel(const float* __restrict__ s2, const float* __restrict__ sos,
                              float* __restrict__ h)
{
    int bg = blockIdx.x; int c = threadIdx.x; // 384
    int g = bg & (GG-1);
    float m = -3.4e38f;
    for (int k = 0; k < KNb; k++) m = fmaxf(m, s2[((size_t)bg*KNb + k)*CC + c]);
    if (g < GG-1) h[(size_t)(bg+1)*CC + c] = m;   // shift-right (sos at g=0)
    if (g == 0)   h[(size_t)bg*CC + c] = sos[c];
}

// --------------------------- positional embedding ----------------------------
__global__ void pos_kernel(const float* __restrict__ cenO, float* __restrict__ pos)
{
    int bg = blockIdx.x; int t = threadIdx.x; // 384
    int ch = t >> 7;
    int rem = t & 127;
    int i = rem >> 1, s = rem & 1;
    float coord = cenO[bg*3 + ch];
    float inv = expf(-(2.f * (float)i / 128.f) * logf(10000.f));
    float ang = coord * inv;
    pos[(size_t)bg*CC + t] = s ? cosf(ang) : sinf(ang);
}

// ------------------------------ LayerNorm (warp per row) ---------------------
// YBF=1: y written as bf16 (feeds GEMM); YBF=0: fp32 (final output)
template<int YBF>
__global__ void ln_kernel(const float* __restrict__ x, const float* __restrict__ pos,
                          float* __restrict__ xin, void* __restrict__ yv,
                          const float* __restrict__ gw, const float* __restrict__ bw)
{
    int lane = threadIdx.x & 31, warp = threadIdx.x >> 5;
    int r = blockIdx.x * 4 + warp;            // 128 threads = 4 rows
    const int NV = CC / 32;                   // 12
    float v[NV];
    float s = 0.f;
#pragma unroll
    for (int i = 0; i < NV; i++) {
        int c = lane + i*32;
        float vv = x[(size_t)r*CC + c];
        if (pos) vv += pos[(size_t)r*CC + c];
        if (xin) xin[(size_t)r*CC + c] = vv;
        v[i] = vv; s += vv;
    }
#pragma unroll
    for (int off = 16; off > 0; off >>= 1) s += __shfl_xor_sync(0xffffffffu, s, off);
    float mean = s / (float)CC;
    float d = 0.f;
#pragma unroll
    for (int i = 0; i < NV; i++) { float e = v[i]-mean; d += e*e; }
#pragma unroll
    for (int off = 16; off > 0; off >>= 1) d += __shfl_xor_sync(0xffffffffu, d, off);
    float rstd = rsqrtf(d / (float)CC + EPSf);
#pragma unroll
    for (int i = 0; i < NV; i++) {
        int c = lane + i*32;
        float o = (v[i]-mean)*rstd*gw[c] + bw[c];
        if (YBF) ((__nv_bfloat16*)yv)[(size_t)r*CC + c] = __float2bfloat16(o);
        else     ((float*)yv)[(size_t)r*CC + c] = o;
    }
}

// ------------------------------ attention ------------------------------------
__global__ void attn_kernel(const float* __restrict__ qkv, __nv_bfloat16* __restrict__ out)
{
    __shared__ float sK[128*64];    // 32 KB
    int h = blockIdx.x, b = blockIdx.y;
    int t = threadIdx.x;            // 128 = one query each
    const float* base = qkv + (size_t)b*GG*(3*CC) + h*64;
    const float* src = base + (size_t)t*(3*CC);
    float q[64];
#pragma unroll
    for (int d = 0; d < 64; d += 4) {
        float4 qv = *(const float4*)&src[d];
        q[d+0]=qv.x; q[d+1]=qv.y; q[d+2]=qv.z; q[d+3]=qv.w;
        float4 kv = *(const float4*)&src[CC + d];
        sK[t*64+d+0]=kv.x; sK[t*64+d+1]=kv.y; sK[t*64+d+2]=kv.z; sK[t*64+d+3]=kv.w;
    }
    __syncthreads();
    const float scale = 0.125f;
    float mx = -3.4e38f;
    for (int j = 0; j <= t; j++) {
        float s = 0.f;
#pragma unroll
        for (int d = 0; d < 64; d++) s = fmaf(q[d], sK[j*64+d], s);
        s *= scale;
        if (s > mx) mx = s;
    }
    float acc[64];
#pragma unroll
    for (int d = 0; d < 64; d++) acc[d] = 0.f;
    float sum = 0.f;
    for (int j = 0; j <= t; j++) {
        float s = 0.f;
#pragma unroll
        for (int d = 0; d < 64; d++) s = fmaf(q[d], sK[j*64+d], s);
        float e = expf(s*scale - mx);
        sum += e;
        const float* vrow = base + (size_t)j*(3*CC) + 2*CC;
#pragma unroll
        for (int d = 0; d < 64; d += 4) {
            float4 vv = *(const float4*)&vrow[d];
            acc[d+0] = fmaf(e, vv.x, acc[d+0]);
            acc[d+1] = fmaf(e, vv.y, acc[d+1]);
            acc[d+2] = fmaf(e, vv.z, acc[d+2]);
            acc[d+3] = fmaf(e, vv.w, acc[d+3]);
        }
    }
    float inv = 1.f / sum;
    __nv_bfloat16* dst = out + ((size_t)(b*GG + t))*CC + h*64;
#pragma unroll
    for (int d = 0; d < 64; d += 2) {
        __nv_bfloat162 v2 = __floats2bfloat162_rn(acc[d]*inv, acc[d+1]*inv);
        *(__nv_bfloat162*)&dst[d] = v2;
    }
}

// --------------------------------- launch ------------------------------------
static void* symv(const void* s) { void* p = nullptr; cudaGetSymbolAddress(&p, s); return p; }
static float* sym(const void* s) { return (float*)symv(s); }
static __nv_bfloat16* symb(const void* s) { return (__nv_bfloat16*)symv(s); }

extern "C" void kernel_launch(void* const* d_in, const int* in_sizes, int n_in,
                              void* d_out, int out_size)
{
    const float* xyz    = (const float*)d_in[0];
    const float* ec1_w  = (const float*)d_in[1];
    const float* ec1_b  = (const float*)d_in[2];
    const float* bn1_g  = (const float*)d_in[3];
    const float* bn1_b  = (const float*)d_in[4];
    const float* ec2_w  = (const float*)d_in[5];
    const float* ec2_b  = (const float*)d_in[6];
    const float* sc1_w  = (const float*)d_in[7];
    const float* sc1_b  = (const float*)d_in[8];
    const float* bn2_g  = (const float*)d_in[9];
    const float* bn2_b  = (const float*)d_in[10];
    const float* sc2_w  = (const float*)d_in[11];
    const float* sc2_b  = (const float*)d_in[12];
    const float* sos    = (const float*)d_in[13];
    const float* ln1_g  = (const float*)d_in[14];
    const float* ln1_b  = (const float*)d_in[15];
    const float* qkv_w  = (const float*)d_in[16];
    const float* qkv_b  = (const float*)d_in[17];
    const float* out_w  = (const float*)d_in[18];
    const float* out_b  = (const float*)d_in[19];
    const float* ln2_g  = (const float*)d_in[20];
    const float* ln2_b  = (const float*)d_in[21];
    const float* mlp1_w = (const float*)d_in[22];
    const float* mlp1_b = (const float*)d_in[23];
    const float* mlp2_w = (const float*)d_in[24];
    const float* mlp2_b = (const float*)d_in[25];
    const float* lnf_g  = (const float*)d_in[26];
    const float* lnf_b  = (const float*)d_in[27];

    float* p_center  = sym(g_center);
    float* p_centerO = sym(g_centerO);
    float* p_neigh   = sym(g_neigh);
    float* p_f1   = sym(g_f1);
    float* p_f2   = sym(g_f2);
    float* p_gmax = sym(g_gmax);
    float* p_t    = sym(g_t);
    float* p_s1   = sym(g_s1);
    float* p_s2   = sym(g_s2);
    float* p_psum = sym(g_psum);
    float* p_psq  = sym(g_psq);
    float* p_scale= sym(g_scale);
    float* p_shift= sym(g_shift);
    float* p_h    = sym(g_h);
    float* p_pos  = sym(g_pos);
    float* p_xin  = sym(g_xin);
    float* p_x1   = sym(g_x1);
    float* p_qkv  = sym(g_qkv);
    __nv_bfloat16* p_ybf   = symb(g_ybf);
    __nv_bfloat16* p_attnbf= symb(g_attnbf);
    __nv_bfloat16* p_mhbf  = symb(g_mhbf);
    __nv_bfloat16* p_wqkv  = symb(g_wqkv);
    __nv_bfloat16* p_wout  = symb(g_wout);
    __nv_bfloat16* p_wm1   = symb(g_wm1);
    __nv_bfloat16* p_wm2   = symb(g_wm2);
    __nv_bfloat16* p_wec2  = symb(g_wec2);
    __nv_bfloat16* p_wsc1  = symb(g_wsc1);
    __nv_bfloat16* p_wsc2  = symb(g_wsc2);

    // ---- weight preconversion (fp32 -> bf16) ----
    {
        struct { const float* s; __nv_bfloat16* d; size_t n; } cv[7] = {
            { qkv_w,  p_wqkv, (size_t)LL*3*CC*CC },
            { out_w,  p_wout, (size_t)LL*CC*CC },
            { mlp1_w, p_wm1,  (size_t)LL*HIDD*CC },
            { mlp2_w, p_wm2,  (size_t)LL*CC*HIDD },
            { ec2_w,  p_wec2, (size_t)256*128 },
            { sc1_w,  p_wsc1, (size_t)512*512 },
            { sc2_w,  p_wsc2, (size_t)384*512 },
        };
        for (int i = 0; i < 7; i++) {
            int n4 = (int)(cv[i].n / 4);
            cvt_kernel<<<(n4 + 255)/256, 256>>>(cv[i].s, cv[i].d, n4);
        }
    }

    // ---- grouping ----
    fps_kernel  <<<BB, 1024>>>(xyz, p_center);
    order_kernel<<<BB, GG  >>>(p_center, p_centerO);
    knn_kernel  <<<BG, 256 >>>(xyz, p_centerO, p_neigh);

    // ---- encoder ----
    gemm_k<0,0,0><<<dim3(128/64, MROWS/64), 256>>>(p_neigh, 3, ec1_w, 3, ec1_b,
                                                   nullptr, nullptr, nullptr,
                                                   p_f1, MROWS, 128, 3);
    colstats_kernel<<<dim3(128/32, 64), dim3(32,8)>>>(p_f1, MROWS, 128, p_psum, p_psq);
    bnfin_kernel<<<1, 128>>>(p_psum, p_psq, 128, 1.f/(float)MROWS, bn1_g, bn1_b, p_scale, p_shift);
    // ec2 (BN1+relu fused, fp32 A): (65536,128)->(65536,256)
    gemm_bf<128,0,0,1,0,0><<<dim3(256/128, MROWS/128), 256>>>(p_f1, 128, p_wec2, 128, ec2_b,
                                                              nullptr, p_scale, p_shift,
                                                              p_f2, MROWS, 256, 128);
    gmax_kernel<<<BG, 256>>>(p_f2, p_gmax);
    // t = gmax @ sc1_w[:, :256]^T + sc1_b   (fp32 A, BM=64 -> 128 CTAs)
    gemm_bf<64,0,0,0,0,0><<<dim3(512/128, BG/64), 256>>>(p_gmax, 256, p_wsc1, 512, sc1_b,
                                                         nullptr, nullptr, nullptr,
                                                         p_t, BG, 512, 256);
    // s1 = f2 @ sc1_w[:, 256:]^T + broadcast(t)
    gemm_bf<128,0,2,0,0,0><<<dim3(512/128, MROWS/128), 256>>>(p_f2, 256, p_wsc1 + 256, 512, nullptr,
                                                              p_t, nullptr, nullptr,
                                                              p_s1, MROWS, 512, 256);
    colstats_kernel<<<dim3(512/32, 64), dim3(32,8)>>>(p_s1, MROWS, 512, p_psum, p_psq);
    bnfin_kernel<<<4, 128>>>(p_psum, p_psq, 512, 1.f/(float)MROWS, bn2_g, bn2_b, p_scale, p_shift);
    // sc2 (BN2+relu fused, fp32 A): (65536,512)->(65536,384)
    gemm_bf<128,0,0,1,0,0><<<dim3(384/128, MROWS/128), 256>>>(p_s1, 512, p_wsc2, 512, sc2_b,
                                                              nullptr, p_scale, p_shift,
                                                              p_s2, MROWS, 384, 512);
    tokmax_kernel<<<BG, CC>>>(p_s2, sos, p_h);
    pos_kernel<<<BG, CC>>>(p_centerO, p_pos);

    // ---- GPT ----
    for (int l = 0; l < LL; l++) {
        const __nv_bfloat16* qw = p_wqkv + (size_t)l*3*CC*CC;
        const float* qb = qkv_b  + (size_t)l*3*CC;
        const __nv_bfloat16* ow = p_wout + (size_t)l*CC*CC;
        const float* ob = out_b  + (size_t)l*CC;
        const __nv_bfloat16* m1w= p_wm1 + (size_t)l*HIDD*CC;
        const float* m1b= mlp1_b + (size_t)l*HIDD;
        const __nv_bfloat16* m2w= p_wm2 + (size_t)l*CC*HIDD;
        const float* m2b= mlp2_b + (size_t)l*CC;

        // xin = h + pos ; y = LN1(xin)  (y in bf16)
        ln_kernel<1><<<BG/4, 128>>>(p_h, p_pos, p_xin, p_ybf, ln1_g + l*CC, ln1_b + l*CC);
        // qkv (bf16 A, fp32 out): (2048,384)->(2048,1152), 288 CTAs
        gemm_bf<64,0,0,0,1,0><<<dim3(3*CC/128, BG/64), 256>>>(p_ybf, CC, qw, CC, qb,
                                                              nullptr, nullptr, nullptr,
                                                              p_qkv, BG, 3*CC, CC);
        attn_kernel<<<dim3(HH, BB), 128>>>(p_qkv, p_attnbf);
        // x1 = xin + attn @ ow^T + ob  (bf16 A, fp32 out), 96 CTAs
        gemm_bf<64,0,1,0,1,0><<<dim3(CC/128, BG/64), 256>>>(p_attnbf, CC, ow, CC, ob,
                                                            p_xin, nullptr, nullptr,
                                                            p_x1, BG, CC, CC);
        // y = LN2(x1) (bf16)
        ln_kernel<1><<<BG/4, 128>>>(p_x1, nullptr, nullptr, p_ybf, ln2_g + l*CC, ln2_b + l*CC);
        // mh = gelu(y @ m1w^T + m1b)  (bf16 A, bf16 out), 384 CTAs
        gemm_bf<64,2,0,0,1,1><<<dim3(HIDD/128, BG/64), 256>>>(p_ybf, CC, m1w, CC, m1b,
                                                              nullptr, nullptr, nullptr,
                                                              p_mhbf, BG, HIDD, CC);
        // h = x1 + mh @ m2w^T + m2b  (bf16 A, fp32 out), 96 CTAs
        gemm_bf<64,0,1,0,1,0><<<dim3(CC/128, BG/64), 256>>>(p_mhbf, HIDD, m2w, HIDD, m2b,
                                                            p_x1, nullptr, nullptr,
                                                            p_h, BG, CC, HIDD);
    }

    // final LN -> output (fp32)
    ln_kernel<0><<<BG/4, 128>>>(p_h, nullptr, nullptr, (float*)d_out, lnf_g, lnf_b);
}

// round 11
// speedup vs baseline: 4.1539x; 1.1231x over previous
#include <cuda_runtime.h>
#include <cuda_bf16.h>
#include <math.h>
#include <stdint.h>

#define BB 16
#define NP 8192
#define GG 128
#define KNb 32
#define CC 384
#define HH 6
#define LL 12
#define HIDD 1536
#define BG (BB*GG)          /* 2048 */
#define MROWS (BG*KNb)      /* 65536 */
#define EPSf 1e-5f

// ------------------------- scratch (static device memory) -------------------
__device__ float g_center [BG*3];
__device__ float g_centerO[BG*3];
__device__ float g_neigh  [MROWS*3];
__device__ float g_f1 [(size_t)MROWS*128];
__device__ float g_f2 [(size_t)MROWS*256];
__device__ float g_gmax[(size_t)BG*256];
__device__ float g_t  [(size_t)BG*512];
__device__ float g_s1 [(size_t)MROWS*512];
__device__ float g_s2 [(size_t)MROWS*384];
__device__ float g_psum[64*512];
__device__ float g_psq [64*512];
__device__ float g_scale[512];
__device__ float g_shift[512];
__device__ float g_h   [BG*CC];
__device__ float g_pos [BG*CC];
__device__ float g_xin [BG*CC];
__device__ float g_x1  [BG*CC];
__device__ float g_qkv [BG*3*CC];
// bf16 activations (GEMM inputs only)
__device__ __nv_bfloat16 g_ybf  [BG*CC];
__device__ __nv_bfloat16 g_attnbf[BG*CC];
__device__ __nv_bfloat16 g_mhbf [BG*HIDD];
// bf16 pre-converted weights
__device__ __nv_bfloat16 g_wqkv[(size_t)LL*3*CC*CC];
__device__ __nv_bfloat16 g_wout[(size_t)LL*CC*CC];
__device__ __nv_bfloat16 g_wm1 [(size_t)LL*HIDD*CC];
__device__ __nv_bfloat16 g_wm2 [(size_t)LL*CC*HIDD];
__device__ __nv_bfloat16 g_wec2[256*128];
__device__ __nv_bfloat16 g_wsc1[512*512];
__device__ __nv_bfloat16 g_wsc2[384*512];

// ------------------------ fp32 -> bf16 conversion ----------------------------
__global__ void cvt_kernel(const float* __restrict__ src, __nv_bfloat16* __restrict__ dst, int n4)
{
    int i = blockIdx.x * blockDim.x + threadIdx.x;
    if (i >= n4) return;
    float4 v = *(const float4*)&src[i*4];
    union { __nv_bfloat162 h2[2]; uint2 u; } c;
    c.h2[0] = __floats2bfloat162_rn(v.x, v.y);
    c.h2[1] = __floats2bfloat162_rn(v.z, v.w);
    *(uint2*)&dst[i*4] = c.u;
}

// ------------------------------- FPS ----------------------------------------
__global__ void fps_kernel(const float* __restrict__ xyz, float* __restrict__ center)
{
    int b = blockIdx.x;
    int t = threadIdx.x;                      // 1024 threads = 32 warps
    int lane = t & 31, warp = t >> 5;
    const float* X = xyz + (size_t)b * NP * 3;
    float px[8], py[8], pz[8], dd[8];
#pragma unroll
    for (int j = 0; j < 8; j++) {
        int p = t + j * 1024;
        px[j] = X[p*3+0]; py[j] = X[p*3+1]; pz[j] = X[p*3+2];
        dd[j] = 1e10f;
    }
    __shared__ float rv[32];
    __shared__ int   ri[32];
    __shared__ int   s_far;
    int far = 0;
    for (int it = 0; it < GG; it++) {
        float cx = X[far*3+0], cy = X[far*3+1], cz = X[far*3+2];
        if (t == 0) {
            center[(b*GG+it)*3+0] = cx;
            center[(b*GG+it)*3+1] = cy;
            center[(b*GG+it)*3+2] = cz;
        }
        float bv = -1.f; int bi = 0;
#pragma unroll
        for (int j = 0; j < 8; j++) {
            float dx = px[j]-cx, dy = py[j]-cy, dz = pz[j]-cz;
            float d = dx*dx + dy*dy + dz*dz;
            if (d < dd[j]) dd[j] = d;
            if (dd[j] > bv) { bv = dd[j]; bi = t + j*1024; }
        }
#pragma unroll
        for (int off = 16; off > 0; off >>= 1) {
            float ov = __shfl_down_sync(0xffffffffu, bv, off);
            int   oi = __shfl_down_sync(0xffffffffu, bi, off);
            if (ov > bv || (ov == bv && oi < bi)) { bv = ov; bi = oi; }
        }
        if (lane == 0) { rv[warp] = bv; ri[warp] = bi; }
        __syncthreads();
        if (warp == 0) {
            bv = rv[lane]; bi = ri[lane];
#pragma unroll
            for (int off = 16; off > 0; off >>= 1) {
                float ov = __shfl_down_sync(0xffffffffu, bv, off);
                int   oi = __shfl_down_sync(0xffffffffu, bi, off);
                if (ov > bv || (ov == bv && oi < bi)) { bv = ov; bi = oi; }
            }
            if (lane == 0) s_far = bi;
        }
        __syncthreads();
        far = s_far;
    }
}

// --------------------------- greedy NN ordering ------------------------------
__global__ void order_kernel(const float* __restrict__ cen, float* __restrict__ cenO)
{
    int b = blockIdx.x;
    int t = threadIdx.x;                      // 128 threads = 4 warps
    int lane = t & 31, warp = t >> 5;
    __shared__ float cx[GG], cy[GG], cz[GG], nn[GG];
    __shared__ int visited[GG];
    __shared__ int s_last;
    __shared__ float rv[4];
    __shared__ int ri[4];
    cx[t] = cen[(b*GG+t)*3+0];
    cy[t] = cen[(b*GG+t)*3+1];
    cz[t] = cen[(b*GG+t)*3+2];
    nn[t] = cx[t]*cx[t] + cy[t]*cy[t] + cz[t]*cz[t];
    visited[t] = 0;
    if (t == 0) {
        visited[0] = 1; s_last = 0;
        cenO[(b*GG)*3+0] = cx[0]; cenO[(b*GG)*3+1] = cy[0]; cenO[(b*GG)*3+2] = cz[0];
    }
    __syncthreads();
    for (int step = 1; step < GG; step++) {
        int last = s_last;
        float d;
        if (visited[t]) d = 3.4e38f;
        else {
            float dot = cx[last]*cx[t] + cy[last]*cy[t] + cz[last]*cz[t];
            d = fmaxf(nn[last] + nn[t] - 2.f*dot, 0.f);
        }
        float bv = d; int bi = t;
#pragma unroll
        for (int off = 16; off > 0; off >>= 1) {
            float ov = __shfl_down_sync(0xffffffffu, bv, off);
            int   oi = __shfl_down_sync(0xffffffffu, bi, off);
            if (ov < bv || (ov == bv && oi < bi)) { bv = ov; bi = oi; }
        }
        if (lane == 0) { rv[warp] = bv; ri[warp] = bi; }
        __syncthreads();
        if (t == 0) {
            float mv = rv[0]; int mi = ri[0];
#pragma unroll
            for (int j = 1; j < 4; j++)
                if (rv[j] < mv || (rv[j] == mv && ri[j] < mi)) { mv = rv[j]; mi = ri[j]; }
            visited[mi] = 1; s_last = mi;
            cenO[(b*GG+step)*3+0] = cx[mi];
            cenO[(b*GG+step)*3+1] = cy[mi];
            cenO[(b*GG+step)*3+2] = cz[mi];
        }
        __syncthreads();
    }
}

// ------------------------------- kNN + gather --------------------------------
__global__ void knn_kernel(const float* __restrict__ xyz, const float* __restrict__ cenO,
                           float* __restrict__ neigh)
{
    int bg = blockIdx.x;
    int b  = bg >> 7;
    int t  = threadIdx.x;                     // 256 threads = 8 warps
    int lane = t & 31, warp = t >> 5;
    const float* X = xyz + (size_t)b * NP * 3;
    float cx = cenO[bg*3+0], cy = cenO[bg*3+1], cz = cenO[bg*3+2];
    __shared__ float sd[NP];
    __shared__ float rv[8];
    __shared__ int ri[8];
#pragma unroll
    for (int j = 0; j < NP/256; j++) {
        int p = t + j*256;
        float dx = X[p*3+0]-cx, dy = X[p*3+1]-cy, dz = X[p*3+2]-cz;
        sd[p] = dx*dx + dy*dy + dz*dz;
    }
    __syncthreads();
    for (int k = 0; k < KNb; k++) {
        float bv = 3.4e38f; int bi = 0;
#pragma unroll
        for (int j = 0; j < NP/256; j++) {
            int p = t + j*256;
            float d = sd[p];
            if (d < bv) { bv = d; bi = p; }
        }
#pragma unroll
        for (int off = 16; off > 0; off >>= 1) {
            float ov = __shfl_down_sync(0xffffffffu, bv, off);
            int   oi = __shfl_down_sync(0xffffffffu, bi, off);
            if (ov < bv || (ov == bv && oi < bi)) { bv = ov; bi = oi; }
        }
        if (lane == 0) { rv[warp] = bv; ri[warp] = bi; }
        __syncthreads();
        if (t == 0) {
            float mv = rv[0]; int mi = ri[0];
#pragma unroll
            for (int j = 1; j < 8; j++)
                if (rv[j] < mv || (rv[j] == mv && ri[j] < mi)) { mv = rv[j]; mi = ri[j]; }
            neigh[((size_t)bg*KNb + k)*3+0] = X[mi*3+0]-cx;
            neigh[((size_t)bg*KNb + k)*3+1] = X[mi*3+1]-cy;
            neigh[((size_t)bg*KNb + k)*3+2] = X[mi*3+2]-cz;
            sd[mi] = 3.4e38f;
        }
        __syncthreads();
    }
}

// --------------------- small-K GEMM (only ec1, K=3) ---------------------------
template<int ACT, int RES, int BNA>
__global__ void __launch_bounds__(256) gemm_k(
    const float* __restrict__ A, int lda,
    const float* __restrict__ W, int ldw,
    const float* __restrict__ bias,
    const float* __restrict__ res,
    const float* __restrict__ bnscale, const float* __restrict__ bnshift,
    float* __restrict__ C, int M, int N, int K)
{
    __shared__ float As[16][64];
    __shared__ float Ws[16][64];
    int tid = threadIdx.x;
    int tx = tid & 15, ty = tid >> 4;
    int m0 = blockIdx.y * 64, n0 = blockIdx.x * 64;
    float acc[4][4] = {};
    for (int kk = 0; kk < K; kk += 16) {
#pragma unroll
        for (int i = 0; i < 4; i++) {
            int idx = tid + i*256;
            int k = idx & 15, m = idx >> 4;
            float a = 0.f, w = 0.f;
            if (kk + k < K) {
                a = A[(size_t)(m0+m)*lda + kk + k];
                if (BNA) a = fmaxf(fmaf(a, bnscale[kk+k], bnshift[kk+k]), 0.f);
                w = W[(size_t)(n0+m)*ldw + kk + k];
            }
            As[k][m] = a;
            Ws[k][m] = w;
        }
        __syncthreads();
#pragma unroll
        for (int k = 0; k < 16; k++) {
            float4 av = *(const float4*)&As[k][ty*4];
            float4 wv = *(const float4*)&Ws[k][tx*4];
            float ar[4] = {av.x, av.y, av.z, av.w};
            float wr[4] = {wv.x, wv.y, wv.z, wv.w};
#pragma unroll
            for (int i = 0; i < 4; i++)
#pragma unroll
                for (int j = 0; j < 4; j++)
                    acc[i][j] = fmaf(ar[i], wr[j], acc[i][j]);
        }
        __syncthreads();
    }
#pragma unroll
    for (int i = 0; i < 4; i++) {
        int m = m0 + ty*4 + i;
#pragma unroll
        for (int j = 0; j < 4; j++) {
            int n = n0 + tx*4 + j;
            float v = acc[i][j];
            if (bias) v += bias[n];
            C[(size_t)m*N + n] = v;
        }
    }
}

// ----------------------------- ldmatrix helper -------------------------------
__device__ __forceinline__ void ldm_x4(uint32_t (&r)[4], const void* p)
{
    uint32_t a = (uint32_t)__cvta_generic_to_shared(p);
    asm volatile("ldmatrix.sync.aligned.m8n8.x4.shared.b16 {%0,%1,%2,%3}, [%4];\n"
        : "=r"(r[0]), "=r"(r[1]), "=r"(r[2]), "=r"(r[3]) : "r"(a));
}

// ------------------- bf16 tensor-core GEMM (mma.sync m16n8k16) ---------------
// BM x 128 block tile, KT=32, 256 threads = 8 warps.
//   BM=128: warps 2x4, warp tile 64x32 (4x4 MMA tiles)
//   BM=64 : warps 1x8, warp tile 64x16 (4x2 MMA tiles)
// Fragments loaded via ldmatrix.x4 (A: rows lane&15, kcol (lane>>4)*8).
// smem rows padded to RS=40 bf16 (20-bank stride, conflict-free).
template<int BM, int ACT, int RES, int BNA, int ABF, int OUTBF>
__global__ void __launch_bounds__(256) gemm_bf(
    const void* __restrict__ Av, int lda,
    const __nv_bfloat16* __restrict__ W, int ldw,
    const float* __restrict__ bias,
    const float* __restrict__ res,
    const float* __restrict__ bnsc, const float* __restrict__ bnsh,
    void* __restrict__ Cv, int M, int N, int K)
{
    constexpr int KT = 32, RS = 40;
    constexpr int NT  = (BM == 128) ? 4 : 2;     // n-tiles per warp
    constexpr int NA8 = BM*KT/8/256;             // 16B chunks/thread (bf16 A)
    constexpr int NA4 = BM*KT/4/256;             // 4-float chunks/thread (fp32 A)
    __shared__ __align__(16) __nv_bfloat16 As[2][BM][RS];
    __shared__ __align__(16) __nv_bfloat16 Ws[2][128][RS];

    const float* Af = (const float*)Av;
    const __nv_bfloat16* Ab = (const __nv_bfloat16*)Av;
    float* Cf = (float*)Cv;
    __nv_bfloat16* Cb = (__nv_bfloat16*)Cv;

    int tid  = threadIdx.x;
    int m0 = blockIdx.y * BM, n0 = blockIdx.x * 128;
    int lane = tid & 31, warp = tid >> 5;
    int m0w = (BM == 128) ? (warp & 1)*64 : 0;
    int n0w = (BM == 128) ? (warp >> 1)*32 : warp*16;
    int g  = lane >> 2, tg = lane & 3;
    int laneR  = lane & 15;                   // ldmatrix row within 16-row tile
    int laneK8 = ((lane >> 4) & 1) << 3;      // ldmatrix k-col offset (0 or 8)

    uint4 rw4[2];
    uint4 raB[NA8 > 0 ? NA8 : 1];
    uint2 raF[NA4];
    float acc[4][NT][4];
#pragma unroll
    for (int a = 0; a < 4; a++)
#pragma unroll
        for (int b = 0; b < NT; b++)
#pragma unroll
            for (int c = 0; c < 4; c++) acc[a][b][c] = 0.f;

    auto prefetch = [&](int kk) {
        if (ABF) {
#pragma unroll
            for (int j = 0; j < NA8; j++) {
                int f = tid + j*256; int m = f >> 2, c = f & 3;
                raB[j] = *(const uint4*)&Ab[(size_t)(m0+m)*lda + kk + c*8];
            }
        } else {
#pragma unroll
            for (int j = 0; j < NA4; j++) {
                int f = tid + j*256; int m = f >> 3, c = f & 7;
                float4 v = *(const float4*)&Af[(size_t)(m0+m)*lda + kk + c*4];
                if (BNA) {
                    float4 s = *(const float4*)&bnsc[kk + c*4];
                    float4 h = *(const float4*)&bnsh[kk + c*4];
                    v.x = fmaxf(fmaf(v.x,s.x,h.x),0.f);
                    v.y = fmaxf(fmaf(v.y,s.y,h.y),0.f);
                    v.z = fmaxf(fmaf(v.z,s.z,h.z),0.f);
                    v.w = fmaxf(fmaf(v.w,s.w,h.w),0.f);
                }
                union { __nv_bfloat162 h2[2]; uint2 u; } cvu;
                cvu.h2[0] = __floats2bfloat162_rn(v.x, v.y);
                cvu.h2[1] = __floats2bfloat162_rn(v.z, v.w);
                raF[j] = cvu.u;
            }
        }
#pragma unroll
        for (int j = 0; j < 2; j++) {
            int f = tid + j*256; int m = f >> 2, c = f & 3;
            rw4[j] = *(const uint4*)&W[(size_t)(n0+m)*ldw + kk + c*8];
        }
    };
    auto store = [&](int nb) {
        if (ABF) {
#pragma unroll
            for (int j = 0; j < NA8; j++) {
                int f = tid + j*256; int m = f >> 2, c = f & 3;
                *(uint4*)&As[nb][m][c*8] = raB[j];
            }
        } else {
#pragma unroll
            for (int j = 0; j < NA4; j++) {
                int f = tid + j*256; int m = f >> 3, c = f & 7;
                *(uint2*)&As[nb][m][c*4] = raF[j];
            }
        }
#pragma unroll
        for (int j = 0; j < 2; j++) {
            int f = tid + j*256; int m = f >> 2, c = f & 3;
            *(uint4*)&Ws[nb][m][c*8] = rw4[j];
        }
    };

    prefetch(0);
    store(0);
    __syncthreads();

    int ntiles = K / KT;
    int buf = 0;
    for (int t = 0; t < ntiles; t++) {
        if (t + 1 < ntiles) prefetch((t+1)*KT);
        // ---- compute current KT=32 tile: 2 k16 substeps ----
#pragma unroll
        for (int ks = 0; ks < 2; ks++) {
            int kb = ks*16;
            uint32_t af[4][4], bfr[NT][2];
#pragma unroll
            for (int mt = 0; mt < 4; mt++)
                ldm_x4(af[mt], &As[buf][m0w + mt*16 + laneR][kb + laneK8]);
            if (NT == 2) {
                uint32_t tmp[4];
                ldm_x4(tmp, &Ws[buf][n0w + laneR][kb + laneK8]);
                bfr[0][0] = tmp[0]; bfr[1][0] = tmp[1];
                bfr[0][1] = tmp[2]; bfr[1][1] = tmp[3];
            } else {
#pragma unroll
                for (int np = 0; np < 2; np++) {
                    uint32_t tmp[4];
                    ldm_x4(tmp, &Ws[buf][n0w + np*16 + laneR][kb + laneK8]);
                    bfr[np*2+0][0] = tmp[0]; bfr[np*2+1][0] = tmp[1];
                    bfr[np*2+0][1] = tmp[2]; bfr[np*2+1][1] = tmp[3];
                }
            }
#pragma unroll
            for (int mt = 0; mt < 4; mt++)
#pragma unroll
                for (int nt = 0; nt < NT; nt++) {
                    asm volatile(
                        "mma.sync.aligned.m16n8k16.row.col.f32.bf16.bf16.f32 "
                        "{%0,%1,%2,%3}, {%4,%5,%6,%7}, {%8,%9}, {%0,%1,%2,%3};\n"
                        : "+f"(acc[mt][nt][0]), "+f"(acc[mt][nt][1]),
                          "+f"(acc[mt][nt][2]), "+f"(acc[mt][nt][3])
                        : "r"(af[mt][0]), "r"(af[mt][1]), "r"(af[mt][2]), "r"(af[mt][3]),
                          "r"(bfr[nt][0]), "r"(bfr[nt][1]));
                }
        }
        if (t + 1 < ntiles) {
            int nb = buf ^ 1;
            store(nb);
            __syncthreads();
            buf = nb;
        }
    }

    // ---- epilogue ----
#pragma unroll
    for (int mt = 0; mt < 4; mt++) {
#pragma unroll
        for (int nt = 0; nt < NT; nt++) {
            int c0 = n0 + n0w + nt*8 + 2*tg;
#pragma unroll
            for (int h = 0; h < 2; h++) {
                int r = m0 + m0w + mt*16 + g + h*8;
                float x0 = acc[mt][nt][h*2+0];
                float x1 = acc[mt][nt][h*2+1];
                if (bias) { x0 += bias[c0]; x1 += bias[c0+1]; }
                if (RES == 1) { x0 += res[(size_t)r*N + c0]; x1 += res[(size_t)r*N + c0+1]; }
                if (RES == 2) { x0 += res[(size_t)(r >> 5)*N + c0]; x1 += res[(size_t)(r >> 5)*N + c0+1]; }
                if (ACT == 1) { x0 = fmaxf(x0, 0.f); x1 = fmaxf(x1, 0.f); }
                if (ACT == 2) {
                    x0 = 0.5f*x0*(1.f + erff(x0*0.70710678118654752f));
                    x1 = 0.5f*x1*(1.f + erff(x1*0.70710678118654752f));
                }
                if (OUTBF) {
                    __nv_bfloat162 v2 = __floats2bfloat162_rn(x0, x1);
                    *(__nv_bfloat162*)&Cb[(size_t)r*N + c0] = v2;
                } else {
                    *(float2*)&Cf[(size_t)r*N + c0] = make_float2(x0, x1);
                }
            }
        }
    }
}

// --------------------------- BN column stats ---------------------------------
__global__ void colstats_kernel(const float* __restrict__ X, int M, int C,
                                float* __restrict__ psum, float* __restrict__ psq)
{
    int c = blockIdx.x * 32 + threadIdx.x;
    int ry = threadIdx.y;                     // 8
    float s = 0.f, s2 = 0.f;
    for (int r = blockIdx.y*8 + ry; r < M; r += gridDim.y*8) {
        float v = X[(size_t)r*C + c];
        s += v; s2 += v*v;
    }
    __shared__ float sh[8][32], sh2[8][32];
    sh[ry][threadIdx.x] = s; sh2[ry][threadIdx.x] = s2;
    __syncthreads();
    if (ry == 0) {
        for (int j = 1; j < 8; j++) { s += sh[j][threadIdx.x]; s2 += sh2[j][threadIdx.x]; }
        psum[blockIdx.y*C + c] = s;
        psq [blockIdx.y*C + c] = s2;
    }
}

__global__ void bnfin_kernel(const float* __restrict__ psum, const float* __restrict__ psq,
                             int C, float invM,
                             const float* __restrict__ g, const float* __restrict__ b,
                             float* __restrict__ scale, float* __restrict__ shift)
{
    int c = blockIdx.x * blockDim.x + threadIdx.x;
    if (c >= C) return;
    float s = 0.f, s2 = 0.f;
    for (int j = 0; j < 64; j++) { s += psum[j*C + c]; s2 += psq[j*C + c]; }
    float mean = s * invM;
    float var  = s2 * invM - mean*mean;
    float sc = g[c] * rsqrtf(var + EPSf);
    scale[c] = sc;
    shift[c] = b[c] - mean*sc;
}

// ------------------------------ max pools ------------------------------------
__global__ void gmax_kernel(const float* __restrict__ f2, float* __restrict__ gm)
{
    int g = blockIdx.x; int c = threadIdx.x;  // 256
    float m = -3.4e38f;
    for (int k = 0; k < KNb; k++) m = fmaxf(m, f2[((size_t)g*KNb + k)*256 + c]);
    gm[(size_t)g*256 + c] = m;
}

__global__ void tokmax_kernel(const float* __restrict__ s2, const float* __restrict__ sos,
                              float* __restrict__ h)
{
    int bg = blockIdx.x; int c = threadIdx.x; // 384
    int g = bg & (GG-1);
    float m = -3.4e38f;
    for (int k = 0; k < KNb; k++) m = fmaxf(m, s2[((size_t)bg*KNb + k)*CC + c]);
    if (g < GG-1) h[(size_t)(bg+1)*CC + c] = m;   // shift-right (sos at g=0)
    if (g == 0)   h[(size_t)bg*CC + c] = sos[c];
}

// --------------------------- positional embedding ----------------------------
__global__ void pos_kernel(const float* __restrict__ cenO, float* __restrict__ pos)
{
    int bg = blockIdx.x; int t = threadIdx.x; // 384
    int ch = t >> 7;
    int rem = t & 127;
    int i = rem >> 1, s = rem & 1;
    float coord = cenO[bg*3 + ch];
    float inv = expf(-(2.f * (float)i / 128.f) * logf(10000.f));
    float ang = coord * inv;
    pos[(size_t)bg*CC + t] = s ? cosf(ang) : sinf(ang);
}

// ------------------------------ LayerNorm (warp per row) ---------------------
template<int YBF>
__global__ void ln_kernel(const float* __restrict__ x, const float* __restrict__ pos,
                          float* __restrict__ xin, void* __restrict__ yv,
                          const float* __restrict__ gw, const float* __restrict__ bw)
{
    int lane = threadIdx.x & 31, warp = threadIdx.x >> 5;
    int r = blockIdx.x * 4 + warp;            // 128 threads = 4 rows
    const int NV = CC / 32;                   // 12
    float v[NV];
    float s = 0.f;
#pragma unroll
    for (int i = 0; i < NV; i++) {
        int c = lane + i*32;
        float vv = x[(size_t)r*CC + c];
        if (pos) vv += pos[(size_t)r*CC + c];
        if (xin) xin[(size_t)r*CC + c] = vv;
        v[i] = vv; s += vv;
    }
#pragma unroll
    for (int off = 16; off > 0; off >>= 1) s += __shfl_xor_sync(0xffffffffu, s, off);
    float mean = s / (float)CC;
    float d = 0.f;
#pragma unroll
    for (int i = 0; i < NV; i++) { float e = v[i]-mean; d += e*e; }
#pragma unroll
    for (int off = 16; off > 0; off >>= 1) d += __shfl_xor_sync(0xffffffffu, d, off);
    float rstd = rsqrtf(d / (float)CC + EPSf);
#pragma unroll
    for (int i = 0; i < NV; i++) {
        int c = lane + i*32;
        float o = (v[i]-mean)*rstd*gw[c] + bw[c];
        if (YBF) ((__nv_bfloat16*)yv)[(size_t)r*CC + c] = __float2bfloat16(o);
        else     ((float*)yv)[(size_t)r*CC + c] = o;
    }
}

// ------------------------------ attention ------------------------------------
// Block (h,b): 1024 threads = 128 queries x 8 lanes. K staged fp32 in smem,
// V streamed from global (L1 broadcast). Online softmax, single pass.
__global__ void __launch_bounds__(1024) attn_kernel(const float* __restrict__ qkv,
                                                    __nv_bfloat16* __restrict__ out)
{
    __shared__ float sK[128*64];    // 32 KB
    int h = blockIdx.x, b = blockIdx.y;
    int tid = threadIdx.x;
    int tq = tid >> 3, dsl = tid & 7;
    const float* base = qkv + (size_t)b*GG*(3*CC) + h*64;

    // stage K, load q slice
    {
        const float* krow = base + (size_t)tq*(3*CC) + CC + dsl*8;
        *(float4*)&sK[tq*64 + dsl*8]     = *(const float4*)&krow[0];
        *(float4*)&sK[tq*64 + dsl*8 + 4] = *(const float4*)&krow[4];
    }
    float q[8];
    {
        const float* qrow = base + (size_t)tq*(3*CC) + dsl*8;
        *(float4*)&q[0] = *(const float4*)&qrow[0];
        *(float4*)&q[4] = *(const float4*)&qrow[4];
    }
    __syncthreads();

    unsigned grpmask = 0xFFu << (((tid & 31) >> 3) << 3);
    const float scale = 0.125f;
    float mx = -3.4e38f, sum = 0.f;
    float acc[8];
#pragma unroll
    for (int d = 0; d < 8; d++) acc[d] = 0.f;

    for (int j = 0; j <= tq; j++) {
        const float* ks = &sK[j*64 + dsl*8];
        float s = 0.f;
#pragma unroll
        for (int d = 0; d < 8; d++) s = fmaf(q[d], ks[d], s);
        s += __shfl_xor_sync(grpmask, s, 1);
        s += __shfl_xor_sync(grpmask, s, 2);
        s += __shfl_xor_sync(grpmask, s, 4);
        s *= scale;
        const float* vrow = base + (size_t)j*(3*CC) + 2*CC + dsl*8;
        float4 v0 = *(const float4*)&vrow[0];
        float4 v1 = *(const float4*)&vrow[4];
        float v[8] = {v0.x, v0.y, v0.z, v0.w, v1.x, v1.y, v1.z, v1.w};
        if (s > mx) {
            float corr = __expf(mx - s);
            sum = fmaf(sum, corr, 1.f);
#pragma unroll
            for (int d = 0; d < 8; d++) acc[d] = fmaf(acc[d], corr, v[d]);
            mx = s;
        } else {
            float e = __expf(s - mx);
            sum += e;
#pragma unroll
            for (int d = 0; d < 8; d++) acc[d] = fmaf(e, v[d], acc[d]);
        }
    }
    float inv = 1.f / sum;
    __nv_bfloat16* dst = out + ((size_t)(b*GG + tq))*CC + h*64 + dsl*8;
#pragma unroll
    for (int d = 0; d < 8; d += 2) {
        __nv_bfloat162 v2 = __floats2bfloat162_rn(acc[d]*inv, acc[d+1]*inv);
        *(__nv_bfloat162*)&dst[d] = v2;
    }
}

// --------------------------------- launch ------------------------------------
static void* symv(const void* s) { void* p = nullptr; cudaGetSymbolAddress(&p, s); return p; }
static float* sym(const void* s) { return (float*)symv(s); }
static __nv_bfloat16* symb(const void* s) { return (__nv_bfloat16*)symv(s); }

extern "C" void kernel_launch(void* const* d_in, const int* in_sizes, int n_in,
                              void* d_out, int out_size)
{
    const float* xyz    = (const float*)d_in[0];
    const float* ec1_w  = (const float*)d_in[1];
    const float* ec1_b  = (const float*)d_in[2];
    const float* bn1_g  = (const float*)d_in[3];
    const float* bn1_b  = (const float*)d_in[4];
    const float* ec2_w  = (const float*)d_in[5];
    const float* ec2_b  = (const float*)d_in[6];
    const float* sc1_w  = (const float*)d_in[7];
    const float* sc1_b  = (const float*)d_in[8];
    const float* bn2_g  = (const float*)d_in[9];
    const float* bn2_b  = (const float*)d_in[10];
    const float* sc2_w  = (const float*)d_in[11];
    const float* sc2_b  = (const float*)d_in[12];
    const float* sos    = (const float*)d_in[13];
    const float* ln1_g  = (const float*)d_in[14];
    const float* ln1_b  = (const float*)d_in[15];
    const float* qkv_w  = (const float*)d_in[16];
    const float* qkv_b  = (const float*)d_in[17];
    const float* out_w  = (const float*)d_in[18];
    const float* out_b  = (const float*)d_in[19];
    const float* ln2_g  = (const float*)d_in[20];
    const float* ln2_b  = (const float*)d_in[21];
    const float* mlp1_w = (const float*)d_in[22];
    const float* mlp1_b = (const float*)d_in[23];
    const float* mlp2_w = (const float*)d_in[24];
    const float* mlp2_b = (const float*)d_in[25];
    const float* lnf_g  = (const float*)d_in[26];
    const float* lnf_b  = (const float*)d_in[27];

    float* p_center  = sym(g_center);
    float* p_centerO = sym(g_centerO);
    float* p_neigh   = sym(g_neigh);
    float* p_f1   = sym(g_f1);
    float* p_f2   = sym(g_f2);
    float* p_gmax = sym(g_gmax);
    float* p_t    = sym(g_t);
    float* p_s1   = sym(g_s1);
    float* p_s2   = sym(g_s2);
    float* p_psum = sym(g_psum);
    float* p_psq  = sym(g_psq);
    float* p_scale= sym(g_scale);
    float* p_shift= sym(g_shift);
    float* p_h    = sym(g_h);
    float* p_pos  = sym(g_pos);
    float* p_xin  = sym(g_xin);
    float* p_x1   = sym(g_x1);
    float* p_qkv  = sym(g_qkv);
    __nv_bfloat16* p_ybf   = symb(g_ybf);
    __nv_bfloat16* p_attnbf= symb(g_attnbf);
    __nv_bfloat16* p_mhbf  = symb(g_mhbf);
    __nv_bfloat16* p_wqkv  = symb(g_wqkv);
    __nv_bfloat16* p_wout  = symb(g_wout);
    __nv_bfloat16* p_wm1   = symb(g_wm1);
    __nv_bfloat16* p_wm2   = symb(g_wm2);
    __nv_bfloat16* p_wec2  = symb(g_wec2);
    __nv_bfloat16* p_wsc1  = symb(g_wsc1);
    __nv_bfloat16* p_wsc2  = symb(g_wsc2);

    // ---- weight preconversion (fp32 -> bf16) ----
    {
        struct { const float* s; __nv_bfloat16* d; size_t n; } cv[7] = {
            { qkv_w,  p_wqkv, (size_t)LL*3*CC*CC },
            { out_w,  p_wout, (size_t)LL*CC*CC },
            { mlp1_w, p_wm1,  (size_t)LL*HIDD*CC },
            { mlp2_w, p_wm2,  (size_t)LL*CC*HIDD },
            { ec2_w,  p_wec2, (size_t)256*128 },
            { sc1_w,  p_wsc1, (size_t)512*512 },
            { sc2_w,  p_wsc2, (size_t)384*512 },
        };
        for (int i = 0; i < 7; i++) {
            int n4 = (int)(cv[i].n / 4);
            cvt_kernel<<<(n4 + 255)/256, 256>>>(cv[i].s, cv[i].d, n4);
        }
    }

    // ---- grouping ----
    fps_kernel  <<<BB, 1024>>>(xyz, p_center);
    order_kernel<<<BB, GG  >>>(p_center, p_centerO);
    knn_kernel  <<<BG, 256 >>>(xyz, p_centerO, p_neigh);

    // ---- encoder ----
    gemm_k<0,0,0><<<dim3(128/64, MROWS/64), 256>>>(p_neigh, 3, ec1_w, 3, ec1_b,
                                                   nullptr, nullptr, nullptr,
                                                   p_f1, MROWS, 128, 3);
    colstats_kernel<<<dim3(128/32, 64), dim3(32,8)>>>(p_f1, MROWS, 128, p_psum, p_psq);
    bnfin_kernel<<<1, 128>>>(p_psum, p_psq, 128, 1.f/(float)MROWS, bn1_g, bn1_b, p_scale, p_shift);
    gemm_bf<128,0,0,1,0,0><<<dim3(256/128, MROWS/128), 256>>>(p_f1, 128, p_wec2, 128, ec2_b,
                                                              nullptr, p_scale, p_shift,
                                                              p_f2, MROWS, 256, 128);
    gmax_kernel<<<BG, 256>>>(p_f2, p_gmax);
    gemm_bf<64,0,0,0,0,0><<<dim3(512/128, BG/64), 256>>>(p_gmax, 256, p_wsc1, 512, sc1_b,
                                                         nullptr, nullptr, nullptr,
                                                         p_t, BG, 512, 256);
    gemm_bf<128,0,2,0,0,0><<<dim3(512/128, MROWS/128), 256>>>(p_f2, 256, p_wsc1 + 256, 512, nullptr,
                                                              p_t, nullptr, nullptr,
                                                              p_s1, MROWS, 512, 256);
    colstats_kernel<<<dim3(512/32, 64), dim3(32,8)>>>(p_s1, MROWS, 512, p_psum, p_psq);
    bnfin_kernel<<<4, 128>>>(p_psum, p_psq, 512, 1.f/(float)MROWS, bn2_g, bn2_b, p_scale, p_shift);
    gemm_bf<128,0,0,1,0,0><<<dim3(384/128, MROWS/128), 256>>>(p_s1, 512, p_wsc2, 512, sc2_b,
                                                              nullptr, p_scale, p_shift,
                                                              p_s2, MROWS, 384, 512);
    tokmax_kernel<<<BG, CC>>>(p_s2, sos, p_h);
    pos_kernel<<<BG, CC>>>(p_centerO, p_pos);

    // ---- GPT ----
    for (int l = 0; l < LL; l++) {
        const __nv_bfloat16* qw = p_wqkv + (size_t)l*3*CC*CC;
        const float* qb = qkv_b  + (size_t)l*3*CC;
        const __nv_bfloat16* ow = p_wout + (size_t)l*CC*CC;
        const float* ob = out_b  + (size_t)l*CC;
        const __nv_bfloat16* m1w= p_wm1 + (size_t)l*HIDD*CC;
        const float* m1b= mlp1_b + (size_t)l*HIDD;
        const __nv_bfloat16* m2w= p_wm2 + (size_t)l*CC*HIDD;
        const float* m2b= mlp2_b + (size_t)l*CC;

        ln_kernel<1><<<BG/4, 128>>>(p_h, p_pos, p_xin, p_ybf, ln1_g + l*CC, ln1_b + l*CC);
        gemm_bf<64,0,0,0,1,0><<<dim3(3*CC/128, BG/64), 256>>>(p_ybf, CC, qw, CC, qb,
                                                              nullptr, nullptr, nullptr,
                                                              p_qkv, BG, 3*CC, CC);
        attn_kernel<<<dim3(HH, BB), 1024>>>(p_qkv, p_attnbf);
        gemm_bf<64,0,1,0,1,0><<<dim3(CC/128, BG/64), 256>>>(p_attnbf, CC, ow, CC, ob,
                                                            p_xin, nullptr, nullptr,
                                                            p_x1, BG, CC, CC);
        ln_kernel<1><<<BG/4, 128>>>(p_x1, nullptr, nullptr, p_ybf, ln2_g + l*CC, ln2_b + l*CC);
        gemm_bf<64,2,0,0,1,1><<<dim3(HIDD/128, BG/64), 256>>>(p_ybf, CC, m1w, CC, m1b,
                                                              nullptr, nullptr, nullptr,
                                                              p_mhbf, BG, HIDD, CC);
        gemm_bf<64,0,1,0,1,0><<<dim3(CC/128, BG/64), 256>>>(p_mhbf, HIDD, m2w, HIDD, m2b,
                                                            p_x1, nullptr, nullptr,
                                                            p_h, BG, CC, HIDD);
    }

    // final LN -> output (fp32)
    ln_kernel<0><<<BG/4, 128>>>(p_h, nullptr, nullptr, (float*)d_out, lnf_g, lnf_b);
}

// round 13
// speedup vs baseline: 4.4585x; 1.0733x over previous
#include <cuda_runtime.h>
#include <cuda_bf16.h>
#include <math.h>
#include <stdint.h>

#define BB 16
#define NP 8192
#define GG 128
#define KNb 32
#define CC 384
#define HH 6
#define LL 12
#define HIDD 1536
#define BG (BB*GG)          /* 2048 */
#define MROWS (BG*KNb)      /* 65536 */
#define EPSf 1e-5f

// ------------------------- scratch (static device memory) -------------------
__device__ float g_center [BG*3];
__device__ float g_centerO[BG*3];
__device__ float g_neigh  [MROWS*3];
__device__ float g_f1 [(size_t)MROWS*128];
__device__ float g_t  [(size_t)BG*512];
__device__ float g_psum[64*512];
__device__ float g_psq [64*512];
__device__ float g_scale[512];
__device__ float g_shift[512];
__device__ float g_h   [BG*CC];
__device__ float g_pos [BG*CC];
__device__ float g_xin [BG*CC];
__device__ float g_x1  [BG*CC];
__device__ float g_qkv [BG*3*CC];
// bf16 encoder activations
__device__ __align__(16) __nv_bfloat16 g_f1b [(size_t)MROWS*128];
__device__ __align__(16) __nv_bfloat16 g_f2b [(size_t)MROWS*256];
__device__ __align__(16) __nv_bfloat16 g_gmaxb[(size_t)BG*256];
__device__ __align__(16) __nv_bfloat16 g_s1b [(size_t)MROWS*512];
__device__ __align__(16) __nv_bfloat16 g_s1c [(size_t)MROWS*512];
__device__ __align__(16) __nv_bfloat16 g_s2b [(size_t)MROWS*384];
// bf16 transformer activations
__device__ __align__(16) __nv_bfloat16 g_ybf  [BG*CC];
__device__ __align__(16) __nv_bfloat16 g_attnbf[BG*CC];
__device__ __align__(16) __nv_bfloat16 g_mhbf [BG*HIDD];
// bf16 pre-converted weights
__device__ __align__(16) __nv_bfloat16 g_wqkv[(size_t)LL*3*CC*CC];
__device__ __align__(16) __nv_bfloat16 g_wout[(size_t)LL*CC*CC];
__device__ __align__(16) __nv_bfloat16 g_wm1 [(size_t)LL*HIDD*CC];
__device__ __align__(16) __nv_bfloat16 g_wm2 [(size_t)LL*CC*HIDD];
__device__ __align__(16) __nv_bfloat16 g_wec2[256*128];
__device__ __align__(16) __nv_bfloat16 g_wsc1[512*512];
__device__ __align__(16) __nv_bfloat16 g_wsc2[384*512];

// ------------------------ fp32 -> bf16 conversion ----------------------------
__global__ void cvt_kernel(const float* __restrict__ src, __nv_bfloat16* __restrict__ dst, int n4)
{
    int i = blockIdx.x * blockDim.x + threadIdx.x;
    if (i >= n4) return;
    float4 v = *(const float4*)&src[i*4];
    union { __nv_bfloat162 h2[2]; uint2 u; } c;
    c.h2[0] = __floats2bfloat162_rn(v.x, v.y);
    c.h2[1] = __floats2bfloat162_rn(v.z, v.w);
    *(uint2*)&dst[i*4] = c.u;
}

// -------------------- BN apply + relu -> bf16 (fp32 / bf16 in) ---------------
__global__ void bnapply_f_kernel(const float* __restrict__ x,
                                 const float* __restrict__ sc, const float* __restrict__ sh,
                                 __nv_bfloat16* __restrict__ y, int n4, int cmask)
{
    int i = blockIdx.x * blockDim.x + threadIdx.x;
    if (i >= n4) return;
    float4 v = *(const float4*)&x[i*4];
    int c = (i*4) & cmask;
    float4 s = *(const float4*)&sc[c];
    float4 h = *(const float4*)&sh[c];
    v.x = fmaxf(fmaf(v.x,s.x,h.x),0.f);
    v.y = fmaxf(fmaf(v.y,s.y,h.y),0.f);
    v.z = fmaxf(fmaf(v.z,s.z,h.z),0.f);
    v.w = fmaxf(fmaf(v.w,s.w,h.w),0.f);
    union { __nv_bfloat162 h2[2]; uint2 u; } o;
    o.h2[0] = __floats2bfloat162_rn(v.x, v.y);
    o.h2[1] = __floats2bfloat162_rn(v.z, v.w);
    *(uint2*)&y[i*4] = o.u;
}

__global__ void bnapply_b_kernel(const __nv_bfloat16* __restrict__ x,
                                 const float* __restrict__ sc, const float* __restrict__ sh,
                                 __nv_bfloat16* __restrict__ y, int n4, int cmask)
{
    int i = blockIdx.x * blockDim.x + threadIdx.x;
    if (i >= n4) return;
    union { __nv_bfloat162 h2[2]; uint2 u; } in;
    in.u = *(const uint2*)&x[i*4];
    float4 v;
    v.x = __bfloat162float(in.h2[0].x); v.y = __bfloat162float(in.h2[0].y);
    v.z = __bfloat162float(in.h2[1].x); v.w = __bfloat162float(in.h2[1].y);
    int c = (i*4) & cmask;
    float4 s = *(const float4*)&sc[c];
    float4 h = *(const float4*)&sh[c];
    v.x = fmaxf(fmaf(v.x,s.x,h.x),0.f);
    v.y = fmaxf(fmaf(v.y,s.y,h.y),0.f);
    v.z = fmaxf(fmaf(v.z,s.z,h.z),0.f);
    v.w = fmaxf(fmaf(v.w,s.w,h.w),0.f);
    union { __nv_bfloat162 h2[2]; uint2 u; } o;
    o.h2[0] = __floats2bfloat162_rn(v.x, v.y);
    o.h2[1] = __floats2bfloat162_rn(v.z, v.w);
    *(uint2*)&y[i*4] = o.u;
}

// ------------------------------- FPS ----------------------------------------
__global__ void fps_kernel(const float* __restrict__ xyz, float* __restrict__ center)
{
    int b = blockIdx.x;
    int t = threadIdx.x;                      // 1024 threads = 32 warps
    int lane = t & 31, warp = t >> 5;
    const float* X = xyz + (size_t)b * NP * 3;
    float px[8], py[8], pz[8], dd[8];
#pragma unroll
    for (int j = 0; j < 8; j++) {
        int p = t + j * 1024;
        px[j] = X[p*3+0]; py[j] = X[p*3+1]; pz[j] = X[p*3+2];
        dd[j] = 1e10f;
    }
    __shared__ float rv[32];
    __shared__ int   ri[32];
    __shared__ int   s_far;
    int far = 0;
    for (int it = 0; it < GG; it++) {
        float cx = X[far*3+0], cy = X[far*3+1], cz = X[far*3+2];
        if (t == 0) {
            center[(b*GG+it)*3+0] = cx;
            center[(b*GG+it)*3+1] = cy;
            center[(b*GG+it)*3+2] = cz;
        }
        float bv = -1.f; int bi = 0;
#pragma unroll
        for (int j = 0; j < 8; j++) {
            float dx = px[j]-cx, dy = py[j]-cy, dz = pz[j]-cz;
            float d = dx*dx + dy*dy + dz*dz;
            if (d < dd[j]) dd[j] = d;
            if (dd[j] > bv) { bv = dd[j]; bi = t + j*1024; }
        }
#pragma unroll
        for (int off = 16; off > 0; off >>= 1) {
            float ov = __shfl_down_sync(0xffffffffu, bv, off);
            int   oi = __shfl_down_sync(0xffffffffu, bi, off);
            if (ov > bv || (ov == bv && oi < bi)) { bv = ov; bi = oi; }
        }
        if (lane == 0) { rv[warp] = bv; ri[warp] = bi; }
        __syncthreads();
        if (warp == 0) {
            bv = rv[lane]; bi = ri[lane];
#pragma unroll
            for (int off = 16; off > 0; off >>= 1) {
                float ov = __shfl_down_sync(0xffffffffu, bv, off);
                int   oi = __shfl_down_sync(0xffffffffu, bi, off);
                if (ov > bv || (ov == bv && oi < bi)) { bv = ov; bi = oi; }
            }
            if (lane == 0) s_far = bi;
        }
        __syncthreads();
        far = s_far;
    }
}

// --------------------------- greedy NN ordering ------------------------------
__global__ void order_kernel(const float* __restrict__ cen, float* __restrict__ cenO)
{
    int b = blockIdx.x;
    int t = threadIdx.x;                      // 128 threads = 4 warps
    int lane = t & 31, warp = t >> 5;
    __shared__ float cx[GG], cy[GG], cz[GG], nn[GG];
    __shared__ int visited[GG];
    __shared__ int s_last;
    __shared__ float rv[4];
    __shared__ int ri[4];
    cx[t] = cen[(b*GG+t)*3+0];
    cy[t] = cen[(b*GG+t)*3+1];
    cz[t] = cen[(b*GG+t)*3+2];
    nn[t] = cx[t]*cx[t] + cy[t]*cy[t] + cz[t]*cz[t];
    visited[t] = 0;
    if (t == 0) {
        visited[0] = 1; s_last = 0;
        cenO[(b*GG)*3+0] = cx[0]; cenO[(b*GG)*3+1] = cy[0]; cenO[(b*GG)*3+2] = cz[0];
    }
    __syncthreads();
    for (int step = 1; step < GG; step++) {
        int last = s_last;
        float d;
        if (visited[t]) d = 3.4e38f;
        else {
            float dot = cx[last]*cx[t] + cy[last]*cy[t] + cz[last]*cz[t];
            d = fmaxf(nn[last] + nn[t] - 2.f*dot, 0.f);
        }
        float bv = d; int bi = t;
#pragma unroll
        for (int off = 16; off > 0; off >>= 1) {
            float ov = __shfl_down_sync(0xffffffffu, bv, off);
            int   oi = __shfl_down_sync(0xffffffffu, bi, off);
            if (ov < bv || (ov == bv && oi < bi)) { bv = ov; bi = oi; }
        }
        if (lane == 0) { rv[warp] = bv; ri[warp] = bi; }
        __syncthreads();
        if (t == 0) {
            float mv = rv[0]; int mi = ri[0];
#pragma unroll
            for (int j = 1; j < 4; j++)
                if (rv[j] < mv || (rv[j] == mv && ri[j] < mi)) { mv = rv[j]; mi = ri[j]; }
            visited[mi] = 1; s_last = mi;
            cenO[(b*GG+step)*3+0] = cx[mi];
            cenO[(b*GG+step)*3+1] = cy[mi];
            cenO[(b*GG+step)*3+2] = cz[mi];
        }
        __syncthreads();
    }
}

// ------------------------------- kNN + gather --------------------------------
__global__ void knn_kernel(const float* __restrict__ xyz, const float* __restrict__ cenO,
                           float* __restrict__ neigh)
{
    int bg = blockIdx.x;
    int b  = bg >> 7;
    int t  = threadIdx.x;                     // 256 threads = 8 warps
    int lane = t & 31, warp = t >> 5;
    const float* X = xyz + (size_t)b * NP * 3;
    float cx = cenO[bg*3+0], cy = cenO[bg*3+1], cz = cenO[bg*3+2];
    __shared__ float sd[NP];
    __shared__ float rv[8];
    __shared__ int ri[8];
#pragma unroll
    for (int j = 0; j < NP/256; j++) {
        int p = t + j*256;
        float dx = X[p*3+0]-cx, dy = X[p*3+1]-cy, dz = X[p*3+2]-cz;
        sd[p] = dx*dx + dy*dy + dz*dz;
    }
    __syncthreads();
    for (int k = 0; k < KNb; k++) {
        float bv = 3.4e38f; int bi = 0;
#pragma unroll
        for (int j = 0; j < NP/256; j++) {
            int p = t + j*256;
            float d = sd[p];
            if (d < bv) { bv = d; bi = p; }
        }
#pragma unroll
        for (int off = 16; off > 0; off >>= 1) {
            float ov = __shfl_down_sync(0xffffffffu, bv, off);
            int   oi = __shfl_down_sync(0xffffffffu, bi, off);
            if (ov < bv || (ov == bv && oi < bi)) { bv = ov; bi = oi; }
        }
        if (lane == 0) { rv[warp] = bv; ri[warp] = bi; }
        __syncthreads();
        if (t == 0) {
            float mv = rv[0]; int mi = ri[0];
#pragma unroll
            for (int j = 1; j < 8; j++)
                if (rv[j] < mv || (rv[j] == mv && ri[j] < mi)) { mv = rv[j]; mi = ri[j]; }
            neigh[((size_t)bg*KNb + k)*3+0] = X[mi*3+0]-cx;
            neigh[((size_t)bg*KNb + k)*3+1] = X[mi*3+1]-cy;
            neigh[((size_t)bg*KNb + k)*3+2] = X[mi*3+2]-cz;
            sd[mi] = 3.4e38f;
        }
        __syncthreads();
    }
}

// --------------------- small-K GEMM (only ec1, K=3) ---------------------------
template<int ACT, int RES, int BNA>
__global__ void __launch_bounds__(256) gemm_k(
    const float* __restrict__ A, int lda,
    const float* __restrict__ W, int ldw,
    const float* __restrict__ bias,
    const float* __restrict__ res,
    const float* __restrict__ bnscale, const float* __restrict__ bnshift,
    float* __restrict__ C, int M, int N, int K)
{
    __shared__ float As[16][64];
    __shared__ float Ws[16][64];
    int tid = threadIdx.x;
    int tx = tid & 15, ty = tid >> 4;
    int m0 = blockIdx.y * 64, n0 = blockIdx.x * 64;
    float acc[4][4] = {};
    for (int kk = 0; kk < K; kk += 16) {
#pragma unroll
        for (int i = 0; i < 4; i++) {
            int idx = tid + i*256;
            int k = idx & 15, m = idx >> 4;
            float a = 0.f, w = 0.f;
            if (kk + k < K) {
                a = A[(size_t)(m0+m)*lda + kk + k];
                if (BNA) a = fmaxf(fmaf(a, bnscale[kk+k], bnshift[kk+k]), 0.f);
                w = W[(size_t)(n0+m)*ldw + kk + k];
            }
            As[k][m] = a;
            Ws[k][m] = w;
        }
        __syncthreads();
#pragma unroll
        for (int k = 0; k < 16; k++) {
            float4 av = *(const float4*)&As[k][ty*4];
            float4 wv = *(const float4*)&Ws[k][tx*4];
            float ar[4] = {av.x, av.y, av.z, av.w};
            float wr[4] = {wv.x, wv.y, wv.z, wv.w};
#pragma unroll
            for (int i = 0; i < 4; i++)
#pragma unroll
                for (int j = 0; j < 4; j++)
                    acc[i][j] = fmaf(ar[i], wr[j], acc[i][j]);
        }
        __syncthreads();
    }
#pragma unroll
    for (int i = 0; i < 4; i++) {
        int m = m0 + ty*4 + i;
#pragma unroll
        for (int j = 0; j < 4; j++) {
            int n = n0 + tx*4 + j;
            float v = acc[i][j];
            if (bias) v += bias[n];
            C[(size_t)m*N + n] = v;
        }
    }
}

// ----------------------------- asm helpers -----------------------------------
__device__ __forceinline__ void ldm_x4(uint32_t (&r)[4], const void* p)
{
    uint32_t a = (uint32_t)__cvta_generic_to_shared(p);
    asm volatile("ldmatrix.sync.aligned.m8n8.x4.shared.b16 {%0,%1,%2,%3}, [%4];\n"
        : "=r"(r[0]), "=r"(r[1]), "=r"(r[2]), "=r"(r[3]) : "r"(a));
}
__device__ __forceinline__ void cp16(void* dst, const void* src)
{
    uint32_t d = (uint32_t)__cvta_generic_to_shared(dst);
    asm volatile("cp.async.cg.shared.global [%0], [%1], 16;\n" :: "r"(d), "l"(src));
}
__device__ __forceinline__ void cp_commit() { asm volatile("cp.async.commit_group;\n"); }

// ------------------- bf16 tensor-core GEMM (cp.async 3-stage) ----------------
// 64 x 128 block tile, KT=32, 256 threads = 8 warps (1x8), warp tile 64x16.
// A,W bf16; fragments via ldmatrix.x4; rows padded to RS=40 (20-bank stride).
// Static smem: 3*(64+128)*40*2 = 46080 B (< 48KB).
// M%64==0, N%128==0, K%32==0, K/32 >= 2.
template<int ACT, int RES, int OUTBF>
__global__ void __launch_bounds__(256) gemm_bf(
    const __nv_bfloat16* __restrict__ A, int lda,
    const __nv_bfloat16* __restrict__ W, int ldw,
    const float* __restrict__ bias,
    const float* __restrict__ res,
    void* __restrict__ Cv, int M, int N, int K)
{
    constexpr int BM = 64, KT = 32, RS = 40, ST = 3, NT = 2;
    __shared__ __align__(16) __nv_bfloat16 As[ST][BM][RS];
    __shared__ __align__(16) __nv_bfloat16 Ws[ST][128][RS];

    float* Cf = (float*)Cv;
    __nv_bfloat16* Cb = (__nv_bfloat16*)Cv;

    int tid  = threadIdx.x;
    int m0 = blockIdx.y * BM, n0 = blockIdx.x * 128;
    int lane = tid & 31, warp = tid >> 5;
    int n0w = warp*16;
    int g  = lane >> 2, tg = lane & 3;
    int laneR  = lane & 15;
    int laneK8 = ((lane >> 4) & 1) << 3;

    float acc[4][NT][4];
#pragma unroll
    for (int a = 0; a < 4; a++)
#pragma unroll
        for (int b = 0; b < NT; b++)
#pragma unroll
            for (int c = 0; c < 4; c++) acc[a][b][c] = 0.f;

    auto load_stage = [&](int s, int kk) {
        {   // A: 64 rows x 32 cols bf16 = 256 chunks of 16B -> 1 per thread
            int m = tid >> 2, c = tid & 3;
            cp16(&As[s][m][c*8], &A[(size_t)(m0+m)*lda + kk + c*8]);
        }
#pragma unroll
        for (int j = 0; j < 2; j++) {   // W: 128 rows -> 512 chunks
            int f = tid + j*256; int m = f >> 2, c = f & 3;
            cp16(&Ws[s][m][c*8], &W[(size_t)(n0+m)*ldw + kk + c*8]);
        }
        cp_commit();
    };

    int ntiles = K / KT;
#pragma unroll
    for (int s = 0; s < ST-1; s++) {
        if (s < ntiles) load_stage(s, s*KT);
        else cp_commit();
    }

    for (int t = 0; t < ntiles; t++) {
        asm volatile("cp.async.wait_group %0;\n" :: "n"(ST-2));
        __syncthreads();
        int nl = t + ST - 1;
        if (nl < ntiles) load_stage(nl % ST, nl*KT);
        else cp_commit();
        int buf = t % ST;
#pragma unroll
        for (int ks = 0; ks < 2; ks++) {
            int kb = ks*16;
            uint32_t af[4][4], bfr[NT][2];
#pragma unroll
            for (int mt = 0; mt < 4; mt++)
                ldm_x4(af[mt], &As[buf][mt*16 + laneR][kb + laneK8]);
            {
                uint32_t tmp[4];
                ldm_x4(tmp, &Ws[buf][n0w + laneR][kb + laneK8]);
                bfr[0][0] = tmp[0]; bfr[1][0] = tmp[1];
                bfr[0][1] = tmp[2]; bfr[1][1] = tmp[3];
            }
#pragma unroll
            for (int mt = 0; mt < 4; mt++)
#pragma unroll
                for (int nt = 0; nt < NT; nt++) {
                    asm volatile(
                        "mma.sync.aligned.m16n8k16.row.col.f32.bf16.bf16.f32 "
                        "{%0,%1,%2,%3}, {%4,%5,%6,%7}, {%8,%9}, {%0,%1,%2,%3};\n"
                        : "+f"(acc[mt][nt][0]), "+f"(acc[mt][nt][1]),
                          "+f"(acc[mt][nt][2]), "+f"(acc[mt][nt][3])
                        : "r"(af[mt][0]), "r"(af[mt][1]), "r"(af[mt][2]), "r"(af[mt][3]),
                          "r"(bfr[nt][0]), "r"(bfr[nt][1]));
                }
        }
    }

    // ---- epilogue ----
#pragma unroll
    for (int mt = 0; mt < 4; mt++) {
#pragma unroll
        for (int nt = 0; nt < NT; nt++) {
            int c0 = n0 + n0w + nt*8 + 2*tg;
#pragma unroll
            for (int h = 0; h < 2; h++) {
                int r = m0 + mt*16 + g + h*8;
                float x0 = acc[mt][nt][h*2+0];
                float x1 = acc[mt][nt][h*2+1];
                if (bias) { x0 += bias[c0]; x1 += bias[c0+1]; }
                if (RES == 1) { x0 += res[(size_t)r*N + c0]; x1 += res[(size_t)r*N + c0+1]; }
                if (RES == 2) { x0 += res[(size_t)(r >> 5)*N + c0]; x1 += res[(size_t)(r >> 5)*N + c0+1]; }
                if (ACT == 1) { x0 = fmaxf(x0, 0.f); x1 = fmaxf(x1, 0.f); }
                if (ACT == 2) {
                    x0 = 0.5f*x0*(1.f + erff(x0*0.70710678118654752f));
                    x1 = 0.5f*x1*(1.f + erff(x1*0.70710678118654752f));
                }
                if (OUTBF) {
                    __nv_bfloat162 v2 = __floats2bfloat162_rn(x0, x1);
                    *(__nv_bfloat162*)&Cb[(size_t)r*N + c0] = v2;
                } else {
                    *(float2*)&Cf[(size_t)r*N + c0] = make_float2(x0, x1);
                }
            }
        }
    }
}

// --------------------------- BN column stats ---------------------------------
__global__ void colstats_kernel(const float* __restrict__ X, int M, int C,
                                float* __restrict__ psum, float* __restrict__ psq)
{
    int c = blockIdx.x * 32 + threadIdx.x;
    int ry = threadIdx.y;                     // 8
    float s = 0.f, s2 = 0.f;
    for (int r = blockIdx.y*8 + ry; r < M; r += gridDim.y*8) {
        float v = X[(size_t)r*C + c];
        s += v; s2 += v*v;
    }
    __shared__ float sh[8][32], sh2[8][32];
    sh[ry][threadIdx.x] = s; sh2[ry][threadIdx.x] = s2;
    __syncthreads();
    if (ry == 0) {
        for (int j = 1; j < 8; j++) { s += sh[j][threadIdx.x]; s2 += sh2[j][threadIdx.x]; }
        psum[blockIdx.y*C + c] = s;
        psq [blockIdx.y*C + c] = s2;
    }
}

__global__ void colstats_bf_kernel(const __nv_bfloat16* __restrict__ X, int M, int C,
                                   float* __restrict__ psum, float* __restrict__ psq)
{
    int c = blockIdx.x * 32 + threadIdx.x;
    int ry = threadIdx.y;                     // 8
    float s = 0.f, s2 = 0.f;
    for (int r = blockIdx.y*8 + ry; r < M; r += gridDim.y*8) {
        float v = __bfloat162float(X[(size_t)r*C + c]);
        s += v; s2 += v*v;
    }
    __shared__ float sh[8][32], sh2[8][32];
    sh[ry][threadIdx.x] = s; sh2[ry][threadIdx.x] = s2;
    __syncthreads();
    if (ry == 0) {
        for (int j = 1; j < 8; j++) { s += sh[j][threadIdx.x]; s2 += sh2[j][threadIdx.x]; }
        psum[blockIdx.y*C + c] = s;
        psq [blockIdx.y*C + c] = s2;
    }
}

__global__ void bnfin_kernel(const float* __restrict__ psum, const float* __restrict__ psq,
                             int C, float invM,
                             const float* __restrict__ g, const float* __restrict__ b,
                             float* __restrict__ scale, float* __restrict__ shift)
{
    int c = blockIdx.x * blockDim.x + threadIdx.x;
    if (c >= C) return;
    float s = 0.f, s2 = 0.f;
    for (int j = 0; j < 64; j++) { s += psum[j*C + c]; s2 += psq[j*C + c]; }
    float mean = s * invM;
    float var  = s2 * invM - mean*mean;
    float sc = g[c] * rsqrtf(var + EPSf);
    scale[c] = sc;
    shift[c] = b[c] - mean*sc;
}

// ------------------------------ max pools (bf16) ------------------------------
__global__ void gmax_kernel(const __nv_bfloat16* __restrict__ f2, __nv_bfloat16* __restrict__ gm)
{
    int g = blockIdx.x; int c = threadIdx.x;  // 256
    float m = -3.4e38f;
    for (int k = 0; k < KNb; k++) m = fmaxf(m, __bfloat162float(f2[((size_t)g*KNb + k)*256 + c]));
    gm[(size_t)g*256 + c] = __float2bfloat16(m);
}

__global__ void tokmax_kernel(const __nv_bfloat16* __restrict__ s2, const float* __restrict__ sos,
                              float* __restrict__ h)
{
    int bg = blockIdx.x; int c = threadIdx.x; // 384
    int g = bg & (GG-1);
    float m = -3.4e38f;
    for (int k = 0; k < KNb; k++) m = fmaxf(m, __bfloat162float(s2[((size_t)bg*KNb + k)*CC + c]));
    if (g < GG-1) h[(size_t)(bg+1)*CC + c] = m;   // shift-right (sos at g=0)
    if (g == 0)   h[(size_t)bg*CC + c] = sos[c];
}

// --------------------------- positional embedding ----------------------------
__global__ void pos_kernel(const float* __restrict__ cenO, float* __restrict__ pos)
{
    int bg = blockIdx.x; int t = threadIdx.x; // 384
    int ch = t >> 7;
    int rem = t & 127;
    int i = rem >> 1, s = rem & 1;
    float coord = cenO[bg*3 + ch];
    float inv = expf(-(2.f * (float)i / 128.f) * logf(10000.f));
    float ang = coord * inv;
    pos[(size_t)bg*CC + t] = s ? cosf(ang) : sinf(ang);
}

// ------------------------------ LayerNorm (warp per row) ---------------------
template<int YBF>
__global__ void ln_kernel(const float* __restrict__ x, const float* __restrict__ pos,
                          float* __restrict__ xin, void* __restrict__ yv,
                          const float* __restrict__ gw, const float* __restrict__ bw)
{
    int lane = threadIdx.x & 31, warp = threadIdx.x >> 5;
    int r = blockIdx.x * 4 + warp;            // 128 threads = 4 rows
    const int NV = CC / 32;                   // 12
    float v[NV];
    float s = 0.f;
#pragma unroll
    for (int i = 0; i < NV; i++) {
        int c = lane + i*32;
        float vv = x[(size_t)r*CC + c];
        if (pos) vv += pos[(size_t)r*CC + c];
        if (xin) xin[(size_t)r*CC + c] = vv;
        v[i] = vv; s += vv;
    }
#pragma unroll
    for (int off = 16; off > 0; off >>= 1) s += __shfl_xor_sync(0xffffffffu, s, off);
    float mean = s / (float)CC;
    float d = 0.f;
#pragma unroll
    for (int i = 0; i < NV; i++) { float e = v[i]-mean; d += e*e; }
#pragma unroll
    for (int off = 16; off > 0; off >>= 1) d += __shfl_xor_sync(0xffffffffu, d, off);
    float rstd = rsqrtf(d / (float)CC + EPSf);
#pragma unroll
    for (int i = 0; i < NV; i++) {
        int c = lane + i*32;
        float o = (v[i]-mean)*rstd*gw[c] + bw[c];
        if (YBF) ((__nv_bfloat16*)yv)[(size_t)r*CC + c] = __float2bfloat16(o);
        else     ((float*)yv)[(size_t)r*CC + c] = o;
    }
}

// ------------------------------ attention ------------------------------------
__global__ void __launch_bounds__(1024) attn_kernel(const float* __restrict__ qkv,
                                                    __nv_bfloat16* __restrict__ out)
{
    __shared__ float sK[128*64];    // 32 KB
    int h = blockIdx.x, b = blockIdx.y;
    int tid = threadIdx.x;
    int tq = tid >> 3, dsl = tid & 7;
    const float* base = qkv + (size_t)b*GG*(3*CC) + h*64;

    {
        const float* krow = base + (size_t)tq*(3*CC) + CC + dsl*8;
        *(float4*)&sK[tq*64 + dsl*8]     = *(const float4*)&krow[0];
        *(float4*)&sK[tq*64 + dsl*8 + 4] = *(const float4*)&krow[4];
    }
    float q[8];
    {
        const float* qrow = base + (size_t)tq*(3*CC) + dsl*8;
        *(float4*)&q[0] = *(const float4*)&qrow[0];
        *(float4*)&q[4] = *(const float4*)&qrow[4];
    }
    __syncthreads();

    unsigned grpmask = 0xFFu << (((tid & 31) >> 3) << 3);
    const float scale = 0.125f;
    float mx = -3.4e38f, sum = 0.f;
    float acc[8];
#pragma unroll
    for (int d = 0; d < 8; d++) acc[d] = 0.f;

    for (int j = 0; j <= tq; j++) {
        const float* ks = &sK[j*64 + dsl*8];
        float s = 0.f;
#pragma unroll
        for (int d = 0; d < 8; d++) s = fmaf(q[d], ks[d], s);
        s += __shfl_xor_sync(grpmask, s, 1);
        s += __shfl_xor_sync(grpmask, s, 2);
        s += __shfl_xor_sync(grpmask, s, 4);
        s *= scale;
        const float* vrow = base + (size_t)j*(3*CC) + 2*CC + dsl*8;
        float4 v0 = *(const float4*)&vrow[0];
        float4 v1 = *(const float4*)&vrow[4];
        float v[8] = {v0.x, v0.y, v0.z, v0.w, v1.x, v1.y, v1.z, v1.w};
        if (s > mx) {
            float corr = __expf(mx - s);
            sum = fmaf(sum, corr, 1.f);
#pragma unroll
            for (int d = 0; d < 8; d++) acc[d] = fmaf(acc[d], corr, v[d]);
            mx = s;
        } else {
            float e = __expf(s - mx);
            sum += e;
#pragma unroll
            for (int d = 0; d < 8; d++) acc[d] = fmaf(e, v[d], acc[d]);
        }
    }
    float inv = 1.f / sum;
    __nv_bfloat16* dst = out + ((size_t)(b*GG + tq))*CC + h*64 + dsl*8;
#pragma unroll
    for (int d = 0; d < 8; d += 2) {
        __nv_bfloat162 v2 = __floats2bfloat162_rn(acc[d]*inv, acc[d+1]*inv);
        *(__nv_bfloat162*)&dst[d] = v2;
    }
}

// --------------------------------- launch ------------------------------------
static void* symv(const void* s) { void* p = nullptr; cudaGetSymbolAddress(&p, s); return p; }
static float* sym(const void* s) { return (float*)symv(s); }
static __nv_bfloat16* symb(const void* s) { return (__nv_bfloat16*)symv(s); }

extern "C" void kernel_launch(void* const* d_in, const int* in_sizes, int n_in,
                              void* d_out, int out_size)
{
    const float* xyz    = (const float*)d_in[0];
    const float* ec1_w  = (const float*)d_in[1];
    const float* ec1_b  = (const float*)d_in[2];
    const float* bn1_g  = (const float*)d_in[3];
    const float* bn1_b  = (const float*)d_in[4];
    const float* ec2_w  = (const float*)d_in[5];
    const float* ec2_b  = (const float*)d_in[6];
    const float* sc1_w  = (const float*)d_in[7];
    const float* sc1_b  = (const float*)d_in[8];
    const float* bn2_g  = (const float*)d_in[9];
    const float* bn2_b  = (const float*)d_in[10];
    const float* sc2_w  = (const float*)d_in[11];
    const float* sc2_b  = (const float*)d_in[12];
    const float* sos    = (const float*)d_in[13];
    const float* ln1_g  = (const float*)d_in[14];
    const float* ln1_b  = (const float*)d_in[15];
    const float* qkv_w  = (const float*)d_in[16];
    const float* qkv_b  = (const float*)d_in[17];
    const float* out_w  = (const float*)d_in[18];
    const float* out_b  = (const float*)d_in[19];
    const float* ln2_g  = (const float*)d_in[20];
    const float* ln2_b  = (const float*)d_in[21];
    const float* mlp1_w = (const float*)d_in[22];
    const float* mlp1_b = (const float*)d_in[23];
    const float* mlp2_w = (const float*)d_in[24];
    const float* mlp2_b = (const float*)d_in[25];
    const float* lnf_g  = (const float*)d_in[26];
    const float* lnf_b  = (const float*)d_in[27];

    float* p_center  = sym(g_center);
    float* p_centerO = sym(g_centerO);
    float* p_neigh   = sym(g_neigh);
    float* p_f1   = sym(g_f1);
    float* p_t    = sym(g_t);
    float* p_psum = sym(g_psum);
    float* p_psq  = sym(g_psq);
    float* p_scale= sym(g_scale);
    float* p_shift= sym(g_shift);
    float* p_h    = sym(g_h);
    float* p_pos  = sym(g_pos);
    float* p_xin  = sym(g_xin);
    float* p_x1   = sym(g_x1);
    float* p_qkv  = sym(g_qkv);
    __nv_bfloat16* p_f1b   = symb(g_f1b);
    __nv_bfloat16* p_f2b   = symb(g_f2b);
    __nv_bfloat16* p_gmaxb = symb(g_gmaxb);
    __nv_bfloat16* p_s1b   = symb(g_s1b);
    __nv_bfloat16* p_s1c   = symb(g_s1c);
    __nv_bfloat16* p_s2b   = symb(g_s2b);
    __nv_bfloat16* p_ybf   = symb(g_ybf);
    __nv_bfloat16* p_attnbf= symb(g_attnbf);
    __nv_bfloat16* p_mhbf  = symb(g_mhbf);
    __nv_bfloat16* p_wqkv  = symb(g_wqkv);
    __nv_bfloat16* p_wout  = symb(g_wout);
    __nv_bfloat16* p_wm1   = symb(g_wm1);
    __nv_bfloat16* p_wm2   = symb(g_wm2);
    __nv_bfloat16* p_wec2  = symb(g_wec2);
    __nv_bfloat16* p_wsc1  = symb(g_wsc1);
    __nv_bfloat16* p_wsc2  = symb(g_wsc2);

    // ---- weight preconversion (fp32 -> bf16) ----
    {
        struct { const float* s; __nv_bfloat16* d; size_t n; } cv[7] = {
            { qkv_w,  p_wqkv, (size_t)LL*3*CC*CC },
            { out_w,  p_wout, (size_t)LL*CC*CC },
            { mlp1_w, p_wm1,  (size_t)LL*HIDD*CC },
            { mlp2_w, p_wm2,  (size_t)LL*CC*HIDD },
            { ec2_w,  p_wec2, (size_t)256*128 },
            { sc1_w,  p_wsc1, (size_t)512*512 },
            { sc2_w,  p_wsc2, (size_t)384*512 },
        };
        for (int i = 0; i < 7; i++) {
            int n4 = (int)(cv[i].n / 4);
            cvt_kernel<<<(n4 + 255)/256, 256>>>(cv[i].s, cv[i].d, n4);
        }
    }

    // ---- grouping ----
    fps_kernel  <<<BB, 1024>>>(xyz, p_center);
    order_kernel<<<BB, GG  >>>(p_center, p_centerO);
    knn_kernel  <<<BG, 256 >>>(xyz, p_centerO, p_neigh);

    // ---- encoder ----
    gemm_k<0,0,0><<<dim3(128/64, MROWS/64), 256>>>(p_neigh, 3, ec1_w, 3, ec1_b,
                                                   nullptr, nullptr, nullptr,
                                                   p_f1, MROWS, 128, 3);
    colstats_kernel<<<dim3(128/32, 64), dim3(32,8)>>>(p_f1, MROWS, 128, p_psum, p_psq);
    bnfin_kernel<<<1, 128>>>(p_psum, p_psq, 128, 1.f/(float)MROWS, bn1_g, bn1_b, p_scale, p_shift);
    bnapply_f_kernel<<<(MROWS*128/4 + 255)/256, 256>>>(p_f1, p_scale, p_shift, p_f1b,
                                                       MROWS*128/4, 127);
    // ec2: (65536,128)->(65536,256) bf16
    gemm_bf<0,0,1><<<dim3(256/128, MROWS/64), 256>>>(p_f1b, 128, p_wec2, 128, ec2_b,
                                                     nullptr, p_f2b, MROWS, 256, 128);
    gmax_kernel<<<BG, 256>>>(p_f2b, p_gmaxb);
    // t = gmax @ sc1_w[:, :256]^T + sc1_b  (fp32 out)
    gemm_bf<0,0,0><<<dim3(512/128, BG/64), 256>>>(p_gmaxb, 256, p_wsc1, 512, sc1_b,
                                                  nullptr, p_t, BG, 512, 256);
    // s1 = f2 @ sc1_w[:, 256:]^T + broadcast(t) -> bf16
    gemm_bf<0,2,1><<<dim3(512/128, MROWS/64), 256>>>(p_f2b, 256, p_wsc1 + 256, 512, nullptr,
                                                     p_t, p_s1b, MROWS, 512, 256);
    colstats_bf_kernel<<<dim3(512/32, 64), dim3(32,8)>>>(p_s1b, MROWS, 512, p_psum, p_psq);
    bnfin_kernel<<<4, 128>>>(p_psum, p_psq, 512, 1.f/(float)MROWS, bn2_g, bn2_b, p_scale, p_shift);
    bnapply_b_kernel<<<(MROWS*512/4 + 255)/256, 256>>>(p_s1b, p_scale, p_shift, p_s1c,
                                                       MROWS*512/4, 511);
    // sc2: (65536,512)->(65536,384) bf16
    gemm_bf<0,0,1><<<dim3(384/128, MROWS/64), 256>>>(p_s1c, 512, p_wsc2, 512, sc2_b,
                                                     nullptr, p_s2b, MROWS, 384, 512);
    tokmax_kernel<<<BG, CC>>>(p_s2b, sos, p_h);
    pos_kernel<<<BG, CC>>>(p_centerO, p_pos);

    // ---- GPT ----
    for (int l = 0; l < LL; l++) {
        const __nv_bfloat16* qw = p_wqkv + (size_t)l*3*CC*CC;
        const float* qb = qkv_b  + (size_t)l*3*CC;
        const __nv_bfloat16* ow = p_wout + (size_t)l*CC*CC;
        const float* ob = out_b  + (size_t)l*CC;
        const __nv_bfloat16* m1w= p_wm1 + (size_t)l*HIDD*CC;
        const float* m1b= mlp1_b + (size_t)l*HIDD;
        const __nv_bfloat16* m2w= p_wm2 + (size_t)l*CC*HIDD;
        const float* m2b= mlp2_b + (size_t)l*CC;

        ln_kernel<1><<<BG/4, 128>>>(p_h, p_pos, p_xin, p_ybf, ln1_g + l*CC, ln1_b + l*CC);
        gemm_bf<0,0,0><<<dim3(3*CC/128, BG/64), 256>>>(p_ybf, CC, qw, CC, qb,
                                                       nullptr, p_qkv, BG, 3*CC, CC);
        attn_kernel<<<dim3(HH, BB), 1024>>>(p_qkv, p_attnbf);
        gemm_bf<0,1,0><<<dim3(CC/128, BG/64), 256>>>(p_attnbf, CC, ow, CC, ob,
                                                     p_xin, p_x1, BG, CC, CC);
        ln_kernel<1><<<BG/4, 128>>>(p_x1, nullptr, nullptr, p_ybf, ln2_g + l*CC, ln2_b + l*CC);
        gemm_bf<2,0,1><<<dim3(HIDD/128, BG/64), 256>>>(p_ybf, CC, m1w, CC, m1b,
                                                       nullptr, p_mhbf, BG, HIDD, CC);
        gemm_bf<0,1,0><<<dim3(CC/128, BG/64), 256>>>(p_mhbf, HIDD, m2w, HIDD, m2b,
                                                     p_x1, p_h, BG, CC, HIDD);
    }

    // final LN -> output (fp32)
    ln_kernel<0><<<BG/4, 128>>>(p_h, nullptr, nullptr, (float*)d_out, lnf_g, lnf_b);
}

// round 14
// speedup vs baseline: 4.4812x; 1.0051x over previous
#include <cuda_runtime.h>
#include <cuda_bf16.h>
#include <math.h>
#include <stdint.h>

#define BB 16
#define NP 8192
#define GG 128
#define KNb 32
#define CC 384
#define HH 6
#define LL 12
#define HIDD 1536
#define BG (BB*GG)          /* 2048 */
#define MROWS (BG*KNb)      /* 65536 */
#define EPSf 1e-5f

// ------------------------- scratch (static device memory) -------------------
__device__ float g_center [BG*3];
__device__ float g_centerO[BG*3];
__device__ float g_neigh  [MROWS*3];
__device__ float g_t  [(size_t)BG*512];
__device__ float g_psum[64*512];
__device__ float g_psq [64*512];
__device__ float g_scale[512];
__device__ float g_shift[512];
__device__ float g_h   [BG*CC];
__device__ float g_pos [BG*CC];
__device__ float g_xin [BG*CC];
__device__ float g_x1  [BG*CC];
// bf16 encoder activations
__device__ __align__(16) __nv_bfloat16 g_f1b [(size_t)MROWS*128];
__device__ __align__(16) __nv_bfloat16 g_f1c [(size_t)MROWS*128];
__device__ __align__(16) __nv_bfloat16 g_f2b [(size_t)MROWS*256];
__device__ __align__(16) __nv_bfloat16 g_gmaxb[(size_t)BG*256];
__device__ __align__(16) __nv_bfloat16 g_s1b [(size_t)MROWS*512];
__device__ __align__(16) __nv_bfloat16 g_s1c [(size_t)MROWS*512];
__device__ __align__(16) __nv_bfloat16 g_s2b [(size_t)MROWS*384];
// bf16 transformer activations
__device__ __align__(16) __nv_bfloat16 g_ybf  [BG*CC];
__device__ __align__(16) __nv_bfloat16 g_qkvb [BG*3*CC];
__device__ __align__(16) __nv_bfloat16 g_attnbf[BG*CC];
__device__ __align__(16) __nv_bfloat16 g_mhbf [BG*HIDD];
// bf16 pre-converted weights
__device__ __align__(16) __nv_bfloat16 g_wqkv[(size_t)LL*3*CC*CC];
__device__ __align__(16) __nv_bfloat16 g_wout[(size_t)LL*CC*CC];
__device__ __align__(16) __nv_bfloat16 g_wm1 [(size_t)LL*HIDD*CC];
__device__ __align__(16) __nv_bfloat16 g_wm2 [(size_t)LL*CC*HIDD];
__device__ __align__(16) __nv_bfloat16 g_wec2[256*128];
__device__ __align__(16) __nv_bfloat16 g_wsc1[512*512];
__device__ __align__(16) __nv_bfloat16 g_wsc2[384*512];

// ---------------- fp32 -> bf16 conversion (all weights, 1 launch) ------------
#define CV1 1327104   /* wqkv n4 */
#define CV2 1769472   /* + wout */
#define CV3 3538944   /* + wm1 */
#define CV4 5308416   /* + wm2 */
#define CV5 5316608   /* + wec2 */
#define CV6 5382144   /* + wsc1 */
#define CV7 5431296   /* + wsc2 (total) */
__global__ void cvt_all_kernel(
    const float* __restrict__ s0, const float* __restrict__ s1,
    const float* __restrict__ s2, const float* __restrict__ s3,
    const float* __restrict__ s4, const float* __restrict__ s5,
    const float* __restrict__ s6)
{
    int i = blockIdx.x * blockDim.x + threadIdx.x;
    if (i >= CV7) return;
    const float* src; __nv_bfloat16* dst; int base;
    if      (i < CV1) { src = s0; dst = g_wqkv; base = 0; }
    else if (i < CV2) { src = s1; dst = g_wout; base = CV1; }
    else if (i < CV3) { src = s2; dst = g_wm1;  base = CV2; }
    else if (i < CV4) { src = s3; dst = g_wm2;  base = CV3; }
    else if (i < CV5) { src = s4; dst = g_wec2; base = CV4; }
    else if (i < CV6) { src = s5; dst = g_wsc1; base = CV5; }
    else              { src = s6; dst = g_wsc2; base = CV6; }
    int j = i - base;
    float4 v = *(const float4*)&src[j*4];
    union { __nv_bfloat162 h2[2]; uint2 u; } c;
    c.h2[0] = __floats2bfloat162_rn(v.x, v.y);
    c.h2[1] = __floats2bfloat162_rn(v.z, v.w);
    *(uint2*)&dst[j*4] = c.u;
}

// -------------------- BN apply + relu -> bf16 (bf16 in) ----------------------
__global__ void bnapply_b_kernel(const __nv_bfloat16* __restrict__ x,
                                 const float* __restrict__ sc, const float* __restrict__ sh,
                                 __nv_bfloat16* __restrict__ y, int n4, int cmask)
{
    int i = blockIdx.x * blockDim.x + threadIdx.x;
    if (i >= n4) return;
    union { __nv_bfloat162 h2[2]; uint2 u; } in;
    in.u = *(const uint2*)&x[i*4];
    float4 v;
    v.x = __bfloat162float(in.h2[0].x); v.y = __bfloat162float(in.h2[0].y);
    v.z = __bfloat162float(in.h2[1].x); v.w = __bfloat162float(in.h2[1].y);
    int c = (i*4) & cmask;
    float4 s = *(const float4*)&sc[c];
    float4 h = *(const float4*)&sh[c];
    v.x = fmaxf(fmaf(v.x,s.x,h.x),0.f);
    v.y = fmaxf(fmaf(v.y,s.y,h.y),0.f);
    v.z = fmaxf(fmaf(v.z,s.z,h.z),0.f);
    v.w = fmaxf(fmaf(v.w,s.w,h.w),0.f);
    union { __nv_bfloat162 h2[2]; uint2 u; } o;
    o.h2[0] = __floats2bfloat162_rn(v.x, v.y);
    o.h2[1] = __floats2bfloat162_rn(v.z, v.w);
    *(uint2*)&y[i*4] = o.u;
}

// ------------------------------- FPS ----------------------------------------
__global__ void fps_kernel(const float* __restrict__ xyz, float* __restrict__ center)
{
    int b = blockIdx.x;
    int t = threadIdx.x;                      // 1024 threads = 32 warps
    int lane = t & 31, warp = t >> 5;
    const float* X = xyz + (size_t)b * NP * 3;
    float px[8], py[8], pz[8], dd[8];
#pragma unroll
    for (int j = 0; j < 8; j++) {
        int p = t + j * 1024;
        px[j] = X[p*3+0]; py[j] = X[p*3+1]; pz[j] = X[p*3+2];
        dd[j] = 1e10f;
    }
    __shared__ float rv[32];
    __shared__ int   ri[32];
    __shared__ int   s_far;
    int far = 0;
    for (int it = 0; it < GG; it++) {
        float cx = X[far*3+0], cy = X[far*3+1], cz = X[far*3+2];
        if (t == 0) {
            center[(b*GG+it)*3+0] = cx;
            center[(b*GG+it)*3+1] = cy;
            center[(b*GG+it)*3+2] = cz;
        }
        float bv = -1.f; int bi = 0;
#pragma unroll
        for (int j = 0; j < 8; j++) {
            float dx = px[j]-cx, dy = py[j]-cy, dz = pz[j]-cz;
            float d = dx*dx + dy*dy + dz*dz;
            if (d < dd[j]) dd[j] = d;
            if (dd[j] > bv) { bv = dd[j]; bi = t + j*1024; }
        }
#pragma unroll
        for (int off = 16; off > 0; off >>= 1) {
            float ov = __shfl_down_sync(0xffffffffu, bv, off);
            int   oi = __shfl_down_sync(0xffffffffu, bi, off);
            if (ov > bv || (ov == bv && oi < bi)) { bv = ov; bi = oi; }
        }
        if (lane == 0) { rv[warp] = bv; ri[warp] = bi; }
        __syncthreads();
        if (warp == 0) {
            bv = rv[lane]; bi = ri[lane];
#pragma unroll
            for (int off = 16; off > 0; off >>= 1) {
                float ov = __shfl_down_sync(0xffffffffu, bv, off);
                int   oi = __shfl_down_sync(0xffffffffu, bi, off);
                if (ov > bv || (ov == bv && oi < bi)) { bv = ov; bi = oi; }
            }
            if (lane == 0) s_far = bi;
        }
        __syncthreads();
        far = s_far;
    }
}

// --------------------------- greedy NN ordering ------------------------------
__global__ void order_kernel(const float* __restrict__ cen, float* __restrict__ cenO)
{
    int b = blockIdx.x;
    int t = threadIdx.x;                      // 128 threads = 4 warps
    int lane = t & 31, warp = t >> 5;
    __shared__ float cx[GG], cy[GG], cz[GG], nn[GG];
    __shared__ int visited[GG];
    __shared__ int s_last;
    __shared__ float rv[4];
    __shared__ int ri[4];
    cx[t] = cen[(b*GG+t)*3+0];
    cy[t] = cen[(b*GG+t)*3+1];
    cz[t] = cen[(b*GG+t)*3+2];
    nn[t] = cx[t]*cx[t] + cy[t]*cy[t] + cz[t]*cz[t];
    visited[t] = 0;
    if (t == 0) {
        visited[0] = 1; s_last = 0;
        cenO[(b*GG)*3+0] = cx[0]; cenO[(b*GG)*3+1] = cy[0]; cenO[(b*GG)*3+2] = cz[0];
    }
    __syncthreads();
    for (int step = 1; step < GG; step++) {
        int last = s_last;
        float d;
        if (visited[t]) d = 3.4e38f;
        else {
            float dot = cx[last]*cx[t] + cy[last]*cy[t] + cz[last]*cz[t];
            d = fmaxf(nn[last] + nn[t] - 2.f*dot, 0.f);
        }
        float bv = d; int bi = t;
#pragma unroll
        for (int off = 16; off > 0; off >>= 1) {
            float ov = __shfl_down_sync(0xffffffffu, bv, off);
            int   oi = __shfl_down_sync(0xffffffffu, bi, off);
            if (ov < bv || (ov == bv && oi < bi)) { bv = ov; bi = oi; }
        }
        if (lane == 0) { rv[warp] = bv; ri[warp] = bi; }
        __syncthreads();
        if (t == 0) {
            float mv = rv[0]; int mi = ri[0];
#pragma unroll
            for (int j = 1; j < 4; j++)
                if (rv[j] < mv || (rv[j] == mv && ri[j] < mi)) { mv = rv[j]; mi = ri[j]; }
            visited[mi] = 1; s_last = mi;
            cenO[(b*GG+step)*3+0] = cx[mi];
            cenO[(b*GG+step)*3+1] = cy[mi];
            cenO[(b*GG+step)*3+2] = cz[mi];
        }
        __syncthreads();
    }
}

// ------------------------------- kNN + gather --------------------------------
__global__ void knn_kernel(const float* __restrict__ xyz, const float* __restrict__ cenO,
                           float* __restrict__ neigh)
{
    int bg = blockIdx.x;
    int b  = bg >> 7;
    int t  = threadIdx.x;                     // 256 threads = 8 warps
    int lane = t & 31, warp = t >> 5;
    const float* X = xyz + (size_t)b * NP * 3;
    float cx = cenO[bg*3+0], cy = cenO[bg*3+1], cz = cenO[bg*3+2];
    __shared__ float sd[NP];
    __shared__ float rv[8];
    __shared__ int ri[8];
#pragma unroll
    for (int j = 0; j < NP/256; j++) {
        int p = t + j*256;
        float dx = X[p*3+0]-cx, dy = X[p*3+1]-cy, dz = X[p*3+2]-cz;
        sd[p] = dx*dx + dy*dy + dz*dz;
    }
    __syncthreads();
    for (int k = 0; k < KNb; k++) {
        float bv = 3.4e38f; int bi = 0;
#pragma unroll
        for (int j = 0; j < NP/256; j++) {
            int p = t + j*256;
            float d = sd[p];
            if (d < bv) { bv = d; bi = p; }
        }
#pragma unroll
        for (int off = 16; off > 0; off >>= 1) {
            float ov = __shfl_down_sync(0xffffffffu, bv, off);
            int   oi = __shfl_down_sync(0xffffffffu, bi, off);
            if (ov < bv || (ov == bv && oi < bi)) { bv = ov; bi = oi; }
        }
        if (lane == 0) { rv[warp] = bv; ri[warp] = bi; }
        __syncthreads();
        if (t == 0) {
            float mv = rv[0]; int mi = ri[0];
#pragma unroll
            for (int j = 1; j < 8; j++)
                if (rv[j] < mv || (rv[j] == mv && ri[j] < mi)) { mv = rv[j]; mi = ri[j]; }
            neigh[((size_t)bg*KNb + k)*3+0] = X[mi*3+0]-cx;
            neigh[((size_t)bg*KNb + k)*3+1] = X[mi*3+1]-cy;
            neigh[((size_t)bg*KNb + k)*3+2] = X[mi*3+2]-cz;
            sd[mi] = 3.4e38f;
        }
        __syncthreads();
    }
}

// ---------------- small-K GEMM (only ec1, K=3), bf16 output ------------------
__global__ void __launch_bounds__(256) gemm_k(
    const float* __restrict__ A, int lda,
    const float* __restrict__ W, int ldw,
    const float* __restrict__ bias,
    __nv_bfloat16* __restrict__ C, int M, int N, int K)
{
    __shared__ float As[16][64];
    __shared__ float Ws[16][64];
    int tid = threadIdx.x;
    int tx = tid & 15, ty = tid >> 4;
    int m0 = blockIdx.y * 64, n0 = blockIdx.x * 64;
    float acc[4][4] = {};
    for (int kk = 0; kk < K; kk += 16) {
#pragma unroll
        for (int i = 0; i < 4; i++) {
            int idx = tid + i*256;
            int k = idx & 15, m = idx >> 4;
            float a = 0.f, w = 0.f;
            if (kk + k < K) {
                a = A[(size_t)(m0+m)*lda + kk + k];
                w = W[(size_t)(n0+m)*ldw + kk + k];
            }
            As[k][m] = a;
            Ws[k][m] = w;
        }
        __syncthreads();
#pragma unroll
        for (int k = 0; k < 16; k++) {
            float4 av = *(const float4*)&As[k][ty*4];
            float4 wv = *(const float4*)&Ws[k][tx*4];
            float ar[4] = {av.x, av.y, av.z, av.w};
            float wr[4] = {wv.x, wv.y, wv.z, wv.w};
#pragma unroll
            for (int i = 0; i < 4; i++)
#pragma unroll
                for (int j = 0; j < 4; j++)
                    acc[i][j] = fmaf(ar[i], wr[j], acc[i][j]);
        }
        __syncthreads();
    }
#pragma unroll
    for (int i = 0; i < 4; i++) {
        int m = m0 + ty*4 + i;
#pragma unroll
        for (int j = 0; j < 4; j += 2) {
            int n = n0 + tx*4 + j;
            float v0 = acc[i][j]   + bias[n];
            float v1 = acc[i][j+1] + bias[n+1];
            __nv_bfloat162 v2 = __floats2bfloat162_rn(v0, v1);
            *(__nv_bfloat162*)&C[(size_t)m*N + n] = v2;
        }
    }
}

// ----------------------------- asm helpers -----------------------------------
__device__ __forceinline__ void ldm_x4(uint32_t (&r)[4], const void* p)
{
    uint32_t a = (uint32_t)__cvta_generic_to_shared(p);
    asm volatile("ldmatrix.sync.aligned.m8n8.x4.shared.b16 {%0,%1,%2,%3}, [%4];\n"
        : "=r"(r[0]), "=r"(r[1]), "=r"(r[2]), "=r"(r[3]) : "r"(a));
}
__device__ __forceinline__ void cp16(void* dst, const void* src)
{
    uint32_t d = (uint32_t)__cvta_generic_to_shared(dst);
    asm volatile("cp.async.cg.shared.global [%0], [%1], 16;\n" :: "r"(d), "l"(src));
}
__device__ __forceinline__ void cp_commit() { asm volatile("cp.async.commit_group;\n"); }

// ------------------- bf16 tensor-core GEMM (cp.async 3-stage) ----------------
// 64 x 128 block tile, KT=32, 256 threads = 8 warps in 2x4 grid,
// warp tile 32x32 (mt=2, nt=4). A,W bf16; fragments via ldmatrix.x4;
// rows padded to RS=40 (20-bank stride). Static smem 46080 B.
// M%64==0, N%128==0, K%32==0, K/32 >= 2.
template<int ACT, int RES, int OUTBF>
__global__ void __launch_bounds__(256) gemm_bf(
    const __nv_bfloat16* __restrict__ A, int lda,
    const __nv_bfloat16* __restrict__ W, int ldw,
    const float* __restrict__ bias,
    const float* __restrict__ res,
    void* __restrict__ Cv, int M, int N, int K)
{
    constexpr int BM = 64, KT = 32, RS = 40, ST = 3;
    __shared__ __align__(16) __nv_bfloat16 As[ST][BM][RS];
    __shared__ __align__(16) __nv_bfloat16 Ws[ST][128][RS];

    float* Cf = (float*)Cv;
    __nv_bfloat16* Cb = (__nv_bfloat16*)Cv;

    int tid  = threadIdx.x;
    int m0 = blockIdx.y * BM, n0 = blockIdx.x * 128;
    int lane = tid & 31, warp = tid >> 5;
    int m0w = (warp & 1) * 32;            // 2 m-warps
    int n0w = (warp >> 1) * 32;           // 4 n-warps
    int g  = lane >> 2, tg = lane & 3;
    int laneR  = lane & 15;
    int laneK8 = ((lane >> 4) & 1) << 3;

    float acc[2][4][4];
#pragma unroll
    for (int a = 0; a < 2; a++)
#pragma unroll
        for (int b = 0; b < 4; b++)
#pragma unroll
            for (int c = 0; c < 4; c++) acc[a][b][c] = 0.f;

    auto load_stage = [&](int s, int kk) {
        {   // A: 64 rows x 32 cols bf16 = 256 chunks of 16B -> 1 per thread
            int m = tid >> 2, c = tid & 3;
            cp16(&As[s][m][c*8], &A[(size_t)(m0+m)*lda + kk + c*8]);
        }
#pragma unroll
        for (int j = 0; j < 2; j++) {   // W: 128 rows -> 512 chunks
            int f = tid + j*256; int m = f >> 2, c = f & 3;
            cp16(&Ws[s][m][c*8], &W[(size_t)(n0+m)*ldw + kk + c*8]);
        }
        cp_commit();
    };

    int ntiles = K / KT;
#pragma unroll
    for (int s = 0; s < ST-1; s++) {
        if (s < ntiles) load_stage(s, s*KT);
        else cp_commit();
    }

    for (int t = 0; t < ntiles; t++) {
        asm volatile("cp.async.wait_group %0;\n" :: "n"(ST-2));
        __syncthreads();
        int nl = t + ST - 1;
        if (nl < ntiles) load_stage(nl % ST, nl*KT);
        else cp_commit();
        int buf = t % ST;
#pragma unroll
        for (int ks = 0; ks < 2; ks++) {
            int kb = ks*16;
            uint32_t af[2][4], bfr[4][2];
#pragma unroll
            for (int mt = 0; mt < 2; mt++)
                ldm_x4(af[mt], &As[buf][m0w + mt*16 + laneR][kb + laneK8]);
#pragma unroll
            for (int np = 0; np < 2; np++) {
                uint32_t tmp[4];
                ldm_x4(tmp, &Ws[buf][n0w + np*16 + laneR][kb + laneK8]);
                bfr[np*2+0][0] = tmp[0]; bfr[np*2+1][0] = tmp[1];
                bfr[np*2+0][1] = tmp[2]; bfr[np*2+1][1] = tmp[3];
            }
#pragma unroll
            for (int mt = 0; mt < 2; mt++)
#pragma unroll
                for (int nt = 0; nt < 4; nt++) {
                    asm volatile(
                        "mma.sync.aligned.m16n8k16.row.col.f32.bf16.bf16.f32 "
                        "{%0,%1,%2,%3}, {%4,%5,%6,%7}, {%8,%9}, {%0,%1,%2,%3};\n"
                        : "+f"(acc[mt][nt][0]), "+f"(acc[mt][nt][1]),
                          "+f"(acc[mt][nt][2]), "+f"(acc[mt][nt][3])
                        : "r"(af[mt][0]), "r"(af[mt][1]), "r"(af[mt][2]), "r"(af[mt][3]),
                          "r"(bfr[nt][0]), "r"(bfr[nt][1]));
                }
        }
    }

    // ---- epilogue ----
#pragma unroll
    for (int mt = 0; mt < 2; mt++) {
#pragma unroll
        for (int nt = 0; nt < 4; nt++) {
            int c0 = n0 + n0w + nt*8 + 2*tg;
#pragma unroll
            for (int h = 0; h < 2; h++) {
                int r = m0 + m0w + mt*16 + g + h*8;
                float x0 = acc[mt][nt][h*2+0];
                float x1 = acc[mt][nt][h*2+1];
                if (bias) { x0 += bias[c0]; x1 += bias[c0+1]; }
                if (RES == 1) { x0 += res[(size_t)r*N + c0]; x1 += res[(size_t)r*N + c0+1]; }
                if (RES == 2) { x0 += res[(size_t)(r >> 5)*N + c0]; x1 += res[(size_t)(r >> 5)*N + c0+1]; }
                if (ACT == 1) { x0 = fmaxf(x0, 0.f); x1 = fmaxf(x1, 0.f); }
                if (ACT == 2) {
                    x0 = 0.5f*x0*(1.f + erff(x0*0.70710678118654752f));
                    x1 = 0.5f*x1*(1.f + erff(x1*0.70710678118654752f));
                }
                if (OUTBF) {
                    __nv_bfloat162 v2 = __floats2bfloat162_rn(x0, x1);
                    *(__nv_bfloat162*)&Cb[(size_t)r*N + c0] = v2;
                } else {
                    *(float2*)&Cf[(size_t)r*N + c0] = make_float2(x0, x1);
                }
            }
        }
    }
}

// --------------------------- BN column stats (bf16) ---------------------------
__global__ void colstats_bf_kernel(const __nv_bfloat16* __restrict__ X, int M, int C,
                                   float* __restrict__ psum, float* __restrict__ psq)
{
    int c = blockIdx.x * 32 + threadIdx.x;
    int ry = threadIdx.y;                     // 8
    float s = 0.f, s2 = 0.f;
    for (int r = blockIdx.y*8 + ry; r < M; r += gridDim.y*8) {
        float v = __bfloat162float(X[(size_t)r*C + c]);
        s += v; s2 += v*v;
    }
    __shared__ float sh[8][32], sh2[8][32];
    sh[ry][threadIdx.x] = s; sh2[ry][threadIdx.x] = s2;
    __syncthreads();
    if (ry == 0) {
        for (int j = 1; j < 8; j++) { s += sh[j][threadIdx.x]; s2 += sh2[j][threadIdx.x]; }
        psum[blockIdx.y*C + c] = s;
        psq [blockIdx.y*C + c] = s2;
    }
}

__global__ void bnfin_kernel(const float* __restrict__ psum, const float* __restrict__ psq,
                             int C, float invM,
                             const float* __restrict__ g, const float* __restrict__ b,
                             float* __restrict__ scale, float* __restrict__ shift)
{
    int c = blockIdx.x * blockDim.x + threadIdx.x;
    if (c >= C) return;
    float s = 0.f, s2 = 0.f;
    for (int j = 0; j < 64; j++) { s += psum[j*C + c]; s2 += psq[j*C + c]; }
    float mean = s * invM;
    float var  = s2 * invM - mean*mean;
    float sc = g[c] * rsqrtf(var + EPSf);
    scale[c] = sc;
    shift[c] = b[c] - mean*sc;
}

// ------------------------------ max pools (bf16) ------------------------------
__global__ void gmax_kernel(const __nv_bfloat16* __restrict__ f2, __nv_bfloat16* __restrict__ gm)
{
    int g = blockIdx.x; int c = threadIdx.x;  // 256
    float m = -3.4e38f;
    for (int k = 0; k < KNb; k++) m = fmaxf(m, __bfloat162float(f2[((size_t)g*KNb + k)*256 + c]));
    gm[(size_t)g*256 + c] = __float2bfloat16(m);
}

__global__ void tokmax_kernel(const __nv_bfloat16* __restrict__ s2, const float* __restrict__ sos,
                              float* __restrict__ h)
{
    int bg = blockIdx.x; int c = threadIdx.x; // 384
    int g = bg & (GG-1);
    float m = -3.4e38f;
    for (int k = 0; k < KNb; k++) m = fmaxf(m, __bfloat162float(s2[((size_t)bg*KNb + k)*CC + c]));
    if (g < GG-1) h[(size_t)(bg+1)*CC + c] = m;   // shift-right (sos at g=0)
    if (g == 0)   h[(size_t)bg*CC + c] = sos[c];
}

// --------------------------- positional embedding ----------------------------
__global__ void pos_kernel(const float* __restrict__ cenO, float* __restrict__ pos)
{
    int bg = blockIdx.x; int t = threadIdx.x; // 384
    int ch = t >> 7;
    int rem = t & 127;
    int i = rem >> 1, s = rem & 1;
    float coord = cenO[bg*3 + ch];
    float inv = expf(-(2.f * (float)i / 128.f) * logf(10000.f));
    float ang = coord * inv;
    pos[(size_t)bg*CC + t] = s ? cosf(ang) : sinf(ang);
}

// ------------------------------ LayerNorm (warp per row) ---------------------
template<int YBF>
__global__ void ln_kernel(const float* __restrict__ x, const float* __restrict__ pos,
                          float* __restrict__ xin, void* __restrict__ yv,
                          const float* __restrict__ gw, const float* __restrict__ bw)
{
    int lane = threadIdx.x & 31, warp = threadIdx.x >> 5;
    int r = blockIdx.x * 4 + warp;            // 128 threads = 4 rows
    const int NV = CC / 32;                   // 12
    float v[NV];
    float s = 0.f;
#pragma unroll
    for (int i = 0; i < NV; i++) {
        int c = lane + i*32;
        float vv = x[(size_t)r*CC + c];
        if (pos) vv += pos[(size_t)r*CC + c];
        if (xin) xin[(size_t)r*CC + c] = vv;
        v[i] = vv; s += vv;
    }
#pragma unroll
    for (int off = 16; off > 0; off >>= 1) s += __shfl_xor_sync(0xffffffffu, s, off);
    float mean = s / (float)CC;
    float d = 0.f;
#pragma unroll
    for (int i = 0; i < NV; i++) { float e = v[i]-mean; d += e*e; }
#pragma unroll
    for (int off = 16; off > 0; off >>= 1) d += __shfl_xor_sync(0xffffffffu, d, off);
    float rstd = rsqrtf(d / (float)CC + EPSf);
#pragma unroll
    for (int i = 0; i < NV; i++) {
        int c = lane + i*32;
        float o = (v[i]-mean)*rstd*gw[c] + bw[c];
        if (YBF) ((__nv_bfloat16*)yv)[(size_t)r*CC + c] = __float2bfloat16(o);
        else     ((float*)yv)[(size_t)r*CC + c] = o;
    }
}

// ------------------------------ attention (bf16 qkv) -------------------------
// Block (h,b): 1024 threads = 128 queries x 8 lanes. K staged fp32 in smem
// (converted from bf16), V streamed bf16 from global. Online softmax.
__global__ void __launch_bounds__(1024) attn_kernel(const __nv_bfloat16* __restrict__ qkv,
                                                    __nv_bfloat16* __restrict__ out)
{
    __shared__ float sK[128*64];    // 32 KB
    int h = blockIdx.x, b = blockIdx.y;
    int tid = threadIdx.x;
    int tq = tid >> 3, dsl = tid & 7;
    const __nv_bfloat16* base = qkv + (size_t)b*GG*(3*CC) + h*64;

    {
        union { __nv_bfloat162 h2[4]; uint4 u; } kv;
        kv.u = *(const uint4*)&base[(size_t)tq*(3*CC) + CC + dsl*8];
        float* ks = &sK[tq*64 + dsl*8];
#pragma unroll
        for (int d = 0; d < 4; d++) {
            ks[d*2+0] = __bfloat162float(kv.h2[d].x);
            ks[d*2+1] = __bfloat162float(kv.h2[d].y);
        }
    }
    float q[8];
    {
        union { __nv_bfloat162 h2[4]; uint4 u; } qv;
        qv.u = *(const uint4*)&base[(size_t)tq*(3*CC) + dsl*8];
#pragma unroll
        for (int d = 0; d < 4; d++) {
            q[d*2+0] = __bfloat162float(qv.h2[d].x);
            q[d*2+1] = __bfloat162float(qv.h2[d].y);
        }
    }
    __syncthreads();

    unsigned grpmask = 0xFFu << (((tid & 31) >> 3) << 3);
    const float scale = 0.125f;
    float mx = -3.4e38f, sum = 0.f;
    float acc[8];
#pragma unroll
    for (int d = 0; d < 8; d++) acc[d] = 0.f;

    for (int j = 0; j <= tq; j++) {
        const float* ks = &sK[j*64 + dsl*8];
        float s = 0.f;
#pragma unroll
        for (int d = 0; d < 8; d++) s = fmaf(q[d], ks[d], s);
        s += __shfl_xor_sync(grpmask, s, 1);
        s += __shfl_xor_sync(grpmask, s, 2);
        s += __shfl_xor_sync(grpmask, s, 4);
        s *= scale;
        union { __nv_bfloat162 h2[4]; uint4 u; } vv;
        vv.u = *(const uint4*)&base[(size_t)j*(3*CC) + 2*CC + dsl*8];
        float v[8];
#pragma unroll
        for (int d = 0; d < 4; d++) {
            v[d*2+0] = __bfloat162float(vv.h2[d].x);
            v[d*2+1] = __bfloat162float(vv.h2[d].y);
        }
        if (s > mx) {
            float corr = __expf(mx - s);
            sum = fmaf(sum, corr, 1.f);
#pragma unroll
            for (int d = 0; d < 8; d++) acc[d] = fmaf(acc[d], corr, v[d]);
            mx = s;
        } else {
            float e = __expf(s - mx);
            sum += e;
#pragma unroll
            for (int d = 0; d < 8; d++) acc[d] = fmaf(e, v[d], acc[d]);
        }
    }
    float inv = 1.f / sum;
    __nv_bfloat16* dst = out + ((size_t)(b*GG + tq))*CC + h*64 + dsl*8;
#pragma unroll
    for (int d = 0; d < 8; d += 2) {
        __nv_bfloat162 v2 = __floats2bfloat162_rn(acc[d]*inv, acc[d+1]*inv);
        *(__nv_bfloat162*)&dst[d] = v2;
    }
}

// --------------------------------- launch ------------------------------------
static void* symv(const void* s) { void* p = nullptr; cudaGetSymbolAddress(&p, s); return p; }
static float* sym(const void* s) { return (float*)symv(s); }
static __nv_bfloat16* symb(const void* s) { return (__nv_bfloat16*)symv(s); }

extern "C" void kernel_launch(void* const* d_in, const int* in_sizes, int n_in,
                              void* d_out, int out_size)
{
    const float* xyz    = (const float*)d_in[0];
    const float* ec1_w  = (const float*)d_in[1];
    const float* ec1_b  = (const float*)d_in[2];
    const float* bn1_g  = (const float*)d_in[3];
    const float* bn1_b  = (const float*)d_in[4];
    const float* ec2_w  = (const float*)d_in[5];
    const float* ec2_b  = (const float*)d_in[6];
    const float* sc1_w  = (const float*)d_in[7];
    const float* sc1_b  = (const float*)d_in[8];
    const float* bn2_g  = (const float*)d_in[9];
    const float* bn2_b  = (const float*)d_in[10];
    const float* sc2_w  = (const float*)d_in[11];
    const float* sc2_b  = (const float*)d_in[12];
    const float* sos    = (const float*)d_in[13];
    const float* ln1_g  = (const float*)d_in[14];
    const float* ln1_b  = (const float*)d_in[15];
    const float* qkv_w  = (const float*)d_in[16];
    const float* qkv_b  = (const float*)d_in[17];
    const float* out_w  = (const float*)d_in[18];
    const float* out_b  = (const float*)d_in[19];
    const float* ln2_g  = (const float*)d_in[20];
    const float* ln2_b  = (const float*)d_in[21];
    const float* mlp1_w = (const float*)d_in[22];
    const float* mlp1_b = (const float*)d_in[23];
    const float* mlp2_w = (const float*)d_in[24];
    const float* mlp2_b = (const float*)d_in[25];
    const float* lnf_g  = (const float*)d_in[26];
    const float* lnf_b  = (const float*)d_in[27];

    float* p_center  = sym(g_center);
    float* p_centerO = sym(g_centerO);
    float* p_neigh   = sym(g_neigh);
    float* p_t    = sym(g_t);
    float* p_psum = sym(g_psum);
    float* p_psq  = sym(g_psq);
    float* p_scale= sym(g_scale);
    float* p_shift= sym(g_shift);
    float* p_h    = sym(g_h);
    float* p_pos  = sym(g_pos);
    float* p_xin  = sym(g_xin);
    float* p_x1   = sym(g_x1);
    __nv_bfloat16* p_f1b   = symb(g_f1b);
    __nv_bfloat16* p_f1c   = symb(g_f1c);
    __nv_bfloat16* p_f2b   = symb(g_f2b);
    __nv_bfloat16* p_gmaxb = symb(g_gmaxb);
    __nv_bfloat16* p_s1b   = symb(g_s1b);
    __nv_bfloat16* p_s1c   = symb(g_s1c);
    __nv_bfloat16* p_s2b   = symb(g_s2b);
    __nv_bfloat16* p_ybf   = symb(g_ybf);
    __nv_bfloat16* p_qkvb  = symb(g_qkvb);
    __nv_bfloat16* p_attnbf= symb(g_attnbf);
    __nv_bfloat16* p_mhbf  = symb(g_mhbf);
    __nv_bfloat16* p_wqkv  = symb(g_wqkv);
    __nv_bfloat16* p_wout  = symb(g_wout);
    __nv_bfloat16* p_wm1   = symb(g_wm1);
    __nv_bfloat16* p_wm2   = symb(g_wm2);
    __nv_bfloat16* p_wec2  = symb(g_wec2);
    __nv_bfloat16* p_wsc1  = symb(g_wsc1);
    __nv_bfloat16* p_wsc2  = symb(g_wsc2);

    // ---- weight preconversion (single launch) ----
    cvt_all_kernel<<<(CV7 + 255)/256, 256>>>(qkv_w, out_w, mlp1_w, mlp2_w,
                                             ec2_w, sc1_w, sc2_w);

    // ---- grouping ----
    fps_kernel  <<<BB, 1024>>>(xyz, p_center);
    order_kernel<<<BB, GG  >>>(p_center, p_centerO);
    knn_kernel  <<<BG, 256 >>>(xyz, p_centerO, p_neigh);

    // ---- encoder ----
    gemm_k<<<dim3(128/64, MROWS/64), 256>>>(p_neigh, 3, ec1_w, 3, ec1_b,
                                            p_f1b, MROWS, 128, 3);
    colstats_bf_kernel<<<dim3(128/32, 64), dim3(32,8)>>>(p_f1b, MROWS, 128, p_psum, p_psq);
    bnfin_kernel<<<1, 128>>>(p_psum, p_psq, 128, 1.f/(float)MROWS, bn1_g, bn1_b, p_scale, p_shift);
    bnapply_b_kernel<<<(MROWS*128/4 + 255)/256, 256>>>(p_f1b, p_scale, p_shift, p_f1c,
                                                       MROWS*128/4, 127);
    // ec2: (65536,128)->(65536,256) bf16
    gemm_bf<0,0,1><<<dim3(256/128, MROWS/64), 256>>>(p_f1c, 128, p_wec2, 128, ec2_b,
                                                     nullptr, p_f2b, MROWS, 256, 128);
    gmax_kernel<<<BG, 256>>>(p_f2b, p_gmaxb);
    // t = gmax @ sc1_w[:, :256]^T + sc1_b  (fp32 out)
    gemm_bf<0,0,0><<<dim3(512/128, BG/64), 256>>>(p_gmaxb, 256, p_wsc1, 512, sc1_b,
                                                  nullptr, p_t, BG, 512, 256);
    // s1 = f2 @ sc1_w[:, 256:]^T + broadcast(t) -> bf16
    gemm_bf<0,2,1><<<dim3(512/128, MROWS/64), 256>>>(p_f2b, 256, p_wsc1 + 256, 512, nullptr,
                                                     p_t, p_s1b, MROWS, 512, 256);
    colstats_bf_kernel<<<dim3(512/32, 64), dim3(32,8)>>>(p_s1b, MROWS, 512, p_psum, p_psq);
    bnfin_kernel<<<4, 128>>>(p_psum, p_psq, 512, 1.f/(float)MROWS, bn2_g, bn2_b, p_scale, p_shift);
    bnapply_b_kernel<<<(MROWS*512/4 + 255)/256, 256>>>(p_s1b, p_scale, p_shift, p_s1c,
                                                       MROWS*512/4, 511);
    // sc2: (65536,512)->(65536,384) bf16
    gemm_bf<0,0,1><<<dim3(384/128, MROWS/64), 256>>>(p_s1c, 512, p_wsc2, 512, sc2_b,
                                                     nullptr, p_s2b, MROWS, 384, 512);
    tokmax_kernel<<<BG, CC>>>(p_s2b, sos, p_h);
    pos_kernel<<<BG, CC>>>(p_centerO, p_pos);

    // ---- GPT ----
    for (int l = 0; l < LL; l++) {
        const __nv_bfloat16* qw = p_wqkv + (size_t)l*3*CC*CC;
        const float* qb = qkv_b  + (size_t)l*3*CC;
        const __nv_bfloat16* ow = p_wout + (size_t)l*CC*CC;
        const float* ob = out_b  + (size_t)l*CC;
        const __nv_bfloat16* m1w= p_wm1 + (size_t)l*HIDD*CC;
        const float* m1b= mlp1_b + (size_t)l*HIDD;
        const __nv_bfloat16* m2w= p_wm2 + (size_t)l*CC*HIDD;
        const float* m2b= mlp2_b + (size_t)l*CC;

        ln_kernel<1><<<BG/4, 128>>>(p_h, p_pos, p_xin, p_ybf, ln1_g + l*CC, ln1_b + l*CC);
        gemm_bf<0,0,1><<<dim3(3*CC/128, BG/64), 256>>>(p_ybf, CC, qw, CC, qb,
                                                       nullptr, p_qkvb, BG, 3*CC, CC);
        attn_kernel<<<dim3(HH, BB), 1024>>>(p_qkvb, p_attnbf);
        gemm_bf<0,1,0><<<dim3(CC/128, BG/64), 256>>>(p_attnbf, CC, ow, CC, ob,
                                                     p_xin, p_x1, BG, CC, CC);
        ln_kernel<1><<<BG/4, 128>>>(p_x1, nullptr, nullptr, p_ybf, ln2_g + l*CC, ln2_b + l*CC);
        gemm_bf<2,0,1><<<dim3(HIDD/128, BG/64), 256>>>(p_ybf, CC, m1w, CC, m1b,
                                                       nullptr, p_mhbf, BG, HIDD, CC);
        gemm_bf<0,1,0><<<dim3(CC/128, BG/64), 256>>>(p_mhbf, HIDD, m2w, HIDD, m2b,
                                                     p_x1, p_h, BG, CC, HIDD);
    }

    // final LN -> output (fp32)
    ln_kernel<0><<<BG/4, 128>>>(p_h, nullptr, nullptr, (float*)d_out, lnf_g, lnf_b);
}

// round 15
// speedup vs baseline: 4.5877x; 1.0238x over previous
#include <cuda_runtime.h>
#include <cuda_bf16.h>
#include <math.h>
#include <stdint.h>

#define BB 16
#define NP 8192
#define GG 128
#define KNb 32
#define CC 384
#define HH 6
#define LL 12
#define HIDD 1536
#define BG (BB*GG)          /* 2048 */
#define MROWS (BG*KNb)      /* 65536 */
#define EPSf 1e-5f

// ------------------------- scratch (static device memory) -------------------
__device__ float g_center [BG*3];
__device__ float g_centerO[BG*3];
__device__ float g_neigh  [MROWS*3];
__device__ float g_t  [(size_t)BG*512];
__device__ float g_psum[64*512];
__device__ float g_psq [64*512];
__device__ float g_scale[512];
__device__ float g_shift[512];
__device__ float g_h   [BG*CC];
__device__ float g_pos [BG*CC];
__device__ float g_xin [BG*CC];
__device__ float g_x1  [BG*CC];
// bf16 encoder activations
__device__ __align__(16) __nv_bfloat16 g_f1b [(size_t)MROWS*128];
__device__ __align__(16) __nv_bfloat16 g_f1c [(size_t)MROWS*128];
__device__ __align__(16) __nv_bfloat16 g_f2b [(size_t)MROWS*256];
__device__ __align__(16) __nv_bfloat16 g_gmaxb[(size_t)BG*256];
__device__ __align__(16) __nv_bfloat16 g_s1b [(size_t)MROWS*512];
__device__ __align__(16) __nv_bfloat16 g_s1c [(size_t)MROWS*512];
__device__ __align__(16) __nv_bfloat16 g_s2b [(size_t)MROWS*384];
// bf16 transformer activations
__device__ __align__(16) __nv_bfloat16 g_ybf  [BG*CC];
__device__ __align__(16) __nv_bfloat16 g_qkvb [BG*3*CC];
__device__ __align__(16) __nv_bfloat16 g_attnbf[BG*CC];
__device__ __align__(16) __nv_bfloat16 g_mhbf [BG*HIDD];
// bf16 pre-converted weights
__device__ __align__(16) __nv_bfloat16 g_wqkv[(size_t)LL*3*CC*CC];
__device__ __align__(16) __nv_bfloat16 g_wout[(size_t)LL*CC*CC];
__device__ __align__(16) __nv_bfloat16 g_wm1 [(size_t)LL*HIDD*CC];
__device__ __align__(16) __nv_bfloat16 g_wm2 [(size_t)LL*CC*HIDD];
__device__ __align__(16) __nv_bfloat16 g_wec2[256*128];
__device__ __align__(16) __nv_bfloat16 g_wsc1[512*512];
__device__ __align__(16) __nv_bfloat16 g_wsc2[384*512];

// ---------------- fp32 -> bf16 conversion (all weights, 1 launch) ------------
#define CV1 1327104   /* wqkv n4 */
#define CV2 1769472   /* + wout */
#define CV3 3538944   /* + wm1 */
#define CV4 5308416   /* + wm2 */
#define CV5 5316608   /* + wec2 */
#define CV6 5382144   /* + wsc1 */
#define CV7 5431296   /* + wsc2 (total) */
__global__ void cvt_all_kernel(
    const float* __restrict__ s0, const float* __restrict__ s1,
    const float* __restrict__ s2, const float* __restrict__ s3,
    const float* __restrict__ s4, const float* __restrict__ s5,
    const float* __restrict__ s6)
{
    int i = blockIdx.x * blockDim.x + threadIdx.x;
    if (i >= CV7) return;
    const float* src; __nv_bfloat16* dst; int base;
    if      (i < CV1) { src = s0; dst = g_wqkv; base = 0; }
    else if (i < CV2) { src = s1; dst = g_wout; base = CV1; }
    else if (i < CV3) { src = s2; dst = g_wm1;  base = CV2; }
    else if (i < CV4) { src = s3; dst = g_wm2;  base = CV3; }
    else if (i < CV5) { src = s4; dst = g_wec2; base = CV4; }
    else if (i < CV6) { src = s5; dst = g_wsc1; base = CV5; }
    else              { src = s6; dst = g_wsc2; base = CV6; }
    int j = i - base;
    float4 v = *(const float4*)&src[j*4];
    union { __nv_bfloat162 h2[2]; uint2 u; } c;
    c.h2[0] = __floats2bfloat162_rn(v.x, v.y);
    c.h2[1] = __floats2bfloat162_rn(v.z, v.w);
    *(uint2*)&dst[j*4] = c.u;
}

// -------------------- BN apply + relu -> bf16 (bf16 in) ----------------------
__global__ void bnapply_b_kernel(const __nv_bfloat16* __restrict__ x,
                                 const float* __restrict__ sc, const float* __restrict__ sh,
                                 __nv_bfloat16* __restrict__ y, int n4, int cmask)
{
    int i = blockIdx.x * blockDim.x + threadIdx.x;
    if (i >= n4) return;
    union { __nv_bfloat162 h2[2]; uint2 u; } in;
    in.u = *(const uint2*)&x[i*4];
    float4 v;
    v.x = __bfloat162float(in.h2[0].x); v.y = __bfloat162float(in.h2[0].y);
    v.z = __bfloat162float(in.h2[1].x); v.w = __bfloat162float(in.h2[1].y);
    int c = (i*4) & cmask;
    float4 s = *(const float4*)&sc[c];
    float4 h = *(const float4*)&sh[c];
    v.x = fmaxf(fmaf(v.x,s.x,h.x),0.f);
    v.y = fmaxf(fmaf(v.y,s.y,h.y),0.f);
    v.z = fmaxf(fmaf(v.z,s.z,h.z),0.f);
    v.w = fmaxf(fmaf(v.w,s.w,h.w),0.f);
    union { __nv_bfloat162 h2[2]; uint2 u; } o;
    o.h2[0] = __floats2bfloat162_rn(v.x, v.y);
    o.h2[1] = __floats2bfloat162_rn(v.z, v.w);
    *(uint2*)&y[i*4] = o.u;
}

// ------------------------------- FPS ----------------------------------------
__global__ void fps_kernel(const float* __restrict__ xyz, float* __restrict__ center)
{
    int b = blockIdx.x;
    int t = threadIdx.x;                      // 1024 threads = 32 warps
    int lane = t & 31, warp = t >> 5;
    const float* X = xyz + (size_t)b * NP * 3;
    float px[8], py[8], pz[8], dd[8];
#pragma unroll
    for (int j = 0; j < 8; j++) {
        int p = t + j * 1024;
        px[j] = X[p*3+0]; py[j] = X[p*3+1]; pz[j] = X[p*3+2];
        dd[j] = 1e10f;
    }
    __shared__ float rv[32];
    __shared__ int   ri[32];
    __shared__ int   s_far;
    int far = 0;
    for (int it = 0; it < GG; it++) {
        float cx = X[far*3+0], cy = X[far*3+1], cz = X[far*3+2];
        if (t == 0) {
            center[(b*GG+it)*3+0] = cx;
            center[(b*GG+it)*3+1] = cy;
            center[(b*GG+it)*3+2] = cz;
        }
        float bv = -1.f; int bi = 0;
#pragma unroll
        for (int j = 0; j < 8; j++) {
            float dx = px[j]-cx, dy = py[j]-cy, dz = pz[j]-cz;
            float d = dx*dx + dy*dy + dz*dz;
            if (d < dd[j]) dd[j] = d;
            if (dd[j] > bv) { bv = dd[j]; bi = t + j*1024; }
        }
#pragma unroll
        for (int off = 16; off > 0; off >>= 1) {
            float ov = __shfl_down_sync(0xffffffffu, bv, off);
            int   oi = __shfl_down_sync(0xffffffffu, bi, off);
            if (ov > bv || (ov == bv && oi < bi)) { bv = ov; bi = oi; }
        }
        if (lane == 0) { rv[warp] = bv; ri[warp] = bi; }
        __syncthreads();
        if (warp == 0) {
            bv = rv[lane]; bi = ri[lane];
#pragma unroll
            for (int off = 16; off > 0; off >>= 1) {
                float ov = __shfl_down_sync(0xffffffffu, bv, off);
                int   oi = __shfl_down_sync(0xffffffffu, bi, off);
                if (ov > bv || (ov == bv && oi < bi)) { bv = ov; bi = oi; }
            }
            if (lane == 0) s_far = bi;
        }
        __syncthreads();
        far = s_far;
    }
}

// --------------------------- greedy NN ordering ------------------------------
__global__ void order_kernel(const float* __restrict__ cen, float* __restrict__ cenO)
{
    int b = blockIdx.x;
    int t = threadIdx.x;                      // 128 threads = 4 warps
    int lane = t & 31, warp = t >> 5;
    __shared__ float cx[GG], cy[GG], cz[GG], nn[GG];
    __shared__ int visited[GG];
    __shared__ int s_last;
    __shared__ float rv[4];
    __shared__ int ri[4];
    cx[t] = cen[(b*GG+t)*3+0];
    cy[t] = cen[(b*GG+t)*3+1];
    cz[t] = cen[(b*GG+t)*3+2];
    nn[t] = cx[t]*cx[t] + cy[t]*cy[t] + cz[t]*cz[t];
    visited[t] = 0;
    if (t == 0) {
        visited[0] = 1; s_last = 0;
        cenO[(b*GG)*3+0] = cx[0]; cenO[(b*GG)*3+1] = cy[0]; cenO[(b*GG)*3+2] = cz[0];
    }
    __syncthreads();
    for (int step = 1; step < GG; step++) {
        int last = s_last;
        float d;
        if (visited[t]) d = 3.4e38f;
        else {
            float dot = cx[last]*cx[t] + cy[last]*cy[t] + cz[last]*cz[t];
            d = fmaxf(nn[last] + nn[t] - 2.f*dot, 0.f);
        }
        float bv = d; int bi = t;
#pragma unroll
        for (int off = 16; off > 0; off >>= 1) {
            float ov = __shfl_down_sync(0xffffffffu, bv, off);
            int   oi = __shfl_down_sync(0xffffffffu, bi, off);
            if (ov < bv || (ov == bv && oi < bi)) { bv = ov; bi = oi; }
        }
        if (lane == 0) { rv[warp] = bv; ri[warp] = bi; }
        __syncthreads();
        if (t == 0) {
            float mv = rv[0]; int mi = ri[0];
#pragma unroll
            for (int j = 1; j < 4; j++)
                if (rv[j] < mv || (rv[j] == mv && ri[j] < mi)) { mv = rv[j]; mi = ri[j]; }
            visited[mi] = 1; s_last = mi;
            cenO[(b*GG+step)*3+0] = cx[mi];
            cenO[(b*GG+step)*3+1] = cy[mi];
            cenO[(b*GG+step)*3+2] = cz[mi];
        }
        __syncthreads();
    }
}

// ------------------------------- kNN + gather --------------------------------
// Incremental argmin selection: each thread caches its local (min, argmin)
// over its 32 strided elements; per round only the 256 cached candidates are
// reduced, and only the winner's owner thread rescans. Tie-breaking (lowest
// index) identical to a full argmin scan.
__global__ void knn_kernel(const float* __restrict__ xyz, const float* __restrict__ cenO,
                           float* __restrict__ neigh)
{
    int bg = blockIdx.x;
    int b  = bg >> 7;
    int t  = threadIdx.x;                     // 256 threads = 8 warps
    int lane = t & 31, warp = t >> 5;
    const float* X = xyz + (size_t)b * NP * 3;
    float cx = cenO[bg*3+0], cy = cenO[bg*3+1], cz = cenO[bg*3+2];
    __shared__ float sd[NP];
    __shared__ float rv[8];
    __shared__ int ri[8];
    __shared__ int s_m;
#pragma unroll
    for (int j = 0; j < NP/256; j++) {
        int p = t + j*256;
        float dx = X[p*3+0]-cx, dy = X[p*3+1]-cy, dz = X[p*3+2]-cz;
        sd[p] = dx*dx + dy*dy + dz*dz;
    }
    __syncthreads();
    // initial local candidate (lowest index on ties within thread)
    float bv = 3.4e38f; int bi = 0;
#pragma unroll
    for (int j = 0; j < NP/256; j++) {
        int p = t + j*256;
        float d = sd[p];
        if (d < bv) { bv = d; bi = p; }
    }
    for (int k = 0; k < KNb; k++) {
        float wv_ = bv; int wi_ = bi;
#pragma unroll
        for (int off = 16; off > 0; off >>= 1) {
            float ov = __shfl_down_sync(0xffffffffu, wv_, off);
            int   oi = __shfl_down_sync(0xffffffffu, wi_, off);
            if (ov < wv_ || (ov == wv_ && oi < wi_)) { wv_ = ov; wi_ = oi; }
        }
        if (lane == 0) { rv[warp] = wv_; ri[warp] = wi_; }
        __syncthreads();
        if (t == 0) {
            float mv = rv[0]; int mi = ri[0];
#pragma unroll
            for (int j = 1; j < 8; j++)
                if (rv[j] < mv || (rv[j] == mv && ri[j] < mi)) { mv = rv[j]; mi = ri[j]; }
            neigh[((size_t)bg*KNb + k)*3+0] = X[mi*3+0]-cx;
            neigh[((size_t)bg*KNb + k)*3+1] = X[mi*3+1]-cy;
            neigh[((size_t)bg*KNb + k)*3+2] = X[mi*3+2]-cz;
            sd[mi] = 3.4e38f;
            s_m = mi;
        }
        __syncthreads();
        int mi = s_m;
        if ((mi & 255) == t) {   // owner rescans its 32 elements
            bv = 3.4e38f; bi = 0;
#pragma unroll
            for (int j = 0; j < NP/256; j++) {
                int p = t + j*256;
                float d = sd[p];
                if (d < bv) { bv = d; bi = p; }
            }
        }
    }
}

// ---------------- small-K GEMM (only ec1, K=3), bf16 output ------------------
__global__ void __launch_bounds__(256) gemm_k(
    const float* __restrict__ A, int lda,
    const float* __restrict__ W, int ldw,
    const float* __restrict__ bias,
    __nv_bfloat16* __restrict__ C, int M, int N, int K)
{
    __shared__ float As[16][64];
    __shared__ float Ws[16][64];
    int tid = threadIdx.x;
    int tx = tid & 15, ty = tid >> 4;
    int m0 = blockIdx.y * 64, n0 = blockIdx.x * 64;
    float acc[4][4] = {};
    for (int kk = 0; kk < K; kk += 16) {
#pragma unroll
        for (int i = 0; i < 4; i++) {
            int idx = tid + i*256;
            int k = idx & 15, m = idx >> 4;
            float a = 0.f, w = 0.f;
            if (kk + k < K) {
                a = A[(size_t)(m0+m)*lda + kk + k];
                w = W[(size_t)(n0+m)*ldw + kk + k];
            }
            As[k][m] = a;
            Ws[k][m] = w;
        }
        __syncthreads();
#pragma unroll
        for (int k = 0; k < 16; k++) {
            float4 av = *(const float4*)&As[k][ty*4];
            float4 wv = *(const float4*)&Ws[k][tx*4];
            float ar[4] = {av.x, av.y, av.z, av.w};
            float wr[4] = {wv.x, wv.y, wv.z, wv.w};
#pragma unroll
            for (int i = 0; i < 4; i++)
#pragma unroll
                for (int j = 0; j < 4; j++)
                    acc[i][j] = fmaf(ar[i], wr[j], acc[i][j]);
        }
        __syncthreads();
    }
#pragma unroll
    for (int i = 0; i < 4; i++) {
        int m = m0 + ty*4 + i;
#pragma unroll
        for (int j = 0; j < 4; j += 2) {
            int n = n0 + tx*4 + j;
            float v0 = acc[i][j]   + bias[n];
            float v1 = acc[i][j+1] + bias[n+1];
            __nv_bfloat162 v2 = __floats2bfloat162_rn(v0, v1);
            *(__nv_bfloat162*)&C[(size_t)m*N + n] = v2;
        }
    }
}

// ----------------------------- asm helpers -----------------------------------
__device__ __forceinline__ void ldm_x4(uint32_t (&r)[4], const void* p)
{
    uint32_t a = (uint32_t)__cvta_generic_to_shared(p);
    asm volatile("ldmatrix.sync.aligned.m8n8.x4.shared.b16 {%0,%1,%2,%3}, [%4];\n"
        : "=r"(r[0]), "=r"(r[1]), "=r"(r[2]), "=r"(r[3]) : "r"(a));
}
__device__ __forceinline__ void cp16(void* dst, const void* src)
{
    uint32_t d = (uint32_t)__cvta_generic_to_shared(dst);
    asm volatile("cp.async.cg.shared.global [%0], [%1], 16;\n" :: "r"(d), "l"(src));
}
__device__ __forceinline__ void cp_commit() { asm volatile("cp.async.commit_group;\n"); }

// ------------------- bf16 tensor-core GEMM (cp.async 3-stage) ----------------
// 64 x 128 block tile, KT=32, 256 threads = 8 warps in 2x4 grid,
// warp tile 32x32 (mt=2, nt=4). A,W bf16; fragments via ldmatrix.x4;
// rows padded to RS=40 (20-bank stride). Static smem 46080 B.
// M%64==0, N%128==0, K%32==0, K/32 >= 2.
template<int ACT, int RES, int OUTBF>
__global__ void __launch_bounds__(256) gemm_bf(
    const __nv_bfloat16* __restrict__ A, int lda,
    const __nv_bfloat16* __restrict__ W, int ldw,
    const float* __restrict__ bias,
    const float* __restrict__ res,
    void* __restrict__ Cv, int M, int N, int K)
{
    constexpr int BM = 64, KT = 32, RS = 40, ST = 3;
    __shared__ __align__(16) __nv_bfloat16 As[ST][BM][RS];
    __shared__ __align__(16) __nv_bfloat16 Ws[ST][128][RS];

    float* Cf = (float*)Cv;
    __nv_bfloat16* Cb = (__nv_bfloat16*)Cv;

    int tid  = threadIdx.x;
    int m0 = blockIdx.y * BM, n0 = blockIdx.x * 128;
    int lane = tid & 31, warp = tid >> 5;
    int m0w = (warp & 1) * 32;            // 2 m-warps
    int n0w = (warp >> 1) * 32;           // 4 n-warps
    int g  = lane >> 2, tg = lane & 3;
    int laneR  = lane & 15;
    int laneK8 = ((lane >> 4) & 1) << 3;

    float acc[2][4][4];
#pragma unroll
    for (int a = 0; a < 2; a++)
#pragma unroll
        for (int b = 0; b < 4; b++)
#pragma unroll
            for (int c = 0; c < 4; c++) acc[a][b][c] = 0.f;

    auto load_stage = [&](int s, int kk) {
        {   // A: 64 rows x 32 cols bf16 = 256 chunks of 16B -> 1 per thread
            int m = tid >> 2, c = tid & 3;
            cp16(&As[s][m][c*8], &A[(size_t)(m0+m)*lda + kk + c*8]);
        }
#pragma unroll
        for (int j = 0; j < 2; j++) {   // W: 128 rows -> 512 chunks
            int f = tid + j*256; int m = f >> 2, c = f & 3;
            cp16(&Ws[s][m][c*8], &W[(size_t)(n0+m)*ldw + kk + c*8]);
        }
        cp_commit();
    };

    int ntiles = K / KT;
#pragma unroll
    for (int s = 0; s < ST-1; s++) {
        if (s < ntiles) load_stage(s, s*KT);
        else cp_commit();
    }

    for (int t = 0; t < ntiles; t++) {
        asm volatile("cp.async.wait_group %0;\n" :: "n"(ST-2));
        __syncthreads();
        int nl = t + ST - 1;
        if (nl < ntiles) load_stage(nl % ST, nl*KT);
        else cp_commit();
        int buf = t % ST;
#pragma unroll
        for (int ks = 0; ks < 2; ks++) {
            int kb = ks*16;
            uint32_t af[2][4], bfr[4][2];
#pragma unroll
            for (int mt = 0; mt < 2; mt++)
                ldm_x4(af[mt], &As[buf][m0w + mt*16 + laneR][kb + laneK8]);
#pragma unroll
            for (int np = 0; np < 2; np++) {
                uint32_t tmp[4];
                ldm_x4(tmp, &Ws[buf][n0w + np*16 + laneR][kb + laneK8]);
                bfr[np*2+0][0] = tmp[0]; bfr[np*2+1][0] = tmp[1];
                bfr[np*2+0][1] = tmp[2]; bfr[np*2+1][1] = tmp[3];
            }
#pragma unroll
            for (int mt = 0; mt < 2; mt++)
#pragma unroll
                for (int nt = 0; nt < 4; nt++) {
                    asm volatile(
                        "mma.sync.aligned.m16n8k16.row.col.f32.bf16.bf16.f32 "
                        "{%0,%1,%2,%3}, {%4,%5,%6,%7}, {%8,%9}, {%0,%1,%2,%3};\n"
                        : "+f"(acc[mt][nt][0]), "+f"(acc[mt][nt][1]),
                          "+f"(acc[mt][nt][2]), "+f"(acc[mt][nt][3])
                        : "r"(af[mt][0]), "r"(af[mt][1]), "r"(af[mt][2]), "r"(af[mt][3]),
                          "r"(bfr[nt][0]), "r"(bfr[nt][1]));
                }
        }
    }

    // ---- epilogue ----
#pragma unroll
    for (int mt = 0; mt < 2; mt++) {
#pragma unroll
        for (int nt = 0; nt < 4; nt++) {
            int c0 = n0 + n0w + nt*8 + 2*tg;
#pragma unroll
            for (int h = 0; h < 2; h++) {
                int r = m0 + m0w + mt*16 + g + h*8;
                float x0 = acc[mt][nt][h*2+0];
                float x1 = acc[mt][nt][h*2+1];
                if (bias) { x0 += bias[c0]; x1 += bias[c0+1]; }
                if (RES == 1) { x0 += res[(size_t)r*N + c0]; x1 += res[(size_t)r*N + c0+1]; }
                if (RES == 2) { x0 += res[(size_t)(r >> 5)*N + c0]; x1 += res[(size_t)(r >> 5)*N + c0+1]; }
                if (ACT == 1) { x0 = fmaxf(x0, 0.f); x1 = fmaxf(x1, 0.f); }
                if (ACT == 2) {
                    x0 = 0.5f*x0*(1.f + erff(x0*0.70710678118654752f));
                    x1 = 0.5f*x1*(1.f + erff(x1*0.70710678118654752f));
                }
                if (OUTBF) {
                    __nv_bfloat162 v2 = __floats2bfloat162_rn(x0, x1);
                    *(__nv_bfloat162*)&Cb[(size_t)r*N + c0] = v2;
                } else {
                    *(float2*)&Cf[(size_t)r*N + c0] = make_float2(x0, x1);
                }
            }
        }
    }
}

// --------------------------- BN column stats (bf16) ---------------------------
__global__ void colstats_bf_kernel(const __nv_bfloat16* __restrict__ X, int M, int C,
                                   float* __restrict__ psum, float* __restrict__ psq)
{
    int c = blockIdx.x * 32 + threadIdx.x;
    int ry = threadIdx.y;                     // 8
    float s = 0.f, s2 = 0.f;
    for (int r = blockIdx.y*8 + ry; r < M; r += gridDim.y*8) {
        float v = __bfloat162float(X[(size_t)r*C + c]);
        s += v; s2 += v*v;
    }
    __shared__ float sh[8][32], sh2[8][32];
    sh[ry][threadIdx.x] = s; sh2[ry][threadIdx.x] = s2;
    __syncthreads();
    if (ry == 0) {
        for (int j = 1; j < 8; j++) { s += sh[j][threadIdx.x]; s2 += sh2[j][threadIdx.x]; }
        psum[blockIdx.y*C + c] = s;
        psq [blockIdx.y*C + c] = s2;
    }
}

__global__ void bnfin_kernel(const float* __restrict__ psum, const float* __restrict__ psq,
                             int C, float invM,
                             const float* __restrict__ g, const float* __restrict__ b,
                             float* __restrict__ scale, float* __restrict__ shift)
{
    int c = blockIdx.x * blockDim.x + threadIdx.x;
    if (c >= C) return;
    float s = 0.f, s2 = 0.f;
    for (int j = 0; j < 64; j++) { s += psum[j*C + c]; s2 += psq[j*C + c]; }
    float mean = s * invM;
    float var  = s2 * invM - mean*mean;
    float sc = g[c] * rsqrtf(var + EPSf);
    scale[c] = sc;
    shift[c] = b[c] - mean*sc;
}

// ------------------------------ max pools (bf16) ------------------------------
__global__ void gmax_kernel(const __nv_bfloat16* __restrict__ f2, __nv_bfloat16* __restrict__ gm)
{
    int g = blockIdx.x; int c = threadIdx.x;  // 256
    float m = -3.4e38f;
    for (int k = 0; k < KNb; k++) m = fmaxf(m, __bfloat162float(f2[((size_t)g*KNb + k)*256 + c]));
    gm[(size_t)g*256 + c] = __float2bfloat16(m);
}

__global__ void tokmax_kernel(const __nv_bfloat16* __restrict__ s2, const float* __restrict__ sos,
                              float* __restrict__ h)
{
    int bg = blockIdx.x; int c = threadIdx.x; // 384
    int g = bg & (GG-1);
    float m = -3.4e38f;
    for (int k = 0; k < KNb; k++) m = fmaxf(m, __bfloat162float(s2[((size_t)bg*KNb + k)*CC + c]));
    if (g < GG-1) h[(size_t)(bg+1)*CC + c] = m;   // shift-right (sos at g=0)
    if (g == 0)   h[(size_t)bg*CC + c] = sos[c];
}

// --------------------------- positional embedding ----------------------------
__global__ void pos_kernel(const float* __restrict__ cenO, float* __restrict__ pos)
{
    int bg = blockIdx.x; int t = threadIdx.x; // 384
    int ch = t >> 7;
    int rem = t & 127;
    int i = rem >> 1, s = rem & 1;
    float coord = cenO[bg*3 + ch];
    float inv = expf(-(2.f * (float)i / 128.f) * logf(10000.f));
    float ang = coord * inv;
    pos[(size_t)bg*CC + t] = s ? cosf(ang) : sinf(ang);
}

// ------------------------------ LayerNorm (warp per row) ---------------------
template<int YBF>
__global__ void ln_kernel(const float* __restrict__ x, const float* __restrict__ pos,
                          float* __restrict__ xin, void* __restrict__ yv,
                          const float* __restrict__ gw, const float* __restrict__ bw)
{
    int lane = threadIdx.x & 31, warp = threadIdx.x >> 5;
    int r = blockIdx.x * 4 + warp;            // 128 threads = 4 rows
    const int NV = CC / 32;                   // 12
    float v[NV];
    float s = 0.f;
#pragma unroll
    for (int i = 0; i < NV; i++) {
        int c = lane + i*32;
        float vv = x[(size_t)r*CC + c];
        if (pos) vv += pos[(size_t)r*CC + c];
        if (xin) xin[(size_t)r*CC + c] = vv;
        v[i] = vv; s += vv;
    }
#pragma unroll
    for (int off = 16; off > 0; off >>= 1) s += __shfl_xor_sync(0xffffffffu, s, off);
    float mean = s / (float)CC;
    float d = 0.f;
#pragma unroll
    for (int i = 0; i < NV; i++) { float e = v[i]-mean; d += e*e; }
#pragma unroll
    for (int off = 16; off > 0; off >>= 1) d += __shfl_xor_sync(0xffffffffu, d, off);
    float rstd = rsqrtf(d / (float)CC + EPSf);
#pragma unroll
    for (int i = 0; i < NV; i++) {
        int c = lane + i*32;
        float o = (v[i]-mean)*rstd*gw[c] + bw[c];
        if (YBF) ((__nv_bfloat16*)yv)[(size_t)r*CC + c] = __float2bfloat16(o);
        else     ((float*)yv)[(size_t)r*CC + c] = o;
    }
}

// ------------------------------ attention (bf16 qkv) -------------------------
__global__ void __launch_bounds__(1024) attn_kernel(const __nv_bfloat16* __restrict__ qkv,
                                                    __nv_bfloat16* __restrict__ out)
{
    __shared__ float sK[128*64];    // 32 KB
    int h = blockIdx.x, b = blockIdx.y;
    int tid = threadIdx.x;
    int tq = tid >> 3, dsl = tid & 7;
    const __nv_bfloat16* base = qkv + (size_t)b*GG*(3*CC) + h*64;

    {
        union { __nv_bfloat162 h2[4]; uint4 u; } kv;
        kv.u = *(const uint4*)&base[(size_t)tq*(3*CC) + CC + dsl*8];
        float* ks = &sK[tq*64 + dsl*8];
#pragma unroll
        for (int d = 0; d < 4; d++) {
            ks[d*2+0] = __bfloat162float(kv.h2[d].x);
            ks[d*2+1] = __bfloat162float(kv.h2[d].y);
        }
    }
    float q[8];
    {
        union { __nv_bfloat162 h2[4]; uint4 u; } qv;
        qv.u = *(const uint4*)&base[(size_t)tq*(3*CC) + dsl*8];
#pragma unroll
        for (int d = 0; d < 4; d++) {
            q[d*2+0] = __bfloat162float(qv.h2[d].x);
            q[d*2+1] = __bfloat162float(qv.h2[d].y);
        }
    }
    __syncthreads();

    unsigned grpmask = 0xFFu << (((tid & 31) >> 3) << 3);
    const float scale = 0.125f;
    float mx = -3.4e38f, sum = 0.f;
    float acc[8];
#pragma unroll
    for (int d = 0; d < 8; d++) acc[d] = 0.f;

    for (int j = 0; j <= tq; j++) {
        const float* ks = &sK[j*64 + dsl*8];
        float s = 0.f;
#pragma unroll
        for (int d = 0; d < 8; d++) s = fmaf(q[d], ks[d], s);
        s += __shfl_xor_sync(grpmask, s, 1);
        s += __shfl_xor_sync(grpmask, s, 2);
        s += __shfl_xor_sync(grpmask, s, 4);
        s *= scale;
        union { __nv_bfloat162 h2[4]; uint4 u; } vv;
        vv.u = *(const uint4*)&base[(size_t)j*(3*CC) + 2*CC + dsl*8];
        float v[8];
#pragma unroll
        for (int d = 0; d < 4; d++) {
            v[d*2+0] = __bfloat162float(vv.h2[d].x);
            v[d*2+1] = __bfloat162float(vv.h2[d].y);
        }
        if (s > mx) {
            float corr = __expf(mx - s);
            sum = fmaf(sum, corr, 1.f);
#pragma unroll
            for (int d = 0; d < 8; d++) acc[d] = fmaf(acc[d], corr, v[d]);
            mx = s;
        } else {
            float e = __expf(s - mx);
            sum += e;
#pragma unroll
            for (int d = 0; d < 8; d++) acc[d] = fmaf(e, v[d], acc[d]);
        }
    }
    float inv = 1.f / sum;
    __nv_bfloat16* dst = out + ((size_t)(b*GG + tq))*CC + h*64 + dsl*8;
#pragma unroll
    for (int d = 0; d < 8; d += 2) {
        __nv_bfloat162 v2 = __floats2bfloat162_rn(acc[d]*inv, acc[d+1]*inv);
        *(__nv_bfloat162*)&dst[d] = v2;
    }
}

// --------------------------------- launch ------------------------------------
static void* symv(const void* s) { void* p = nullptr; cudaGetSymbolAddress(&p, s); return p; }
static float* sym(const void* s) { return (float*)symv(s); }
static __nv_bfloat16* symb(const void* s) { return (__nv_bfloat16*)symv(s); }

extern "C" void kernel_launch(void* const* d_in, const int* in_sizes, int n_in,
                              void* d_out, int out_size)
{
    const float* xyz    = (const float*)d_in[0];
    const float* ec1_w  = (const float*)d_in[1];
    const float* ec1_b  = (const float*)d_in[2];
    const float* bn1_g  = (const float*)d_in[3];
    const float* bn1_b  = (const float*)d_in[4];
    const float* ec2_w  = (const float*)d_in[5];
    const float* ec2_b  = (const float*)d_in[6];
    const float* sc1_w  = (const float*)d_in[7];
    const float* sc1_b  = (const float*)d_in[8];
    const float* bn2_g  = (const float*)d_in[9];
    const float* bn2_b  = (const float*)d_in[10];
    const float* sc2_w  = (const float*)d_in[11];
    const float* sc2_b  = (const float*)d_in[12];
    const float* sos    = (const float*)d_in[13];
    const float* ln1_g  = (const float*)d_in[14];
    const float* ln1_b  = (const float*)d_in[15];
    const float* qkv_w  = (const float*)d_in[16];
    const float* qkv_b  = (const float*)d_in[17];
    const float* out_w  = (const float*)d_in[18];
    const float* out_b  = (const float*)d_in[19];
    const float* ln2_g  = (const float*)d_in[20];
    const float* ln2_b  = (const float*)d_in[21];
    const float* mlp1_w = (const float*)d_in[22];
    const float* mlp1_b = (const float*)d_in[23];
    const float* mlp2_w = (const float*)d_in[24];
    const float* mlp2_b = (const float*)d_in[25];
    const float* lnf_g  = (const float*)d_in[26];
    const float* lnf_b  = (const float*)d_in[27];

    float* p_center  = sym(g_center);
    float* p_centerO = sym(g_centerO);
    float* p_neigh   = sym(g_neigh);
    float* p_t    = sym(g_t);
    float* p_psum = sym(g_psum);
    float* p_psq  = sym(g_psq);
    float* p_scale= sym(g_scale);
    float* p_shift= sym(g_shift);
    float* p_h    = sym(g_h);
    float* p_pos  = sym(g_pos);
    float* p_xin  = sym(g_xin);
    float* p_x1   = sym(g_x1);
    __nv_bfloat16* p_f1b   = symb(g_f1b);
    __nv_bfloat16* p_f1c   = symb(g_f1c);
    __nv_bfloat16* p_f2b   = symb(g_f2b);
    __nv_bfloat16* p_gmaxb = symb(g_gmaxb);
    __nv_bfloat16* p_s1b   = symb(g_s1b);
    __nv_bfloat16* p_s1c   = symb(g_s1c);
    __nv_bfloat16* p_s2b   = symb(g_s2b);
    __nv_bfloat16* p_ybf   = symb(g_ybf);
    __nv_bfloat16* p_qkvb  = symb(g_qkvb);
    __nv_bfloat16* p_attnbf= symb(g_attnbf);
    __nv_bfloat16* p_mhbf  = symb(g_mhbf);
    __nv_bfloat16* p_wqkv  = symb(g_wqkv);
    __nv_bfloat16* p_wout  = symb(g_wout);
    __nv_bfloat16* p_wm1   = symb(g_wm1);
    __nv_bfloat16* p_wm2   = symb(g_wm2);
    __nv_bfloat16* p_wec2  = symb(g_wec2);
    __nv_bfloat16* p_wsc1  = symb(g_wsc1);
    __nv_bfloat16* p_wsc2  = symb(g_wsc2);

    // ---- weight preconversion (single launch) ----
    cvt_all_kernel<<<(CV7 + 255)/256, 256>>>(qkv_w, out_w, mlp1_w, mlp2_w,
                                             ec2_w, sc1_w, sc2_w);

    // ---- grouping ----
    fps_kernel  <<<BB, 1024>>>(xyz, p_center);
    order_kernel<<<BB, GG  >>>(p_center, p_centerO);
    knn_kernel  <<<BG, 256 >>>(xyz, p_centerO, p_neigh);

    // ---- encoder ----
    gemm_k<<<dim3(128/64, MROWS/64), 256>>>(p_neigh, 3, ec1_w, 3, ec1_b,
                                            p_f1b, MROWS, 128, 3);
    colstats_bf_kernel<<<dim3(128/32, 64), dim3(32,8)>>>(p_f1b, MROWS, 128, p_psum, p_psq);
    bnfin_kernel<<<1, 128>>>(p_psum, p_psq, 128, 1.f/(float)MROWS, bn1_g, bn1_b, p_scale, p_shift);
    bnapply_b_kernel<<<(MROWS*128/4 + 255)/256, 256>>>(p_f1b, p_scale, p_shift, p_f1c,
                                                       MROWS*128/4, 127);
    // ec2: (65536,128)->(65536,256) bf16
    gemm_bf<0,0,1><<<dim3(256/128, MROWS/64), 256>>>(p_f1c, 128, p_wec2, 128, ec2_b,
                                                     nullptr, p_f2b, MROWS, 256, 128);
    gmax_kernel<<<BG, 256>>>(p_f2b, p_gmaxb);
    // t = gmax @ sc1_w[:, :256]^T + sc1_b  (fp32 out)
    gemm_bf<0,0,0><<<dim3(512/128, BG/64), 256>>>(p_gmaxb, 256, p_wsc1, 512, sc1_b,
                                                  nullptr, p_t, BG, 512, 256);
    // s1 = f2 @ sc1_w[:, 256:]^T + broadcast(t) -> bf16
    gemm_bf<0,2,1><<<dim3(512/128, MROWS/64), 256>>>(p_f2b, 256, p_wsc1 + 256, 512, nullptr,
                                                     p_t, p_s1b, MROWS, 512, 256);
    colstats_bf_kernel<<<dim3(512/32, 64), dim3(32,8)>>>(p_s1b, MROWS, 512, p_psum, p_psq);
    bnfin_kernel<<<4, 128>>>(p_psum, p_psq, 512, 1.f/(float)MROWS, bn2_g, bn2_b, p_scale, p_shift);
    bnapply_b_kernel<<<(MROWS*512/4 + 255)/256, 256>>>(p_s1b, p_scale, p_shift, p_s1c,
                                                       MROWS*512/4, 511);
    // sc2: (65536,512)->(65536,384) bf16
    gemm_bf<0,0,1><<<dim3(384/128, MROWS/64), 256>>>(p_s1c, 512, p_wsc2, 512, sc2_b,
                                                     nullptr, p_s2b, MROWS, 384, 512);
    tokmax_kernel<<<BG, CC>>>(p_s2b, sos, p_h);
    pos_kernel<<<BG, CC>>>(p_centerO, p_pos);

    // ---- GPT ----
    for (int l = 0; l < LL; l++) {
        const __nv_bfloat16* qw = p_wqkv + (size_t)l*3*CC*CC;
        const float* qb = qkv_b  + (size_t)l*3*CC;
        const __nv_bfloat16* ow = p_wout + (size_t)l*CC*CC;
        const float* ob = out_b  + (size_t)l*CC;
        const __nv_bfloat16* m1w= p_wm1 + (size_t)l*HIDD*CC;
        const float* m1b= mlp1_b + (size_t)l*HIDD;
        const __nv_bfloat16* m2w= p_wm2 + (size_t)l*CC*HIDD;
        const float* m2b= mlp2_b + (size_t)l*CC;

        ln_kernel<1><<<BG/4, 128>>>(p_h, p_pos, p_xin, p_ybf, ln1_g + l*CC, ln1_b + l*CC);
        gemm_bf<0,0,1><<<dim3(3*CC/128, BG/64), 256>>>(p_ybf, CC, qw, CC, qb,
                                                       nullptr, p_qkvb, BG, 3*CC, CC);
        attn_kernel<<<dim3(HH, BB), 1024>>>(p_qkvb, p_attnbf);
        gemm_bf<0,1,0><<<dim3(CC/128, BG/64), 256>>>(p_attnbf, CC, ow, CC, ob,
                                                     p_xin, p_x1, BG, CC, CC);
        ln_kernel<1><<<BG/4, 128>>>(p_x1, nullptr, nullptr, p_ybf, ln2_g + l*CC, ln2_b + l*CC);
        gemm_bf<2,0,1><<<dim3(HIDD/128, BG/64), 256>>>(p_ybf, CC, m1w, CC, m1b,
                                                       nullptr, p_mhbf, BG, HIDD, CC);
        gemm_bf<0,1,0><<<dim3(CC/128, BG/64), 256>>>(p_mhbf, HIDD, m2w, HIDD, m2b,
                                                     p_x1, p_h, BG, CC, HIDD);
    }

    // final LN -> output (fp32)
    ln_kernel<0><<<BG/4, 128>>>(p_h, nullptr, nullptr, (float*)d_out, lnf_g, lnf_b);
}